// round 1
// baseline (speedup 1.0000x reference)
#include <cuda_runtime.h>
#include <cstddef>

#define BB 8
#define SS 1024
#define DMM 1024
#define HH 16
#define DKK 64
#define DVV 64
#define MROWS (BB*SS)      /* 8192 */
#define NBH (BB*HH)        /* 128  */

// ---------------- scratch (static device globals; no runtime allocation) ----
__device__ float g_Q[MROWS*DMM];
__device__ float g_K[MROWS*DMM];
__device__ float g_V[MROWS*DMM];
__device__ float g_AO[MROWS*DMM];
__device__ float g_attn[(size_t)NBH*SS*SS];   // 512MB fallback if d_out has no attn slot

// ---------------------------------------------------------------------------
// Generic SGEMM: C[M,N] = A[M,K] @ W[K,N] + bias[N]
// 128x128 block tile, BK=8, 8x8 per thread, 256 threads.
// M,N multiples of 128; K multiple of 8 (true for all uses here).
// ---------------------------------------------------------------------------
__global__ __launch_bounds__(256)
void sgemm_bias(const float* __restrict__ A, const float* __restrict__ W,
                const float* __restrict__ bias, float* __restrict__ C,
                int M, int N, int K)
{
    __shared__ float As[8][132];   // transposed A tile (padded)
    __shared__ float Bs[8][128];
    const int tid = threadIdx.x;
    const int bx = blockIdx.x, by = blockIdx.y;

    const int aRow = tid >> 1, aCol = (tid & 1) * 4;
    const int wRow = tid >> 5, wCol = (tid & 31) * 4;
    const int ty = (tid >> 4) * 8, tx = (tid & 15) * 8;

    float acc[8][8];
#pragma unroll
    for (int i = 0; i < 8; i++)
#pragma unroll
        for (int j = 0; j < 8; j++) acc[i][j] = 0.f;

    const float* Ap = A + (size_t)(by * 128 + aRow) * K + aCol;
    const float* Wp = W + (size_t)wRow * N + bx * 128 + wCol;

    for (int k0 = 0; k0 < K; k0 += 8) {
        float4 a4 = *(const float4*)(Ap + k0);
        As[aCol + 0][aRow] = a4.x;
        As[aCol + 1][aRow] = a4.y;
        As[aCol + 2][aRow] = a4.z;
        As[aCol + 3][aRow] = a4.w;
        *(float4*)&Bs[wRow][wCol] = *(const float4*)(Wp + (size_t)k0 * N);
        __syncthreads();
#pragma unroll
        for (int kk = 0; kk < 8; kk++) {
            float ar[8], br[8];
#pragma unroll
            for (int i = 0; i < 8; i++) ar[i] = As[kk][ty + i];
#pragma unroll
            for (int j = 0; j < 8; j++) br[j] = Bs[kk][tx + j];
#pragma unroll
            for (int i = 0; i < 8; i++)
#pragma unroll
                for (int j = 0; j < 8; j++)
                    acc[i][j] = fmaf(ar[i], br[j], acc[i][j]);
        }
        __syncthreads();
    }

#pragma unroll
    for (int i = 0; i < 8; i++) {
        size_t r = (size_t)(by * 128 + ty + i) * N + bx * 128 + tx;
#pragma unroll
        for (int j = 0; j < 8; j += 4) {
            float4 o;
            o.x = acc[i][j + 0] + bias[bx * 128 + tx + j + 0];
            o.y = acc[i][j + 1] + bias[bx * 128 + tx + j + 1];
            o.z = acc[i][j + 2] + bias[bx * 128 + tx + j + 2];
            o.w = acc[i][j + 3] + bias[bx * 128 + tx + j + 3];
            *(float4*)(C + r + j) = o;
        }
    }
}

// ---------------------------------------------------------------------------
// Scores: per (b,h): Sc[i,j] = (1/64) * sum_d q[i,d]*k[j,d], then mask -> -1e9
// q,k are contiguous 1024x64 blocks.  128x128 tile, full K=64 in 4x BK=16.
// grid = (8, 8, 128)
// ---------------------------------------------------------------------------
__global__ __launch_bounds__(256)
void scores_kernel(const float* __restrict__ Q, const float* __restrict__ K,
                   const int* __restrict__ mask, float* __restrict__ Sc)
{
    __shared__ float As[16][132];
    __shared__ float Bs[16][132];
    const int tid = threadIdx.x;
    const int bx = blockIdx.x, by = blockIdx.y, bh = blockIdx.z;
    const int b = bh >> 4;

    const float* q = Q + (size_t)bh * SS * DKK;
    const float* k = K + (size_t)bh * SS * DKK;
    const int ty = (tid >> 4) * 8, tx = (tid & 15) * 8;

    float acc[8][8];
#pragma unroll
    for (int i = 0; i < 8; i++)
#pragma unroll
        for (int j = 0; j < 8; j++) acc[i][j] = 0.f;

    for (int k0 = 0; k0 < DKK; k0 += 16) {
#pragma unroll
        for (int i = 0; i < 2; i++) {
            int f4 = tid + i * 256;                 // 0..511
            int row = f4 >> 2, c4 = (f4 & 3) * 4;   // 128 rows x 16 cols
            float4 a4 = *(const float4*)(q + (size_t)(by * 128 + row) * DKK + k0 + c4);
            As[c4 + 0][row] = a4.x; As[c4 + 1][row] = a4.y;
            As[c4 + 2][row] = a4.z; As[c4 + 3][row] = a4.w;
            float4 b4 = *(const float4*)(k + (size_t)(bx * 128 + row) * DKK + k0 + c4);
            Bs[c4 + 0][row] = b4.x; Bs[c4 + 1][row] = b4.y;
            Bs[c4 + 2][row] = b4.z; Bs[c4 + 3][row] = b4.w;
        }
        __syncthreads();
#pragma unroll
        for (int kk = 0; kk < 16; kk++) {
            float ar[8], br[8];
#pragma unroll
            for (int i = 0; i < 8; i++) ar[i] = As[kk][ty + i];
#pragma unroll
            for (int j = 0; j < 8; j++) br[j] = Bs[kk][tx + j];
#pragma unroll
            for (int i = 0; i < 8; i++)
#pragma unroll
                for (int j = 0; j < 8; j++)
                    acc[i][j] = fmaf(ar[i], br[j], acc[i][j]);
        }
        __syncthreads();
    }

    const float scale = 1.0f / 64.0f;
    float* outp = Sc + (size_t)bh * SS * SS;
    const int* mb = mask + (size_t)b * SS * SS;
#pragma unroll
    for (int i = 0; i < 8; i++) {
        int gi = by * 128 + ty + i;
        const int* mp = mb + (size_t)gi * SS + bx * 128 + tx;
        int4 m0 = *(const int4*)(mp);
        int4 m1 = *(const int4*)(mp + 4);
        float4 o0, o1;
        o0.x = m0.x ? acc[i][0] * scale : -1e9f;
        o0.y = m0.y ? acc[i][1] * scale : -1e9f;
        o0.z = m0.z ? acc[i][2] * scale : -1e9f;
        o0.w = m0.w ? acc[i][3] * scale : -1e9f;
        o1.x = m1.x ? acc[i][4] * scale : -1e9f;
        o1.y = m1.y ? acc[i][5] * scale : -1e9f;
        o1.z = m1.z ? acc[i][6] * scale : -1e9f;
        o1.w = m1.w ? acc[i][7] * scale : -1e9f;
        float* op = outp + (size_t)gi * SS + bx * 128 + tx;
        *(float4*)(op) = o0;
        *(float4*)(op + 4) = o1;
    }
}

// ---------------------------------------------------------------------------
// Softmax in place, one block per (bh, row). Masked entries are -1e9 ->
// expf underflows to exactly 0, matching where(m,0,attn).
// grid = (1024, 128), 256 threads, 4 elems/thread.
// ---------------------------------------------------------------------------
__global__ __launch_bounds__(256)
void softmax_kernel(float* __restrict__ attn)
{
    const int row = blockIdx.x, bh = blockIdx.y;
    float* p = attn + ((size_t)bh * SS + row) * SS;
    const int tid = threadIdx.x;
    const int lane = tid & 31, wid = tid >> 5;
    __shared__ float red[8];

    float4 x = ((const float4*)p)[tid];
    float m = fmaxf(fmaxf(x.x, x.y), fmaxf(x.z, x.w));
#pragma unroll
    for (int o = 16; o > 0; o >>= 1) m = fmaxf(m, __shfl_xor_sync(0xffffffffu, m, o));
    if (lane == 0) red[wid] = m;
    __syncthreads();
    float bm = red[0];
#pragma unroll
    for (int i = 1; i < 8; i++) bm = fmaxf(bm, red[i]);

    float e0 = expf(x.x - bm);
    float e1 = expf(x.y - bm);
    float e2 = expf(x.z - bm);
    float e3 = expf(x.w - bm);
    float s = (e0 + e1) + (e2 + e3);
    __syncthreads();   // done reading red[] for max
#pragma unroll
    for (int o = 16; o > 0; o >>= 1) s += __shfl_xor_sync(0xffffffffu, s, o);
    if (lane == 0) red[wid] = s;
    __syncthreads();
    float bs = 0.f;
#pragma unroll
    for (int i = 0; i < 8; i++) bs += red[i];
    float inv = 1.0f / bs;

    float4 o4;
    o4.x = e0 * inv; o4.y = e1 * inv; o4.z = e2 * inv; o4.w = e3 * inv;
    ((float4*)p)[tid] = o4;
}

// ---------------------------------------------------------------------------
// AV: per (b,h): AO[1024,64] = attn[1024,1024] @ v[1024,64]
// 128x64 tile, BK=32, 8x4 per thread, 256 threads.  grid = (8, 128)
// ---------------------------------------------------------------------------
__global__ __launch_bounds__(256)
void av_kernel(const float* __restrict__ attn, const float* __restrict__ V,
               float* __restrict__ AO)
{
    __shared__ float As[32][132];
    __shared__ float Bs[32][64];
    const int tid = threadIdx.x;
    const int by = blockIdx.x, bh = blockIdx.y;

    const float* a = attn + (size_t)bh * SS * SS;
    const float* v = V + (size_t)bh * SS * DVV;
    const int ty = (tid >> 4) * 8, tx = (tid & 15) * 4;

    float acc[8][4];
#pragma unroll
    for (int i = 0; i < 8; i++)
#pragma unroll
        for (int j = 0; j < 4; j++) acc[i][j] = 0.f;

    for (int k0 = 0; k0 < SS; k0 += 32) {
#pragma unroll
        for (int i = 0; i < 4; i++) {
            int f4 = tid + i * 256;                  // 0..1023
            int row = f4 >> 3, c4 = (f4 & 7) * 4;    // 128 rows x 32 cols
            float4 a4 = *(const float4*)(a + (size_t)(by * 128 + row) * SS + k0 + c4);
            As[c4 + 0][row] = a4.x; As[c4 + 1][row] = a4.y;
            As[c4 + 2][row] = a4.z; As[c4 + 3][row] = a4.w;
        }
#pragma unroll
        for (int i = 0; i < 2; i++) {
            int f4 = tid + i * 256;                  // 0..511
            int row = f4 >> 4, c4 = (f4 & 15) * 4;   // 32 rows x 64 cols
            *(float4*)&Bs[row][c4] = *(const float4*)(v + (size_t)(k0 + row) * DVV + c4);
        }
        __syncthreads();
#pragma unroll
        for (int kk = 0; kk < 32; kk++) {
            float ar[8], br[4];
#pragma unroll
            for (int i = 0; i < 8; i++) ar[i] = As[kk][ty + i];
#pragma unroll
            for (int j = 0; j < 4; j++) br[j] = Bs[kk][tx + j];
#pragma unroll
            for (int i = 0; i < 8; i++)
#pragma unroll
                for (int j = 0; j < 4; j++)
                    acc[i][j] = fmaf(ar[i], br[j], acc[i][j]);
        }
        __syncthreads();
    }

    float* o = AO + (size_t)bh * SS * DVV;
#pragma unroll
    for (int i = 0; i < 8; i++) {
        float4 o4;
        o4.x = acc[i][0]; o4.y = acc[i][1]; o4.z = acc[i][2]; o4.w = acc[i][3];
        *(float4*)(o + (size_t)(by * 128 + ty + i) * DVV + tx) = o4;
    }
}

// ---------------------------------------------------------------------------
extern "C" void kernel_launch(void* const* d_in, const int* in_sizes, int n_in,
                              void* d_out, int out_size)
{
    const float* query = (const float*)d_in[0];
    const float* keyy  = (const float*)d_in[1];
    const float* value = (const float*)d_in[2];
    const int*   mask  = (const int*)  d_in[3];
    const float* Wq = (const float*)d_in[4];
    const float* bq = (const float*)d_in[5];
    const float* Wk = (const float*)d_in[6];
    const float* bk = (const float*)d_in[7];
    const float* Wv = (const float*)d_in[8];
    const float* bv = (const float*)d_in[9];
    const float* Wo = (const float*)d_in[10];
    const float* bo = (const float*)d_in[11];
    float* out = (float*)d_out;

    void *pq, *pk, *pv, *pao, *pattn;
    cudaGetSymbolAddress(&pq,  g_Q);
    cudaGetSymbolAddress(&pk,  g_K);
    cudaGetSymbolAddress(&pv,  g_V);
    cudaGetSymbolAddress(&pao, g_AO);
    cudaGetSymbolAddress(&pattn, g_attn);

    float* qb  = (float*)pq;
    float* kb  = (float*)pk;
    float* vb  = (float*)pv;
    float* aob = (float*)pao;

    const long long OUT_ELEMS  = (long long)BB * SS * DMM;          // 8388608
    const long long ATTN_ELEMS = (long long)NBH * SS * SS;          // 134217728
    float* attnbuf = (float*)pattn;
    if ((long long)out_size >= OUT_ELEMS + ATTN_ELEMS)
        attnbuf = out + OUT_ELEMS;   // write attn directly into d_out slot 2

    dim3 thr(256);

    // Projections: (8192x1024) @ (1024x1024) + bias
    sgemm_bias<<<dim3(8, 64), thr>>>(query, Wq, bq, qb, MROWS, DMM, DMM);
    sgemm_bias<<<dim3(8, 64), thr>>>(keyy,  Wk, bk, kb, MROWS, DMM, DMM);
    sgemm_bias<<<dim3(8, 64), thr>>>(value, Wv, bv, vb, MROWS, DMM, DMM);

    // Scores + mask
    scores_kernel<<<dim3(8, 8, NBH), thr>>>(qb, kb, mask, attnbuf);

    // Softmax (in place; masked entries become exactly 0)
    softmax_kernel<<<dim3(SS, NBH), thr>>>(attnbuf);

    // attn @ V
    av_kernel<<<dim3(8, NBH), thr>>>(attnbuf, vb, aob);

    // Output projection
    sgemm_bias<<<dim3(8, 64), thr>>>(aob, Wo, bo, out, MROWS, DMM, DMM);
}

// round 3
// speedup vs baseline: 1.3959x; 1.3959x over previous
#include <cuda_runtime.h>
#include <cuda_bf16.h>
#include <cstdint>
#include <cstddef>

#define BB 8
#define SS 1024
#define DMM 1024
#define HH 16
#define DKK 64
#define DVV 64
#define MROWS (BB*SS)      /* 8192 */
#define NBH (BB*HH)        /* 128  */

// ---------------- scratch (static device globals; no runtime allocation) ----
__device__ float g_Q[MROWS*DMM];
__device__ float g_K[MROWS*DMM];
__device__ float g_V[MROWS*DMM];
__device__ float g_AO[MROWS*DMM];
__device__ float g_attn[(size_t)NBH*SS*SS];   // fallback if d_out has no attn slot
__device__ __nv_bfloat16 g_Ahi[(size_t)MROWS*DMM];
__device__ __nv_bfloat16 g_Alo[(size_t)MROWS*DMM];
__device__ __nv_bfloat16 g_Bhi[(size_t)DMM*DMM];
__device__ __nv_bfloat16 g_Blo[(size_t)DMM*DMM];

// ============================================================================
// helpers (compute_80-level PTX only: cp.async, ldmatrix, mma.sync)
// ============================================================================
__device__ __forceinline__ uint32_t smem_u32(const void* p) {
    uint32_t a;
    asm("{ .reg .u64 t; cvta.to.shared.u64 t, %1; cvt.u32.u64 %0, t; }" : "=r"(a) : "l"(p));
    return a;
}
__device__ __forceinline__ void cp_async16(uint32_t dst, const void* src) {
    asm volatile("cp.async.cg.shared.global [%0], [%1], 16;" :: "r"(dst), "l"(src) : "memory");
}
__device__ __forceinline__ void ld4(uint32_t* r, uint32_t addr) {
    asm volatile("ldmatrix.sync.aligned.m8n8.x4.shared.b16 {%0,%1,%2,%3}, [%4];"
                 : "=r"(r[0]), "=r"(r[1]), "=r"(r[2]), "=r"(r[3]) : "r"(addr));
}
__device__ __forceinline__ void mma16816(float* d, const uint32_t* a,
                                         uint32_t b0, uint32_t b1) {
    asm volatile(
        "mma.sync.aligned.m16n8k16.row.col.f32.bf16.bf16.f32 "
        "{%0,%1,%2,%3}, {%4,%5,%6,%7}, {%8,%9}, {%0,%1,%2,%3};"
        : "+f"(d[0]), "+f"(d[1]), "+f"(d[2]), "+f"(d[3])
        : "r"(a[0]), "r"(a[1]), "r"(a[2]), "r"(a[3]), "r"(b0), "r"(b1));
}

// ============================================================================
// bf16x3 mma.sync GEMM: C[M,N] = A[M,K] @ W[K,N] + bias
// A as Ahi/Alo (MxK bf16 row-major), W as Bhi/Blo = W^T (NxK bf16 row-major).
// Logical K' = 3K segments: hi*hi + lo*hi + hi*lo.
// CTA 128x128, BK=32, 8 warps of 32x64, double-buffered cp.async.
// ============================================================================
#define SASTRIDE 40   /* bf16 elems per smem row (80B) -> conflict-free ldmatrix */

__global__ __launch_bounds__(256)
void gemm3x(const __nv_bfloat16* __restrict__ Ahi, const __nv_bfloat16* __restrict__ Alo,
            const __nv_bfloat16* __restrict__ Bhi, const __nv_bfloat16* __restrict__ Blo,
            const float* __restrict__ bias, float* __restrict__ C,
            int M, int N, int K)
{
    __shared__ __nv_bfloat16 sA[2][128][SASTRIDE];
    __shared__ __nv_bfloat16 sB[2][128][SASTRIDE];

    const int tid = threadIdx.x, wid = tid >> 5, lane = tid & 31;
    const int warp_m = wid & 3, warp_n = wid >> 2;
    const int mbase = blockIdx.y * 128, nbase = blockIdx.x * 128;
    const int g = lane >> 3, lr = lane & 7;

    const int KC = K / 32;            // chunks per segment
    const int NC = 3 * KC;            // total chunks
    const __nv_bfloat16* Aseg[3] = { Ahi, Alo, Ahi };
    const __nv_bfloat16* Bseg[3] = { Bhi, Bhi, Blo };

    float acc[2][8][4];
#pragma unroll
    for (int i = 0; i < 2; i++)
#pragma unroll
        for (int j = 0; j < 8; j++)
#pragma unroll
            for (int v = 0; v < 4; v++) acc[i][j][v] = 0.f;

    const uint32_t sa0 = smem_u32(&sA[0][0][0]);
    const uint32_t sb0 = smem_u32(&sB[0][0][0]);
    const uint32_t stageA = 128 * SASTRIDE * 2;   // bytes per stage

    auto issue = [&](int ch) {
        const int seg = ch / KC, k0 = (ch % KC) * 32, s = ch & 1;
        const __nv_bfloat16* Ap = Aseg[seg] + (size_t)mbase * K + k0;
        const __nv_bfloat16* Bp = Bseg[seg] + (size_t)nbase * K + k0;
#pragma unroll
        for (int i = 0; i < 2; i++) {
            int idx = tid + i * 256;              // 0..511
            int r = idx >> 2, cb = (idx & 3) * 16;
            cp_async16(sa0 + s * stageA + r * (SASTRIDE * 2) + cb,
                       (const char*)(Ap + (size_t)r * K) + cb);
            cp_async16(sb0 + s * stageA + r * (SASTRIDE * 2) + cb,
                       (const char*)(Bp + (size_t)r * K) + cb);
        }
        asm volatile("cp.async.commit_group;" ::: "memory");
    };

    issue(0);
    for (int c = 0; c < NC; c++) {
        const int s = c & 1;
        if (c + 1 < NC) {
            issue(c + 1);
            asm volatile("cp.async.wait_group 1;" ::: "memory");
        } else {
            asm volatile("cp.async.wait_group 0;" ::: "memory");
        }
        __syncthreads();

        const uint32_t ab = sa0 + s * stageA;
        const uint32_t bb = sb0 + s * stageA;
#pragma unroll
        for (int kk = 0; kk < 2; kk++) {
            const uint32_t colb = kk * 32 + ((g >> 1) << 4);
            uint32_t afr[2][4];
#pragma unroll
            for (int i = 0; i < 2; i++) {
                int row = warp_m * 32 + i * 16 + ((g & 1) << 3) + lr;
                ld4(afr[i], ab + row * (SASTRIDE * 2) + colb);
            }
#pragma unroll
            for (int j = 0; j < 4; j++) {         // four n16 blocks
                uint32_t bfr[4];
                int row = warp_n * 64 + j * 16 + ((g & 1) << 3) + lr;
                ld4(bfr, bb + row * (SASTRIDE * 2) + colb);
#pragma unroll
                for (int i = 0; i < 2; i++) {
                    mma16816(acc[i][2 * j + 0], afr[i], bfr[0], bfr[2]);
                    mma16816(acc[i][2 * j + 1], afr[i], bfr[1], bfr[3]);
                }
            }
        }
        __syncthreads();
    }

    // epilogue
#pragma unroll
    for (int i = 0; i < 2; i++) {
        int row0 = mbase + warp_m * 32 + i * 16 + (lane >> 2);
#pragma unroll
        for (int j = 0; j < 8; j++) {
            int col = nbase + warp_n * 64 + j * 8 + (lane & 3) * 2;
            float b0 = bias[col], b1 = bias[col + 1];
            float2 lo, hi;
            lo.x = acc[i][j][0] + b0; lo.y = acc[i][j][1] + b1;
            hi.x = acc[i][j][2] + b0; hi.y = acc[i][j][3] + b1;
            *(float2*)(C + (size_t)row0 * N + col) = lo;
            *(float2*)(C + (size_t)(row0 + 8) * N + col) = hi;
        }
    }
}

// ---------------------------------------------------------------------------
// Split fp32 -> (bf16 hi, bf16 lo), elementwise (vectorized by 4)
// ---------------------------------------------------------------------------
__global__ __launch_bounds__(256)
void asplit(const float* __restrict__ A, __nv_bfloat16* __restrict__ hi,
            __nv_bfloat16* __restrict__ lo, int n4)
{
    int i = blockIdx.x * 256 + threadIdx.x;
    if (i >= n4) return;
    float4 v = ((const float4*)A)[i];
    __nv_bfloat16 h0 = __float2bfloat16(v.x), h1 = __float2bfloat16(v.y);
    __nv_bfloat16 h2 = __float2bfloat16(v.z), h3 = __float2bfloat16(v.w);
    __nv_bfloat162* hp = (__nv_bfloat162*)hi;
    __nv_bfloat162* lp = (__nv_bfloat162*)lo;
    hp[2 * i + 0] = __nv_bfloat162(h0, h1);
    hp[2 * i + 1] = __nv_bfloat162(h2, h3);
    lp[2 * i + 0] = __nv_bfloat162(__float2bfloat16(v.x - __bfloat162float(h0)),
                                   __float2bfloat16(v.y - __bfloat162float(h1)));
    lp[2 * i + 1] = __nv_bfloat162(__float2bfloat16(v.z - __bfloat162float(h2)),
                                   __float2bfloat16(v.w - __bfloat162float(h3)));
}

// ---------------------------------------------------------------------------
// Transpose + split: W (K x N fp32) -> Wt_hi/lo (N x K bf16)
// ---------------------------------------------------------------------------
__global__ __launch_bounds__(256)
void wsplit(const float* __restrict__ W, __nv_bfloat16* __restrict__ thi,
            __nv_bfloat16* __restrict__ tlo)
{
    __shared__ float t[32][33];
    const int n0 = blockIdx.x * 32, k0 = blockIdx.y * 32;
    const int x = threadIdx.x, y = threadIdx.y;       // 32 x 8
#pragma unroll
    for (int j = 0; j < 32; j += 8)
        t[y + j][x] = W[(size_t)(k0 + y + j) * DMM + n0 + x];
    __syncthreads();
#pragma unroll
    for (int j = 0; j < 32; j += 8) {
        float v = t[x][y + j];                        // = W[k0+x][n0+y+j]
        __nv_bfloat16 h = __float2bfloat16(v);
        size_t o = (size_t)(n0 + y + j) * DMM + k0 + x;
        thi[o] = h;
        tlo[o] = __float2bfloat16(v - __bfloat162float(h));
    }
}

// ---------------------------------------------------------------------------
// Scores: per (b,h): Sc[i,j] = (1/64) * sum_d q[i,d]*k[j,d], then mask -> -1e9
// ---------------------------------------------------------------------------
__global__ __launch_bounds__(256)
void scores_kernel(const float* __restrict__ Q, const float* __restrict__ K,
                   const int* __restrict__ mask, float* __restrict__ Sc)
{
    __shared__ float As[16][132];
    __shared__ float Bs[16][132];
    const int tid = threadIdx.x;
    const int bx = blockIdx.x, by = blockIdx.y, bh = blockIdx.z;
    const int b = bh >> 4;

    const float* q = Q + (size_t)bh * SS * DKK;
    const float* k = K + (size_t)bh * SS * DKK;
    const int ty = (tid >> 4) * 8, tx = (tid & 15) * 8;

    float acc[8][8];
#pragma unroll
    for (int i = 0; i < 8; i++)
#pragma unroll
        for (int j = 0; j < 8; j++) acc[i][j] = 0.f;

    for (int k0 = 0; k0 < DKK; k0 += 16) {
#pragma unroll
        for (int i = 0; i < 2; i++) {
            int f4 = tid + i * 256;
            int row = f4 >> 2, c4 = (f4 & 3) * 4;
            float4 a4 = *(const float4*)(q + (size_t)(by * 128 + row) * DKK + k0 + c4);
            As[c4 + 0][row] = a4.x; As[c4 + 1][row] = a4.y;
            As[c4 + 2][row] = a4.z; As[c4 + 3][row] = a4.w;
            float4 b4 = *(const float4*)(k + (size_t)(bx * 128 + row) * DKK + k0 + c4);
            Bs[c4 + 0][row] = b4.x; Bs[c4 + 1][row] = b4.y;
            Bs[c4 + 2][row] = b4.z; Bs[c4 + 3][row] = b4.w;
        }
        __syncthreads();
#pragma unroll
        for (int kk = 0; kk < 16; kk++) {
            float ar[8], br[8];
#pragma unroll
            for (int i = 0; i < 8; i++) ar[i] = As[kk][ty + i];
#pragma unroll
            for (int j = 0; j < 8; j++) br[j] = Bs[kk][tx + j];
#pragma unroll
            for (int i = 0; i < 8; i++)
#pragma unroll
                for (int j = 0; j < 8; j++)
                    acc[i][j] = fmaf(ar[i], br[j], acc[i][j]);
        }
        __syncthreads();
    }

    const float scale = 1.0f / 64.0f;
    float* outp = Sc + (size_t)bh * SS * SS;
    const int* mb = mask + (size_t)b * SS * SS;
#pragma unroll
    for (int i = 0; i < 8; i++) {
        int gi = by * 128 + ty + i;
        const int* mp = mb + (size_t)gi * SS + bx * 128 + tx;
        int4 m0 = *(const int4*)(mp);
        int4 m1 = *(const int4*)(mp + 4);
        float4 o0, o1;
        o0.x = m0.x ? acc[i][0] * scale : -1e9f;
        o0.y = m0.y ? acc[i][1] * scale : -1e9f;
        o0.z = m0.z ? acc[i][2] * scale : -1e9f;
        o0.w = m0.w ? acc[i][3] * scale : -1e9f;
        o1.x = m1.x ? acc[i][4] * scale : -1e9f;
        o1.y = m1.y ? acc[i][5] * scale : -1e9f;
        o1.z = m1.z ? acc[i][6] * scale : -1e9f;
        o1.w = m1.w ? acc[i][7] * scale : -1e9f;
        float* op = outp + (size_t)gi * SS + bx * 128 + tx;
        *(float4*)(op) = o0;
        *(float4*)(op + 4) = o1;
    }
}

// ---------------------------------------------------------------------------
// Softmax in place (masked entries are -1e9 -> exp underflows to exactly 0)
// ---------------------------------------------------------------------------
__global__ __launch_bounds__(256)
void softmax_kernel(float* __restrict__ attn)
{
    const int row = blockIdx.x, bh = blockIdx.y;
    float* p = attn + ((size_t)bh * SS + row) * SS;
    const int tid = threadIdx.x;
    const int lane = tid & 31, wid = tid >> 5;
    __shared__ float red[8];

    float4 x = ((const float4*)p)[tid];
    float m = fmaxf(fmaxf(x.x, x.y), fmaxf(x.z, x.w));
#pragma unroll
    for (int o = 16; o > 0; o >>= 1) m = fmaxf(m, __shfl_xor_sync(0xffffffffu, m, o));
    if (lane == 0) red[wid] = m;
    __syncthreads();
    float bm = red[0];
#pragma unroll
    for (int i = 1; i < 8; i++) bm = fmaxf(bm, red[i]);

    float e0 = expf(x.x - bm);
    float e1 = expf(x.y - bm);
    float e2 = expf(x.z - bm);
    float e3 = expf(x.w - bm);
    float s = (e0 + e1) + (e2 + e3);
    __syncthreads();
#pragma unroll
    for (int o = 16; o > 0; o >>= 1) s += __shfl_xor_sync(0xffffffffu, s, o);
    if (lane == 0) red[wid] = s;
    __syncthreads();
    float bs = 0.f;
#pragma unroll
    for (int i = 0; i < 8; i++) bs += red[i];
    float inv = 1.0f / bs;

    float4 o4;
    o4.x = e0 * inv; o4.y = e1 * inv; o4.z = e2 * inv; o4.w = e3 * inv;
    ((float4*)p)[tid] = o4;
}

// ---------------------------------------------------------------------------
// AV: per (b,h): AO[1024,64] = attn[1024,1024] @ v[1024,64]
// ---------------------------------------------------------------------------
__global__ __launch_bounds__(256)
void av_kernel(const float* __restrict__ attn, const float* __restrict__ V,
               float* __restrict__ AO)
{
    __shared__ float As[32][132];
    __shared__ float Bs[32][64];
    const int tid = threadIdx.x;
    const int by = blockIdx.x, bh = blockIdx.y;

    const float* a = attn + (size_t)bh * SS * SS;
    const float* v = V + (size_t)bh * SS * DVV;
    const int ty = (tid >> 4) * 8, tx = (tid & 15) * 4;

    float acc[8][4];
#pragma unroll
    for (int i = 0; i < 8; i++)
#pragma unroll
        for (int j = 0; j < 4; j++) acc[i][j] = 0.f;

    for (int k0 = 0; k0 < SS; k0 += 32) {
#pragma unroll
        for (int i = 0; i < 4; i++) {
            int f4 = tid + i * 256;
            int row = f4 >> 3, c4 = (f4 & 7) * 4;
            float4 a4 = *(const float4*)(a + (size_t)(by * 128 + row) * SS + k0 + c4);
            As[c4 + 0][row] = a4.x; As[c4 + 1][row] = a4.y;
            As[c4 + 2][row] = a4.z; As[c4 + 3][row] = a4.w;
        }
#pragma unroll
        for (int i = 0; i < 2; i++) {
            int f4 = tid + i * 256;
            int row = f4 >> 4, c4 = (f4 & 15) * 4;
            *(float4*)&Bs[row][c4] = *(const float4*)(v + (size_t)(k0 + row) * DVV + c4);
        }
        __syncthreads();
#pragma unroll
        for (int kk = 0; kk < 32; kk++) {
            float ar[8], br[4];
#pragma unroll
            for (int i = 0; i < 8; i++) ar[i] = As[kk][ty + i];
#pragma unroll
            for (int j = 0; j < 4; j++) br[j] = Bs[kk][tx + j];
#pragma unroll
            for (int i = 0; i < 8; i++)
#pragma unroll
                for (int j = 0; j < 4; j++)
                    acc[i][j] = fmaf(ar[i], br[j], acc[i][j]);
        }
        __syncthreads();
    }

    float* o = AO + (size_t)bh * SS * DVV;
#pragma unroll
    for (int i = 0; i < 8; i++) {
        float4 o4;
        o4.x = acc[i][0]; o4.y = acc[i][1]; o4.z = acc[i][2]; o4.w = acc[i][3];
        *(float4*)(o + (size_t)(by * 128 + ty + i) * DVV + tx) = o4;
    }
}

// ---------------------------------------------------------------------------
extern "C" void kernel_launch(void* const* d_in, const int* in_sizes, int n_in,
                              void* d_out, int out_size)
{
    const float* query = (const float*)d_in[0];
    const float* keyy  = (const float*)d_in[1];
    const float* value = (const float*)d_in[2];
    const int*   mask  = (const int*)  d_in[3];
    const float* Wq = (const float*)d_in[4];
    const float* bq = (const float*)d_in[5];
    const float* Wk = (const float*)d_in[6];
    const float* bk = (const float*)d_in[7];
    const float* Wv = (const float*)d_in[8];
    const float* bv = (const float*)d_in[9];
    const float* Wo = (const float*)d_in[10];
    const float* bo = (const float*)d_in[11];
    float* out = (float*)d_out;

    void *pq, *pk, *pv, *pao, *pattn, *pah, *pal, *pbh, *pbl;
    cudaGetSymbolAddress(&pq,  g_Q);
    cudaGetSymbolAddress(&pk,  g_K);
    cudaGetSymbolAddress(&pv,  g_V);
    cudaGetSymbolAddress(&pao, g_AO);
    cudaGetSymbolAddress(&pattn, g_attn);
    cudaGetSymbolAddress(&pah, g_Ahi);
    cudaGetSymbolAddress(&pal, g_Alo);
    cudaGetSymbolAddress(&pbh, g_Bhi);
    cudaGetSymbolAddress(&pbl, g_Blo);

    float* qb  = (float*)pq;
    float* kb  = (float*)pk;
    float* vb  = (float*)pv;
    float* aob = (float*)pao;
    __nv_bfloat16* Ahi = (__nv_bfloat16*)pah;
    __nv_bfloat16* Alo = (__nv_bfloat16*)pal;
    __nv_bfloat16* Bhi = (__nv_bfloat16*)pbh;
    __nv_bfloat16* Blo = (__nv_bfloat16*)pbl;

    const long long OUT_ELEMS  = (long long)BB * SS * DMM;
    const long long ATTN_ELEMS = (long long)NBH * SS * SS;
    float* attnbuf = (float*)pattn;
    if ((long long)out_size >= OUT_ELEMS + ATTN_ELEMS)
        attnbuf = out + OUT_ELEMS;

    const int n4 = MROWS * DMM / 4;
    dim3 thr(256);
    dim3 ggrid(DMM / 128, MROWS / 128);      // (8, 64)
    dim3 wgrid(32, 32), wthr(32, 8);

    // Q = query @ Wq + bq
    asplit<<<n4 / 256, thr>>>(query, Ahi, Alo, n4);
    wsplit<<<wgrid, wthr>>>(Wq, Bhi, Blo);
    gemm3x<<<ggrid, thr>>>(Ahi, Alo, Bhi, Blo, bq, qb, MROWS, DMM, DMM);

    // K = key @ Wk + bk
    asplit<<<n4 / 256, thr>>>(keyy, Ahi, Alo, n4);
    wsplit<<<wgrid, wthr>>>(Wk, Bhi, Blo);
    gemm3x<<<ggrid, thr>>>(Ahi, Alo, Bhi, Blo, bk, kb, MROWS, DMM, DMM);

    // V = value @ Wv + bv
    asplit<<<n4 / 256, thr>>>(value, Ahi, Alo, n4);
    wsplit<<<wgrid, wthr>>>(Wv, Bhi, Blo);
    gemm3x<<<ggrid, thr>>>(Ahi, Alo, Bhi, Blo, bv, vb, MROWS, DMM, DMM);

    // attention (fp32 path, unchanged)
    scores_kernel<<<dim3(8, 8, NBH), thr>>>(qb, kb, mask, attnbuf);
    softmax_kernel<<<dim3(SS, NBH), thr>>>(attnbuf);
    av_kernel<<<dim3(8, NBH), thr>>>(attnbuf, vb, aob);

    // out = AO @ Wo + bo
    asplit<<<n4 / 256, thr>>>(aob, Ahi, Alo, n4);
    wsplit<<<wgrid, wthr>>>(Wo, Bhi, Blo);
    gemm3x<<<ggrid, thr>>>(Ahi, Alo, Bhi, Blo, bo, out, MROWS, DMM, DMM);
}

// round 6
// speedup vs baseline: 2.1466x; 1.5377x over previous
#include <cuda_runtime.h>
#include <cuda_bf16.h>
#include <cstdint>
#include <cstddef>

#define BB 8
#define SS 1024
#define DMM 1024
#define HH 16
#define DKK 64
#define DVV 64
#define MROWS (BB*SS)      /* 8192 */
#define NBH (BB*HH)        /* 128  */

// ---------------- scratch (static device globals; no runtime allocation) ----
__device__ float g_attn[(size_t)NBH*SS*SS];            // fallback attn buffer
__device__ float g_rinv[(size_t)NBH*SS];               // per-row 1/sum
__device__ __nv_bfloat16 g_Ahi[(size_t)MROWS*DMM];
__device__ __nv_bfloat16 g_Alo[(size_t)MROWS*DMM];
__device__ __nv_bfloat16 g_Bhi[(size_t)DMM*DMM];
__device__ __nv_bfloat16 g_Blo[(size_t)DMM*DMM];
__device__ __nv_bfloat16 g_Qb [(size_t)MROWS*DMM];
__device__ __nv_bfloat16 g_Kb [(size_t)MROWS*DMM];
__device__ __nv_bfloat16 g_Vhi[(size_t)MROWS*DMM];
__device__ __nv_bfloat16 g_Vlo[(size_t)MROWS*DMM];
__device__ __nv_bfloat16 g_AOhi[(size_t)MROWS*DMM];
__device__ __nv_bfloat16 g_AOlo[(size_t)MROWS*DMM];

// ============================================================================
// helpers (compute_80-level PTX only)
// ============================================================================
__device__ __forceinline__ uint32_t smem_u32(const void* p) {
    uint32_t a;
    asm("{ .reg .u64 t; cvta.to.shared.u64 t, %1; cvt.u32.u64 %0, t; }" : "=r"(a) : "l"(p));
    return a;
}
__device__ __forceinline__ void cp_async16(uint32_t dst, const void* src) {
    asm volatile("cp.async.cg.shared.global [%0], [%1], 16;" :: "r"(dst), "l"(src) : "memory");
}
__device__ __forceinline__ void ld4(uint32_t* r, uint32_t addr) {
    asm volatile("ldmatrix.sync.aligned.m8n8.x4.shared.b16 {%0,%1,%2,%3}, [%4];"
                 : "=r"(r[0]), "=r"(r[1]), "=r"(r[2]), "=r"(r[3]) : "r"(addr));
}
__device__ __forceinline__ void ld4t(uint32_t* r, uint32_t addr) {
    asm volatile("ldmatrix.sync.aligned.m8n8.x4.trans.shared.b16 {%0,%1,%2,%3}, [%4];"
                 : "=r"(r[0]), "=r"(r[1]), "=r"(r[2]), "=r"(r[3]) : "r"(addr));
}
__device__ __forceinline__ void mma16816(float* d, const uint32_t* a,
                                         uint32_t b0, uint32_t b1) {
    asm volatile(
        "mma.sync.aligned.m16n8k16.row.col.f32.bf16.bf16.f32 "
        "{%0,%1,%2,%3}, {%4,%5,%6,%7}, {%8,%9}, {%0,%1,%2,%3};"
        : "+f"(d[0]), "+f"(d[1]), "+f"(d[2]), "+f"(d[3])
        : "r"(a[0]), "r"(a[1]), "r"(a[2]), "r"(a[3]), "r"(b0), "r"(b1));
}
__device__ __forceinline__ uint32_t packbf2(__nv_bfloat16 x, __nv_bfloat16 y) {
    __nv_bfloat162 t; t.x = x; t.y = y;
    return *reinterpret_cast<uint32_t*>(&t);
}
__device__ __forceinline__ void packhl(float x, float y, uint32_t& h, uint32_t& l) {
    __nv_bfloat16 hx = __float2bfloat16(x), hy = __float2bfloat16(y);
    h = packbf2(hx, hy);
    l = packbf2(__float2bfloat16(x - __bfloat162float(hx)),
                __float2bfloat16(y - __bfloat162float(hy)));
}

// ============================================================================
// bf16x3 mma.sync GEMM: C = A @ W + bias, with selectable output formats.
// ============================================================================
#define SASTRIDE 40

__global__ __launch_bounds__(256)
void gemm3x(const __nv_bfloat16* __restrict__ Ahi, const __nv_bfloat16* __restrict__ Alo,
            const __nv_bfloat16* __restrict__ Bhi, const __nv_bfloat16* __restrict__ Blo,
            const float* __restrict__ bias, float* __restrict__ C,
            __nv_bfloat16* __restrict__ Chi, __nv_bfloat16* __restrict__ Clo,
            int M, int N, int K)
{
    __shared__ __nv_bfloat16 sA[2][128][SASTRIDE];
    __shared__ __nv_bfloat16 sB[2][128][SASTRIDE];

    const int tid = threadIdx.x, wid = tid >> 5, lane = tid & 31;
    const int warp_m = wid & 3, warp_n = wid >> 2;
    const int mbase = blockIdx.y * 128, nbase = blockIdx.x * 128;
    const int g = lane >> 3, lr = lane & 7;

    const int KC = K / 32;
    const int NC = 3 * KC;
    const __nv_bfloat16* Aseg[3] = { Ahi, Alo, Ahi };
    const __nv_bfloat16* Bseg[3] = { Bhi, Bhi, Blo };

    float acc[2][8][4];
#pragma unroll
    for (int i = 0; i < 2; i++)
#pragma unroll
        for (int j = 0; j < 8; j++)
#pragma unroll
            for (int v = 0; v < 4; v++) acc[i][j][v] = 0.f;

    const uint32_t sa0 = smem_u32(&sA[0][0][0]);
    const uint32_t sb0 = smem_u32(&sB[0][0][0]);
    const uint32_t stageA = 128 * SASTRIDE * 2;

    auto issue = [&](int ch) {
        const int seg = ch / KC, k0 = (ch % KC) * 32, s = ch & 1;
        const __nv_bfloat16* Ap = Aseg[seg] + (size_t)mbase * K + k0;
        const __nv_bfloat16* Bp = Bseg[seg] + (size_t)nbase * K + k0;
#pragma unroll
        for (int i = 0; i < 2; i++) {
            int idx = tid + i * 256;
            int r = idx >> 2, cb = (idx & 3) * 16;
            cp_async16(sa0 + s * stageA + r * (SASTRIDE * 2) + cb,
                       (const char*)(Ap + (size_t)r * K) + cb);
            cp_async16(sb0 + s * stageA + r * (SASTRIDE * 2) + cb,
                       (const char*)(Bp + (size_t)r * K) + cb);
        }
        asm volatile("cp.async.commit_group;" ::: "memory");
    };

    issue(0);
    for (int c = 0; c < NC; c++) {
        const int s = c & 1;
        if (c + 1 < NC) {
            issue(c + 1);
            asm volatile("cp.async.wait_group 1;" ::: "memory");
        } else {
            asm volatile("cp.async.wait_group 0;" ::: "memory");
        }
        __syncthreads();

        const uint32_t ab = sa0 + s * stageA;
        const uint32_t bb = sb0 + s * stageA;
#pragma unroll
        for (int kk = 0; kk < 2; kk++) {
            const uint32_t colb = kk * 32 + ((g >> 1) << 4);
            uint32_t afr[2][4];
#pragma unroll
            for (int i = 0; i < 2; i++) {
                int row = warp_m * 32 + i * 16 + ((g & 1) << 3) + lr;
                ld4(afr[i], ab + row * (SASTRIDE * 2) + colb);
            }
#pragma unroll
            for (int j = 0; j < 4; j++) {
                uint32_t bfr[4];
                int row = warp_n * 64 + j * 16 + ((g & 1) << 3) + lr;
                ld4(bfr, bb + row * (SASTRIDE * 2) + colb);
#pragma unroll
                for (int i = 0; i < 2; i++) {
                    mma16816(acc[i][2 * j + 0], afr[i], bfr[0], bfr[2]);
                    mma16816(acc[i][2 * j + 1], afr[i], bfr[1], bfr[3]);
                }
            }
        }
        __syncthreads();
    }

    // epilogue
#pragma unroll
    for (int i = 0; i < 2; i++) {
        int row0 = mbase + warp_m * 32 + i * 16 + (lane >> 2);
#pragma unroll
        for (int j = 0; j < 8; j++) {
            int col = nbase + warp_n * 64 + j * 8 + (lane & 3) * 2;
            float b0 = __ldg(bias + col), b1 = __ldg(bias + col + 1);
            float v0 = acc[i][j][0] + b0, v1 = acc[i][j][1] + b1;
            float v2 = acc[i][j][2] + b0, v3 = acc[i][j][3] + b1;
            if (C) {
                *(float2*)(C + (size_t)row0 * N + col) = make_float2(v0, v1);
                *(float2*)(C + (size_t)(row0 + 8) * N + col) = make_float2(v2, v3);
            }
            if (Chi) {
                __nv_bfloat16 h0 = __float2bfloat16(v0), h1 = __float2bfloat16(v1);
                __nv_bfloat16 h2 = __float2bfloat16(v2), h3 = __float2bfloat16(v3);
                *(uint32_t*)(Chi + (size_t)row0 * N + col) = packbf2(h0, h1);
                *(uint32_t*)(Chi + (size_t)(row0 + 8) * N + col) = packbf2(h2, h3);
                if (Clo) {
                    *(uint32_t*)(Clo + (size_t)row0 * N + col) =
                        packbf2(__float2bfloat16(v0 - __bfloat162float(h0)),
                                __float2bfloat16(v1 - __bfloat162float(h1)));
                    *(uint32_t*)(Clo + (size_t)(row0 + 8) * N + col) =
                        packbf2(__float2bfloat16(v2 - __bfloat162float(h2)),
                                __float2bfloat16(v3 - __bfloat162float(h3)));
                }
            }
        }
    }
}

// ---------------------------------------------------------------------------
__global__ __launch_bounds__(256)
void asplit(const float* __restrict__ A, __nv_bfloat16* __restrict__ hi,
            __nv_bfloat16* __restrict__ lo, int n4)
{
    int i = blockIdx.x * 256 + threadIdx.x;
    if (i >= n4) return;
    float4 v = ((const float4*)A)[i];
    __nv_bfloat16 h0 = __float2bfloat16(v.x), h1 = __float2bfloat16(v.y);
    __nv_bfloat16 h2 = __float2bfloat16(v.z), h3 = __float2bfloat16(v.w);
    __nv_bfloat162* hp = (__nv_bfloat162*)hi;
    __nv_bfloat162* lp = (__nv_bfloat162*)lo;
    hp[2 * i + 0] = __nv_bfloat162(h0, h1);
    hp[2 * i + 1] = __nv_bfloat162(h2, h3);
    lp[2 * i + 0] = __nv_bfloat162(__float2bfloat16(v.x - __bfloat162float(h0)),
                                   __float2bfloat16(v.y - __bfloat162float(h1)));
    lp[2 * i + 1] = __nv_bfloat162(__float2bfloat16(v.z - __bfloat162float(h2)),
                                   __float2bfloat16(v.w - __bfloat162float(h3)));
}

// ---------------------------------------------------------------------------
__global__ __launch_bounds__(256)
void wsplit(const float* __restrict__ W, __nv_bfloat16* __restrict__ thi,
            __nv_bfloat16* __restrict__ tlo)
{
    __shared__ float t[32][33];
    const int n0 = blockIdx.x * 32, k0 = blockIdx.y * 32;
    const int x = threadIdx.x, y = threadIdx.y;
#pragma unroll
    for (int j = 0; j < 32; j += 8)
        t[y + j][x] = W[(size_t)(k0 + y + j) * DMM + n0 + x];
    __syncthreads();
#pragma unroll
    for (int j = 0; j < 32; j += 8) {
        float v = t[x][y + j];
        __nv_bfloat16 h = __float2bfloat16(v);
        size_t o = (size_t)(n0 + y + j) * DMM + k0 + x;
        thi[o] = h;
        tlo[o] = __float2bfloat16(v - __bfloat162float(h));
    }
}

// ============================================================================
// Fused attention. RAW-RESHAPE head split: per (b,h), Q/K/V/AO live in the
// contiguous chunk  buf + bh*65536, viewed as [1024 rows][64 cols] row-major.
// S = Q·K^T (bf16 mma), mask, e=exp(s/64), rowsum, O = (e·V)/rowsum (bf16x3).
// ============================================================================
#define FA_STRIDE 144                 /* bytes per smem row (72 bf16) */
#define OFF_Q  0
#define OFF_K  18432
#define OFF_VH (OFF_K + 2*18432)
#define OFF_VL (OFF_VH + 2*18432)
#define OFF_O  (OFF_VL + 2*18432)     /* 128 x 66 fp32 */
#define OFF_RS (OFF_O + 128*66*4)
#define FA_SMEM (OFF_RS + 1024)       /* 163840 */

__global__ __launch_bounds__(256, 1)
void fused_attn(const __nv_bfloat16* __restrict__ Qb, const __nv_bfloat16* __restrict__ Kb,
                const __nv_bfloat16* __restrict__ Vhi, const __nv_bfloat16* __restrict__ Vlo,
                const int* __restrict__ mask,
                __nv_bfloat16* __restrict__ AOhi, __nv_bfloat16* __restrict__ AOlo,
                float* __restrict__ ebuf, float* __restrict__ rinv, int writeE)
{
    extern __shared__ char smem[];
    const uint32_t sb = smem_u32(smem);
    const int tid = threadIdx.x, wid = tid >> 5, lane = tid & 31;
    const int warp_m = wid & 3, warp_n = wid >> 2;
    const int g = lane >> 3, lr = lane & 7;
    const int lr2 = lane >> 2, lc2 = (lane & 3) * 2;
    const int bh = blockIdx.y, b = bh >> 4;
    const int qbase = blockIdx.x * 128;

    const size_t chunk = (size_t)bh * (SS * 64);   // contiguous (b,h) block
    const int* mb = mask + (size_t)b * SS * SS;
    float* eb = ebuf + (size_t)bh * SS * SS;

    // tiles are fully contiguous 16 KB (128 rows x 128 bytes)
    auto issueKV = [&](int jt) {
        const int st = jt & 1;
        const size_t base = chunk + (size_t)jt * (128 * 64);
#pragma unroll
        for (int i = 0; i < 4; i++) {
            int idx = tid + i * 256;                 // 0..1023
            int r = idx >> 3, cb = (idx & 7) * 16;   // 128 rows x 8 chunks
            cp_async16(sb + OFF_K  + st * 18432 + r * FA_STRIDE + cb, (const char*)(Kb  + base) + idx * 16);
            cp_async16(sb + OFF_VH + st * 18432 + r * FA_STRIDE + cb, (const char*)(Vhi + base) + idx * 16);
            cp_async16(sb + OFF_VL + st * 18432 + r * FA_STRIDE + cb, (const char*)(Vlo + base) + idx * 16);
        }
        asm volatile("cp.async.commit_group;" ::: "memory");
    };

    // Q tile + first KV tile in group 0
    {
        const size_t qb0 = chunk + (size_t)qbase * 64;
#pragma unroll
        for (int i = 0; i < 4; i++) {
            int idx = tid + i * 256;
            int r = idx >> 3, cb = (idx & 7) * 16;
            cp_async16(sb + OFF_Q + r * FA_STRIDE + cb, (const char*)(Qb + qb0) + idx * 16);
        }
        issueKV(0);
    }

    float acc_o[2][8][4];
#pragma unroll
    for (int i = 0; i < 2; i++)
#pragma unroll
        for (int j = 0; j < 8; j++)
#pragma unroll
            for (int v = 0; v < 4; v++) acc_o[i][j][v] = 0.f;
    float rs[2][2] = {{0.f, 0.f}, {0.f, 0.f}};

    const float S64 = 1.0f / 64.0f;

    for (int jt = 0; jt < 8; jt++) {
        const int st = jt & 1;
        if (jt + 1 < 8) {
            issueKV(jt + 1);
            asm volatile("cp.async.wait_group 1;" ::: "memory");
        } else {
            asm volatile("cp.async.wait_group 0;" ::: "memory");
        }
        __syncthreads();

        // ---- S = Q K^T ----
        float acc_s[2][8][4];
#pragma unroll
        for (int i = 0; i < 2; i++)
#pragma unroll
            for (int j = 0; j < 8; j++)
#pragma unroll
                for (int v = 0; v < 4; v++) acc_s[i][j][v] = 0.f;

        const uint32_t sKb = sb + OFF_K + st * 18432;
#pragma unroll
        for (int kk = 0; kk < 4; kk++) {
            const uint32_t colb = kk * 32 + ((g >> 1) << 4);
            uint32_t afr[2][4];
#pragma unroll
            for (int i = 0; i < 2; i++)
                ld4(afr[i], sb + OFF_Q + (warp_m * 32 + i * 16 + ((g & 1) << 3) + lr) * FA_STRIDE + colb);
#pragma unroll
            for (int jj = 0; jj < 4; jj++) {
                uint32_t bfr[4];
                ld4(bfr, sKb + (warp_n * 64 + jj * 16 + ((g & 1) << 3) + lr) * FA_STRIDE + colb);
#pragma unroll
                for (int i = 0; i < 2; i++) {
                    mma16816(acc_s[i][2 * jj + 0], afr[i], bfr[0], bfr[2]);
                    mma16816(acc_s[i][2 * jj + 1], afr[i], bfr[1], bfr[3]);
                }
            }
        }

        // ---- mask + exp + rowsum (+ optional e writeout) ----
#pragma unroll
        for (int i = 0; i < 2; i++) {
            const int qr = qbase + warp_m * 32 + i * 16 + lr2;
#pragma unroll
            for (int jj = 0; jj < 8; jj++) {
                const int kc = jt * 128 + warp_n * 64 + jj * 8 + lc2;
                int2 m0 = __ldg((const int2*)(mb + (size_t)qr * SS + kc));
                int2 m1 = __ldg((const int2*)(mb + (size_t)(qr + 8) * SS + kc));
                float e0 = m0.x ? __expf(acc_s[i][jj][0] * S64) : 0.f;
                float e1 = m0.y ? __expf(acc_s[i][jj][1] * S64) : 0.f;
                float e2 = m1.x ? __expf(acc_s[i][jj][2] * S64) : 0.f;
                float e3 = m1.y ? __expf(acc_s[i][jj][3] * S64) : 0.f;
                acc_s[i][jj][0] = e0; acc_s[i][jj][1] = e1;
                acc_s[i][jj][2] = e2; acc_s[i][jj][3] = e3;
                rs[i][0] += e0 + e1;
                rs[i][1] += e2 + e3;
                if (writeE) {
                    *(float2*)(eb + (size_t)qr * SS + kc) = make_float2(e0, e1);
                    *(float2*)(eb + (size_t)(qr + 8) * SS + kc) = make_float2(e2, e3);
                }
            }
        }

        // ---- O += P V  (bf16x3) ----
        const uint32_t sVh = sb + OFF_VH + st * 18432;
        const uint32_t sVl = sb + OFF_VL + st * 18432;
#pragma unroll
        for (int u = 0; u < 4; u++) {
            uint32_t vh[4][4], vl[4][4];
#pragma unroll
            for (int jj2 = 0; jj2 < 4; jj2++) {
                const uint32_t addr = (warp_n * 64 + u * 16 + ((g & 1) << 3) + lr) * FA_STRIDE
                                    + jj2 * 32 + ((g >> 1) << 4);
                ld4t(vh[jj2], sVh + addr);
                ld4t(vl[jj2], sVl + addr);
            }
#pragma unroll
            for (int i = 0; i < 2; i++) {
                uint32_t ah[4], al[4];
                packhl(acc_s[i][2 * u][0],     acc_s[i][2 * u][1],     ah[0], al[0]);
                packhl(acc_s[i][2 * u][2],     acc_s[i][2 * u][3],     ah[1], al[1]);
                packhl(acc_s[i][2 * u + 1][0], acc_s[i][2 * u + 1][1], ah[2], al[2]);
                packhl(acc_s[i][2 * u + 1][2], acc_s[i][2 * u + 1][3], ah[3], al[3]);
#pragma unroll
                for (int jj2 = 0; jj2 < 4; jj2++) {
                    mma16816(acc_o[i][2 * jj2 + 0], ah, vh[jj2][0], vh[jj2][1]);
                    mma16816(acc_o[i][2 * jj2 + 0], al, vh[jj2][0], vh[jj2][1]);
                    mma16816(acc_o[i][2 * jj2 + 0], ah, vl[jj2][0], vl[jj2][1]);
                    mma16816(acc_o[i][2 * jj2 + 1], ah, vh[jj2][2], vh[jj2][3]);
                    mma16816(acc_o[i][2 * jj2 + 1], al, vh[jj2][2], vh[jj2][3]);
                    mma16816(acc_o[i][2 * jj2 + 1], ah, vl[jj2][2], vl[jj2][3]);
                }
            }
        }
        __syncthreads();
    }

    // ---- rowsum reduce ----
    float* s_rs = (float*)(smem + OFF_RS);   // [2][128]
#pragma unroll
    for (int i = 0; i < 2; i++)
#pragma unroll
        for (int h2 = 0; h2 < 2; h2++) {
            float v = rs[i][h2];
            v += __shfl_xor_sync(0xffffffffu, v, 1);
            v += __shfl_xor_sync(0xffffffffu, v, 2);
            if ((lane & 3) == 0)
                s_rs[warp_n * 128 + warp_m * 32 + i * 16 + lr2 + h2 * 8] = v;
        }
    __syncthreads();

    // ---- O cross-warp reduce + normalize + store (raw-reshape layout) ----
    float* so = (float*)(smem + OFF_O);      // [128][66]
    if (warp_n == 1) {
#pragma unroll
        for (int i = 0; i < 2; i++) {
            int r = warp_m * 32 + i * 16 + lr2;
#pragma unroll
            for (int jj = 0; jj < 8; jj++) {
                int c = jj * 8 + lc2;
                *(float2*)&so[r * 66 + c] = make_float2(acc_o[i][jj][0], acc_o[i][jj][1]);
                *(float2*)&so[(r + 8) * 66 + c] = make_float2(acc_o[i][jj][2], acc_o[i][jj][3]);
            }
        }
    }
    __syncthreads();
    if (warp_n == 0) {
#pragma unroll
        for (int i = 0; i < 2; i++) {
            int r = warp_m * 32 + i * 16 + lr2;
            float inv0 = 1.0f / (s_rs[r] + s_rs[128 + r]);
            float inv1 = 1.0f / (s_rs[r + 8] + s_rs[128 + r + 8]);
            if (writeE && (lane & 3) == 0) {
                rinv[(size_t)bh * SS + qbase + r] = inv0;
                rinv[(size_t)bh * SS + qbase + r + 8] = inv1;
            }
            size_t row0 = chunk + (size_t)(qbase + r) * 64;
            size_t row1 = chunk + (size_t)(qbase + r + 8) * 64;
#pragma unroll
            for (int jj = 0; jj < 8; jj++) {
                int c = jj * 8 + lc2;
                float o0 = (acc_o[i][jj][0] + so[r * 66 + c])       * inv0;
                float o1 = (acc_o[i][jj][1] + so[r * 66 + c + 1])   * inv0;
                float o2 = (acc_o[i][jj][2] + so[(r + 8) * 66 + c]) * inv1;
                float o3 = (acc_o[i][jj][3] + so[(r + 8) * 66 + c + 1]) * inv1;
                __nv_bfloat16 h0 = __float2bfloat16(o0), h1 = __float2bfloat16(o1);
                __nv_bfloat16 h2 = __float2bfloat16(o2), h3 = __float2bfloat16(o3);
                *(uint32_t*)(AOhi + row0 + c) = packbf2(h0, h1);
                *(uint32_t*)(AOhi + row1 + c) = packbf2(h2, h3);
                *(uint32_t*)(AOlo + row0 + c) =
                    packbf2(__float2bfloat16(o0 - __bfloat162float(h0)),
                            __float2bfloat16(o1 - __bfloat162float(h1)));
                *(uint32_t*)(AOlo + row1 + c) =
                    packbf2(__float2bfloat16(o2 - __bfloat162float(h2)),
                            __float2bfloat16(o3 - __bfloat162float(h3)));
            }
        }
    }
}

// ---------------------------------------------------------------------------
__global__ __launch_bounds__(256)
void attn_norm(float* __restrict__ e, const float* __restrict__ rinv)
{
    size_t i4 = (size_t)blockIdx.x * 256 + threadIdx.x;
    float s = rinv[i4 >> 8];
    float4 v = ((const float4*)e)[i4];
    v.x *= s; v.y *= s; v.z *= s; v.w *= s;
    ((float4*)e)[i4] = v;
}

// ---------------------------------------------------------------------------
extern "C" void kernel_launch(void* const* d_in, const int* in_sizes, int n_in,
                              void* d_out, int out_size)
{
    const float* query = (const float*)d_in[0];
    const float* keyy  = (const float*)d_in[1];
    const float* value = (const float*)d_in[2];
    const int*   mask  = (const int*)  d_in[3];
    const float* Wq = (const float*)d_in[4];
    const float* bq = (const float*)d_in[5];
    const float* Wk = (const float*)d_in[6];
    const float* bk = (const float*)d_in[7];
    const float* Wv = (const float*)d_in[8];
    const float* bv = (const float*)d_in[9];
    const float* Wo = (const float*)d_in[10];
    const float* bo = (const float*)d_in[11];
    float* out = (float*)d_out;

    void *pattn, *prinv, *pah, *pal, *pbh, *pbl, *pqb, *pkb, *pvh, *pvl, *paoh, *paol;
    cudaGetSymbolAddress(&pattn, g_attn);
    cudaGetSymbolAddress(&prinv, g_rinv);
    cudaGetSymbolAddress(&pah, g_Ahi);
    cudaGetSymbolAddress(&pal, g_Alo);
    cudaGetSymbolAddress(&pbh, g_Bhi);
    cudaGetSymbolAddress(&pbl, g_Blo);
    cudaGetSymbolAddress(&pqb, g_Qb);
    cudaGetSymbolAddress(&pkb, g_Kb);
    cudaGetSymbolAddress(&pvh, g_Vhi);
    cudaGetSymbolAddress(&pvl, g_Vlo);
    cudaGetSymbolAddress(&paoh, g_AOhi);
    cudaGetSymbolAddress(&paol, g_AOlo);

    __nv_bfloat16* Ahi = (__nv_bfloat16*)pah;
    __nv_bfloat16* Alo = (__nv_bfloat16*)pal;
    __nv_bfloat16* Bhi = (__nv_bfloat16*)pbh;
    __nv_bfloat16* Blo = (__nv_bfloat16*)pbl;
    __nv_bfloat16* Qb  = (__nv_bfloat16*)pqb;
    __nv_bfloat16* Kb  = (__nv_bfloat16*)pkb;
    __nv_bfloat16* Vhi = (__nv_bfloat16*)pvh;
    __nv_bfloat16* Vlo = (__nv_bfloat16*)pvl;
    __nv_bfloat16* AOhi = (__nv_bfloat16*)paoh;
    __nv_bfloat16* AOlo = (__nv_bfloat16*)paol;
    float* rinv = (float*)prinv;

    const long long OUT_ELEMS  = (long long)BB * SS * DMM;
    const long long ATTN_ELEMS = (long long)NBH * SS * SS;
    int writeE = ((long long)out_size >= OUT_ELEMS + ATTN_ELEMS) ? 1 : 0;
    float* attnbuf = writeE ? (out + OUT_ELEMS) : (float*)pattn;

    static int smem_set = 0;
    if (!smem_set) {
        cudaFuncSetAttribute(fused_attn, cudaFuncAttributeMaxDynamicSharedMemorySize, FA_SMEM);
        smem_set = 1;
    }

    const int n4 = MROWS * DMM / 4;
    dim3 thr(256);
    dim3 ggrid(DMM / 128, MROWS / 128);
    dim3 wgrid(32, 32), wthr(32, 8);

    // Q = query @ Wq + bq  -> bf16 Qb
    asplit<<<n4 / 256, thr>>>(query, Ahi, Alo, n4);
    wsplit<<<wgrid, wthr>>>(Wq, Bhi, Blo);
    gemm3x<<<ggrid, thr>>>(Ahi, Alo, Bhi, Blo, bq, nullptr, Qb, nullptr, MROWS, DMM, DMM);

    // K -> bf16 Kb
    asplit<<<n4 / 256, thr>>>(keyy, Ahi, Alo, n4);
    wsplit<<<wgrid, wthr>>>(Wk, Bhi, Blo);
    gemm3x<<<ggrid, thr>>>(Ahi, Alo, Bhi, Blo, bk, nullptr, Kb, nullptr, MROWS, DMM, DMM);

    // V -> bf16 hi/lo
    asplit<<<n4 / 256, thr>>>(value, Ahi, Alo, n4);
    wsplit<<<wgrid, wthr>>>(Wv, Bhi, Blo);
    gemm3x<<<ggrid, thr>>>(Ahi, Alo, Bhi, Blo, bv, nullptr, Vhi, Vlo, MROWS, DMM, DMM);

    // fused attention -> AOhi/AOlo (+ e, rinv when attn is an output)
    fused_attn<<<dim3(SS / 128, NBH), thr, FA_SMEM>>>(
        Qb, Kb, Vhi, Vlo, mask, AOhi, AOlo, attnbuf, rinv, writeE);
    if (writeE)
        attn_norm<<<(unsigned)(ATTN_ELEMS / 4 / 256), thr>>>(attnbuf, rinv);

    // out = AO @ Wo + bo  (fp32)
    wsplit<<<wgrid, wthr>>>(Wo, Bhi, Blo);
    gemm3x<<<ggrid, thr>>>(AOhi, AOlo, Bhi, Blo, bo, out, nullptr, nullptr, MROWS, DMM, DMM);
}

// round 7
// speedup vs baseline: 2.2001x; 1.0249x over previous
#include <cuda_runtime.h>
#include <cuda_bf16.h>
#include <cstdint>
#include <cstddef>

#define BB 8
#define SS 1024
#define DMM 1024
#define HH 16
#define DKK 64
#define DVV 64
#define MROWS (BB*SS)      /* 8192 */
#define NBH (BB*HH)        /* 128  */

// ---------------- scratch (static device globals; no runtime allocation) ----
__device__ float g_attn[(size_t)NBH*SS*SS];            // fallback attn buffer
__device__ __nv_bfloat16 g_Ahi[(size_t)MROWS*DMM];
__device__ __nv_bfloat16 g_Alo[(size_t)MROWS*DMM];
__device__ __nv_bfloat16 g_Bhi[(size_t)DMM*DMM];
__device__ __nv_bfloat16 g_Blo[(size_t)DMM*DMM];
__device__ __nv_bfloat16 g_Qb [(size_t)MROWS*DMM];
__device__ __nv_bfloat16 g_Kb [(size_t)MROWS*DMM];
__device__ __nv_bfloat16 g_Vhi[(size_t)MROWS*DMM];
__device__ __nv_bfloat16 g_Vlo[(size_t)MROWS*DMM];
__device__ __nv_bfloat16 g_AOhi[(size_t)MROWS*DMM];
__device__ __nv_bfloat16 g_AOlo[(size_t)MROWS*DMM];

// ============================================================================
// helpers (compute_80-level PTX only)
// ============================================================================
__device__ __forceinline__ uint32_t smem_u32(const void* p) {
    uint32_t a;
    asm("{ .reg .u64 t; cvta.to.shared.u64 t, %1; cvt.u32.u64 %0, t; }" : "=r"(a) : "l"(p));
    return a;
}
__device__ __forceinline__ void cp_async16(uint32_t dst, const void* src) {
    asm volatile("cp.async.cg.shared.global [%0], [%1], 16;" :: "r"(dst), "l"(src) : "memory");
}
__device__ __forceinline__ void ld4(uint32_t* r, uint32_t addr) {
    asm volatile("ldmatrix.sync.aligned.m8n8.x4.shared.b16 {%0,%1,%2,%3}, [%4];"
                 : "=r"(r[0]), "=r"(r[1]), "=r"(r[2]), "=r"(r[3]) : "r"(addr));
}
__device__ __forceinline__ void ld4t(uint32_t* r, uint32_t addr) {
    asm volatile("ldmatrix.sync.aligned.m8n8.x4.trans.shared.b16 {%0,%1,%2,%3}, [%4];"
                 : "=r"(r[0]), "=r"(r[1]), "=r"(r[2]), "=r"(r[3]) : "r"(addr));
}
__device__ __forceinline__ void mma16816(float* d, const uint32_t* a,
                                         uint32_t b0, uint32_t b1) {
    asm volatile(
        "mma.sync.aligned.m16n8k16.row.col.f32.bf16.bf16.f32 "
        "{%0,%1,%2,%3}, {%4,%5,%6,%7}, {%8,%9}, {%0,%1,%2,%3};"
        : "+f"(d[0]), "+f"(d[1]), "+f"(d[2]), "+f"(d[3])
        : "r"(a[0]), "r"(a[1]), "r"(a[2]), "r"(a[3]), "r"(b0), "r"(b1));
}
__device__ __forceinline__ uint32_t packbf2(__nv_bfloat16 x, __nv_bfloat16 y) {
    __nv_bfloat162 t; t.x = x; t.y = y;
    return *reinterpret_cast<uint32_t*>(&t);
}
__device__ __forceinline__ void packhl(float x, float y, uint32_t& h, uint32_t& l) {
    __nv_bfloat16 hx = __float2bfloat16(x), hy = __float2bfloat16(y);
    h = packbf2(hx, hy);
    l = packbf2(__float2bfloat16(x - __bfloat162float(hx)),
                __float2bfloat16(y - __bfloat162float(hy)));
}

// ============================================================================
// bf16x3 mma.sync GEMM: C = A @ W + bias.  BK=64, 2-stage, dynamic smem.
// A as Ahi/Alo (MxK bf16), W as Bhi/Blo = W^T (NxK bf16).
// CTA 128x128, 8 warps of 32x64.
// ============================================================================
#define GS_STRIDE 144                 /* bytes per smem row (72 bf16) */
#define G_STAGE (128*GS_STRIDE)       /* 18432 */
#define G_SMEM  (4*G_STAGE)           /* A0,A1,B0,B1 = 73728 */

__global__ __launch_bounds__(256)
void gemm3x(const __nv_bfloat16* __restrict__ Ahi, const __nv_bfloat16* __restrict__ Alo,
            const __nv_bfloat16* __restrict__ Bhi, const __nv_bfloat16* __restrict__ Blo,
            const float* __restrict__ bias, float* __restrict__ C,
            __nv_bfloat16* __restrict__ Chi, __nv_bfloat16* __restrict__ Clo,
            int M, int N, int K)
{
    extern __shared__ char gsm[];
    const uint32_t sa0 = smem_u32(gsm);
    const uint32_t sb0 = sa0 + 2 * G_STAGE;

    const int tid = threadIdx.x, wid = tid >> 5, lane = tid & 31;
    const int warp_m = wid & 3, warp_n = wid >> 2;
    const int mbase = blockIdx.y * 128, nbase = blockIdx.x * 128;
    const int g = lane >> 3, lr = lane & 7;

    const int KC = K / 64;            // 16
    const int NC = 3 * KC;            // 48
    const __nv_bfloat16* Aseg[3] = { Ahi, Alo, Ahi };
    const __nv_bfloat16* Bseg[3] = { Bhi, Bhi, Blo };

    float acc[2][8][4];
#pragma unroll
    for (int i = 0; i < 2; i++)
#pragma unroll
        for (int j = 0; j < 8; j++)
#pragma unroll
            for (int v = 0; v < 4; v++) acc[i][j][v] = 0.f;

    auto issue = [&](int ch) {
        const int seg = ch / KC, k0 = (ch % KC) * 64, s = ch & 1;
        const __nv_bfloat16* Ap = Aseg[seg] + (size_t)mbase * K + k0;
        const __nv_bfloat16* Bp = Bseg[seg] + (size_t)nbase * K + k0;
#pragma unroll
        for (int i = 0; i < 4; i++) {
            int idx = tid + i * 256;                 // 0..1023
            int r = idx >> 3, cb = (idx & 7) * 16;   // 128 rows x 8 chunks of 16B
            cp_async16(sa0 + s * G_STAGE + r * GS_STRIDE + cb,
                       (const char*)(Ap + (size_t)r * K) + cb);
            cp_async16(sb0 + s * G_STAGE + r * GS_STRIDE + cb,
                       (const char*)(Bp + (size_t)r * K) + cb);
        }
        asm volatile("cp.async.commit_group;" ::: "memory");
    };

    issue(0);
    for (int c = 0; c < NC; c++) {
        const int s = c & 1;
        if (c + 1 < NC) {
            issue(c + 1);
            asm volatile("cp.async.wait_group 1;" ::: "memory");
        } else {
            asm volatile("cp.async.wait_group 0;" ::: "memory");
        }
        __syncthreads();

        const uint32_t ab = sa0 + s * G_STAGE;
        const uint32_t bb = sb0 + s * G_STAGE;
#pragma unroll
        for (int kk = 0; kk < 4; kk++) {
            const uint32_t colb = kk * 32 + ((g >> 1) << 4);
            uint32_t afr[2][4];
#pragma unroll
            for (int i = 0; i < 2; i++) {
                int row = warp_m * 32 + i * 16 + ((g & 1) << 3) + lr;
                ld4(afr[i], ab + row * GS_STRIDE + colb);
            }
#pragma unroll
            for (int j = 0; j < 4; j++) {
                uint32_t bfr[4];
                int row = warp_n * 64 + j * 16 + ((g & 1) << 3) + lr;
                ld4(bfr, bb + row * GS_STRIDE + colb);
#pragma unroll
                for (int i = 0; i < 2; i++) {
                    mma16816(acc[i][2 * j + 0], afr[i], bfr[0], bfr[2]);
                    mma16816(acc[i][2 * j + 1], afr[i], bfr[1], bfr[3]);
                }
            }
        }
        __syncthreads();
    }

    // epilogue
#pragma unroll
    for (int i = 0; i < 2; i++) {
        int row0 = mbase + warp_m * 32 + i * 16 + (lane >> 2);
#pragma unroll
        for (int j = 0; j < 8; j++) {
            int col = nbase + warp_n * 64 + j * 8 + (lane & 3) * 2;
            float b0 = __ldg(bias + col), b1 = __ldg(bias + col + 1);
            float v0 = acc[i][j][0] + b0, v1 = acc[i][j][1] + b1;
            float v2 = acc[i][j][2] + b0, v3 = acc[i][j][3] + b1;
            if (C) {
                *(float2*)(C + (size_t)row0 * N + col) = make_float2(v0, v1);
                *(float2*)(C + (size_t)(row0 + 8) * N + col) = make_float2(v2, v3);
            }
            if (Chi) {
                __nv_bfloat16 h0 = __float2bfloat16(v0), h1 = __float2bfloat16(v1);
                __nv_bfloat16 h2 = __float2bfloat16(v2), h3 = __float2bfloat16(v3);
                *(uint32_t*)(Chi + (size_t)row0 * N + col) = packbf2(h0, h1);
                *(uint32_t*)(Chi + (size_t)(row0 + 8) * N + col) = packbf2(h2, h3);
                if (Clo) {
                    *(uint32_t*)(Clo + (size_t)row0 * N + col) =
                        packbf2(__float2bfloat16(v0 - __bfloat162float(h0)),
                                __float2bfloat16(v1 - __bfloat162float(h1)));
                    *(uint32_t*)(Clo + (size_t)(row0 + 8) * N + col) =
                        packbf2(__float2bfloat16(v2 - __bfloat162float(h2)),
                                __float2bfloat16(v3 - __bfloat162float(h3)));
                }
            }
        }
    }
}

// ---------------------------------------------------------------------------
__global__ __launch_bounds__(256)
void asplit(const float* __restrict__ A, __nv_bfloat16* __restrict__ hi,
            __nv_bfloat16* __restrict__ lo, int n4)
{
    int i = blockIdx.x * 256 + threadIdx.x;
    if (i >= n4) return;
    float4 v = ((const float4*)A)[i];
    __nv_bfloat16 h0 = __float2bfloat16(v.x), h1 = __float2bfloat16(v.y);
    __nv_bfloat16 h2 = __float2bfloat16(v.z), h3 = __float2bfloat16(v.w);
    __nv_bfloat162* hp = (__nv_bfloat162*)hi;
    __nv_bfloat162* lp = (__nv_bfloat162*)lo;
    hp[2 * i + 0] = __nv_bfloat162(h0, h1);
    hp[2 * i + 1] = __nv_bfloat162(h2, h3);
    lp[2 * i + 0] = __nv_bfloat162(__float2bfloat16(v.x - __bfloat162float(h0)),
                                   __float2bfloat16(v.y - __bfloat162float(h1)));
    lp[2 * i + 1] = __nv_bfloat162(__float2bfloat16(v.z - __bfloat162float(h2)),
                                   __float2bfloat16(v.w - __bfloat162float(h3)));
}

// ---------------------------------------------------------------------------
__global__ __launch_bounds__(256)
void wsplit(const float* __restrict__ W, __nv_bfloat16* __restrict__ thi,
            __nv_bfloat16* __restrict__ tlo)
{
    __shared__ float t[32][33];
    const int n0 = blockIdx.x * 32, k0 = blockIdx.y * 32;
    const int x = threadIdx.x, y = threadIdx.y;
#pragma unroll
    for (int j = 0; j < 32; j += 8)
        t[y + j][x] = W[(size_t)(k0 + y + j) * DMM + n0 + x];
    __syncthreads();
#pragma unroll
    for (int j = 0; j < 32; j += 8) {
        float v = t[x][y + j];
        __nv_bfloat16 h = __float2bfloat16(v);
        size_t o = (size_t)(n0 + y + j) * DMM + k0 + x;
        thi[o] = h;
        tlo[o] = __float2bfloat16(v - __bfloat162float(h));
    }
}

// ============================================================================
// Fused attention, 2-pass normalized. RAW-RESHAPE head split: per (b,h),
// Q/K/V/AO are the contiguous chunk buf + bh*65536, viewed [1024][64].
// Pass A: rowsum of masked exp(QK^T/64).  Pass B: recompute, normalize,
// write attn, O = P_norm · V (bf16x3).
// ============================================================================
#define FA_STRIDE 144                 /* bytes per smem row (72 bf16) */
#define OFF_Q  0
#define OFF_K  18432
#define OFF_VH (OFF_K + 2*18432)
#define OFF_VL (OFF_VH + 2*18432)
#define OFF_O  (OFF_VL + 2*18432)     /* 128 x 66 fp32 */
#define OFF_RS (OFF_O + 128*66*4)     /* 2 x 128 fp32   */
#define OFF_INV (OFF_RS + 1024)       /* 128 fp32       */
#define FA_SMEM (OFF_INV + 512)       /* 164352 */

__global__ __launch_bounds__(256, 1)
void fused_attn(const __nv_bfloat16* __restrict__ Qb, const __nv_bfloat16* __restrict__ Kb,
                const __nv_bfloat16* __restrict__ Vhi, const __nv_bfloat16* __restrict__ Vlo,
                const int* __restrict__ mask,
                __nv_bfloat16* __restrict__ AOhi, __nv_bfloat16* __restrict__ AOlo,
                float* __restrict__ ebuf, int writeE)
{
    extern __shared__ char smem[];
    const uint32_t sb = smem_u32(smem);
    const int tid = threadIdx.x, wid = tid >> 5, lane = tid & 31;
    const int warp_m = wid & 3, warp_n = wid >> 2;
    const int g = lane >> 3, lr = lane & 7;
    const int lr2 = lane >> 2, lc2 = (lane & 3) * 2;
    const int bh = blockIdx.y, b = bh >> 4;
    const int qbase = blockIdx.x * 128;

    const size_t chunk = (size_t)bh * (SS * 64);   // contiguous (b,h) block
    const int* mb = mask + (size_t)b * SS * SS;
    float* eb = ebuf + (size_t)bh * SS * SS;
    const float S64 = 1.0f / 64.0f;

    auto issueK = [&](int jt) {
        const int st = jt & 1;
        const size_t base = chunk + (size_t)jt * (128 * 64);
#pragma unroll
        for (int i = 0; i < 4; i++) {
            int idx = tid + i * 256;                 // 0..1023
            int r = idx >> 3, cb = (idx & 7) * 16;
            cp_async16(sb + OFF_K + st * 18432 + r * FA_STRIDE + cb,
                       (const char*)(Kb + base) + idx * 16);
        }
        asm volatile("cp.async.commit_group;" ::: "memory");
    };
    auto issueKV = [&](int jt) {
        const int st = jt & 1;
        const size_t base = chunk + (size_t)jt * (128 * 64);
#pragma unroll
        for (int i = 0; i < 4; i++) {
            int idx = tid + i * 256;
            int r = idx >> 3, cb = (idx & 7) * 16;
            cp_async16(sb + OFF_K  + st * 18432 + r * FA_STRIDE + cb, (const char*)(Kb  + base) + idx * 16);
            cp_async16(sb + OFF_VH + st * 18432 + r * FA_STRIDE + cb, (const char*)(Vhi + base) + idx * 16);
            cp_async16(sb + OFF_VL + st * 18432 + r * FA_STRIDE + cb, (const char*)(Vlo + base) + idx * 16);
        }
        asm volatile("cp.async.commit_group;" ::: "memory");
    };

    // Q tile + first K tile, one group
    {
        const size_t qb0 = chunk + (size_t)qbase * 64;
#pragma unroll
        for (int i = 0; i < 4; i++) {
            int idx = tid + i * 256;
            int r = idx >> 3, cb = (idx & 7) * 16;
            cp_async16(sb + OFF_Q + r * FA_STRIDE + cb, (const char*)(Qb + qb0) + idx * 16);
        }
        issueK(0);
    }

    // computes S fragments for tile jt into acc_s (caller-provided)
    auto computeS = [&](int st, float (*acc_s)[8][4]) {
#pragma unroll
        for (int i = 0; i < 2; i++)
#pragma unroll
            for (int j = 0; j < 8; j++)
#pragma unroll
                for (int v = 0; v < 4; v++) acc_s[i][j][v] = 0.f;
        const uint32_t sKb = sb + OFF_K + st * 18432;
#pragma unroll
        for (int kk = 0; kk < 4; kk++) {
            const uint32_t colb = kk * 32 + ((g >> 1) << 4);
            uint32_t afr[2][4];
#pragma unroll
            for (int i = 0; i < 2; i++)
                ld4(afr[i], sb + OFF_Q + (warp_m * 32 + i * 16 + ((g & 1) << 3) + lr) * FA_STRIDE + colb);
#pragma unroll
            for (int jj = 0; jj < 4; jj++) {
                uint32_t bfr[4];
                ld4(bfr, sKb + (warp_n * 64 + jj * 16 + ((g & 1) << 3) + lr) * FA_STRIDE + colb);
#pragma unroll
                for (int i = 0; i < 2; i++) {
                    mma16816(acc_s[i][2 * jj + 0], afr[i], bfr[0], bfr[2]);
                    mma16816(acc_s[i][2 * jj + 1], afr[i], bfr[1], bfr[3]);
                }
            }
        }
    };

    // ================= PASS A: rowsums =================
    float rs[2][2] = {{0.f, 0.f}, {0.f, 0.f}};
    for (int jt = 0; jt < 8; jt++) {
        const int st = jt & 1;
        if (jt + 1 < 8) {
            issueK(jt + 1);
            asm volatile("cp.async.wait_group 1;" ::: "memory");
        } else {
            asm volatile("cp.async.wait_group 0;" ::: "memory");
        }
        __syncthreads();

        float acc_s[2][8][4];
        computeS(st, acc_s);

#pragma unroll
        for (int i = 0; i < 2; i++) {
            const int qr = qbase + warp_m * 32 + i * 16 + lr2;
#pragma unroll
            for (int jj = 0; jj < 8; jj++) {
                const int kc = jt * 128 + warp_n * 64 + jj * 8 + lc2;
                int2 m0 = __ldg((const int2*)(mb + (size_t)qr * SS + kc));
                int2 m1 = __ldg((const int2*)(mb + (size_t)(qr + 8) * SS + kc));
                float e0 = m0.x ? __expf(acc_s[i][jj][0] * S64) : 0.f;
                float e1 = m0.y ? __expf(acc_s[i][jj][1] * S64) : 0.f;
                float e2 = m1.x ? __expf(acc_s[i][jj][2] * S64) : 0.f;
                float e3 = m1.y ? __expf(acc_s[i][jj][3] * S64) : 0.f;
                rs[i][0] += e0 + e1;
                rs[i][1] += e2 + e3;
            }
        }
        __syncthreads();
    }

    // rowsum reduce -> per-row inverse in smem
    float* s_rs = (float*)(smem + OFF_RS);    // [2][128]
    float* sinv = (float*)(smem + OFF_INV);   // [128]
#pragma unroll
    for (int i = 0; i < 2; i++)
#pragma unroll
        for (int h2 = 0; h2 < 2; h2++) {
            float v = rs[i][h2];
            v += __shfl_xor_sync(0xffffffffu, v, 1);
            v += __shfl_xor_sync(0xffffffffu, v, 2);
            if ((lane & 3) == 0)
                s_rs[warp_n * 128 + warp_m * 32 + i * 16 + lr2 + h2 * 8] = v;
        }
    __syncthreads();
    if (tid < 128) sinv[tid] = 1.0f / (s_rs[tid] + s_rs[128 + tid]);
    __syncthreads();

    // per-thread inverses for pass B
    float inva[2], invb[2];
#pragma unroll
    for (int i = 0; i < 2; i++) {
        int r = warp_m * 32 + i * 16 + lr2;
        inva[i] = sinv[r];
        invb[i] = sinv[r + 8];
    }

    // ================= PASS B: normalized attn + PV =================
    float acc_o[2][8][4];
#pragma unroll
    for (int i = 0; i < 2; i++)
#pragma unroll
        for (int j = 0; j < 8; j++)
#pragma unroll
            for (int v = 0; v < 4; v++) acc_o[i][j][v] = 0.f;

    issueKV(0);
    for (int jt = 0; jt < 8; jt++) {
        const int st = jt & 1;
        if (jt + 1 < 8) {
            issueKV(jt + 1);
            asm volatile("cp.async.wait_group 1;" ::: "memory");
        } else {
            asm volatile("cp.async.wait_group 0;" ::: "memory");
        }
        __syncthreads();

        float acc_s[2][8][4];
        computeS(st, acc_s);

        // mask + exp + normalize (+ attn writeout)
#pragma unroll
        for (int i = 0; i < 2; i++) {
            const int qr = qbase + warp_m * 32 + i * 16 + lr2;
#pragma unroll
            for (int jj = 0; jj < 8; jj++) {
                const int kc = jt * 128 + warp_n * 64 + jj * 8 + lc2;
                int2 m0 = __ldg((const int2*)(mb + (size_t)qr * SS + kc));
                int2 m1 = __ldg((const int2*)(mb + (size_t)(qr + 8) * SS + kc));
                float e0 = m0.x ? __expf(acc_s[i][jj][0] * S64) * inva[i] : 0.f;
                float e1 = m0.y ? __expf(acc_s[i][jj][1] * S64) * inva[i] : 0.f;
                float e2 = m1.x ? __expf(acc_s[i][jj][2] * S64) * invb[i] : 0.f;
                float e3 = m1.y ? __expf(acc_s[i][jj][3] * S64) * invb[i] : 0.f;
                acc_s[i][jj][0] = e0; acc_s[i][jj][1] = e1;
                acc_s[i][jj][2] = e2; acc_s[i][jj][3] = e3;
                if (writeE) {
                    *(float2*)(eb + (size_t)qr * SS + kc) = make_float2(e0, e1);
                    *(float2*)(eb + (size_t)(qr + 8) * SS + kc) = make_float2(e2, e3);
                }
            }
        }

        // O += P_norm V  (bf16x3)
        const uint32_t sVh = sb + OFF_VH + st * 18432;
        const uint32_t sVl = sb + OFF_VL + st * 18432;
#pragma unroll
        for (int u = 0; u < 4; u++) {
            uint32_t vh[4][4], vl[4][4];
#pragma unroll
            for (int jj2 = 0; jj2 < 4; jj2++) {
                const uint32_t addr = (warp_n * 64 + u * 16 + ((g & 1) << 3) + lr) * FA_STRIDE
                                    + jj2 * 32 + ((g >> 1) << 4);
                ld4t(vh[jj2], sVh + addr);
                ld4t(vl[jj2], sVl + addr);
            }
#pragma unroll
            for (int i = 0; i < 2; i++) {
                uint32_t ah[4], al[4];
                packhl(acc_s[i][2 * u][0],     acc_s[i][2 * u][1],     ah[0], al[0]);
                packhl(acc_s[i][2 * u][2],     acc_s[i][2 * u][3],     ah[1], al[1]);
                packhl(acc_s[i][2 * u + 1][0], acc_s[i][2 * u + 1][1], ah[2], al[2]);
                packhl(acc_s[i][2 * u + 1][2], acc_s[i][2 * u + 1][3], ah[3], al[3]);
#pragma unroll
                for (int jj2 = 0; jj2 < 4; jj2++) {
                    mma16816(acc_o[i][2 * jj2 + 0], ah, vh[jj2][0], vh[jj2][1]);
                    mma16816(acc_o[i][2 * jj2 + 0], al, vh[jj2][0], vh[jj2][1]);
                    mma16816(acc_o[i][2 * jj2 + 0], ah, vl[jj2][0], vl[jj2][1]);
                    mma16816(acc_o[i][2 * jj2 + 1], ah, vh[jj2][2], vh[jj2][3]);
                    mma16816(acc_o[i][2 * jj2 + 1], al, vh[jj2][2], vh[jj2][3]);
                    mma16816(acc_o[i][2 * jj2 + 1], ah, vl[jj2][2], vl[jj2][3]);
                }
            }
        }
        __syncthreads();
    }

    // ---- O cross-warp reduce + store (already normalized) ----
    float* so = (float*)(smem + OFF_O);      // [128][66]
    if (warp_n == 1) {
#pragma unroll
        for (int i = 0; i < 2; i++) {
            int r = warp_m * 32 + i * 16 + lr2;
#pragma unroll
            for (int jj = 0; jj < 8; jj++) {
                int c = jj * 8 + lc2;
                *(float2*)&so[r * 66 + c] = make_float2(acc_o[i][jj][0], acc_o[i][jj][1]);
                *(float2*)&so[(r + 8) * 66 + c] = make_float2(acc_o[i][jj][2], acc_o[i][jj][3]);
            }
        }
    }
    __syncthreads();
    if (warp_n == 0) {
#pragma unroll
        for (int i = 0; i < 2; i++) {
            int r = warp_m * 32 + i * 16 + lr2;
            size_t row0 = chunk + (size_t)(qbase + r) * 64;
            size_t row1 = chunk + (size_t)(qbase + r + 8) * 64;
#pragma unroll
            for (int jj = 0; jj < 8; jj++) {
                int c = jj * 8 + lc2;
                float o0 = acc_o[i][jj][0] + so[r * 66 + c];
                float o1 = acc_o[i][jj][1] + so[r * 66 + c + 1];
                float o2 = acc_o[i][jj][2] + so[(r + 8) * 66 + c];
                float o3 = acc_o[i][jj][3] + so[(r + 8) * 66 + c + 1];
                __nv_bfloat16 h0 = __float2bfloat16(o0), h1 = __float2bfloat16(o1);
                __nv_bfloat16 h2 = __float2bfloat16(o2), h3 = __float2bfloat16(o3);
                *(uint32_t*)(AOhi + row0 + c) = packbf2(h0, h1);
                *(uint32_t*)(AOhi + row1 + c) = packbf2(h2, h3);
                *(uint32_t*)(AOlo + row0 + c) =
                    packbf2(__float2bfloat16(o0 - __bfloat162float(h0)),
                            __float2bfloat16(o1 - __bfloat162float(h1)));
                *(uint32_t*)(AOlo + row1 + c) =
                    packbf2(__float2bfloat16(o2 - __bfloat162float(h2)),
                            __float2bfloat16(o3 - __bfloat162float(h3)));
            }
        }
    }
}

// ---------------------------------------------------------------------------
extern "C" void kernel_launch(void* const* d_in, const int* in_sizes, int n_in,
                              void* d_out, int out_size)
{
    const float* query = (const float*)d_in[0];
    const float* keyy  = (const float*)d_in[1];
    const float* value = (const float*)d_in[2];
    const int*   mask  = (const int*)  d_in[3];
    const float* Wq = (const float*)d_in[4];
    const float* bq = (const float*)d_in[5];
    const float* Wk = (const float*)d_in[6];
    const float* bk = (const float*)d_in[7];
    const float* Wv = (const float*)d_in[8];
    const float* bv = (const float*)d_in[9];
    const float* Wo = (const float*)d_in[10];
    const float* bo = (const float*)d_in[11];
    float* out = (float*)d_out;

    void *pattn, *pah, *pal, *pbh, *pbl, *pqb, *pkb, *pvh, *pvl, *paoh, *paol;
    cudaGetSymbolAddress(&pattn, g_attn);
    cudaGetSymbolAddress(&pah, g_Ahi);
    cudaGetSymbolAddress(&pal, g_Alo);
    cudaGetSymbolAddress(&pbh, g_Bhi);
    cudaGetSymbolAddress(&pbl, g_Blo);
    cudaGetSymbolAddress(&pqb, g_Qb);
    cudaGetSymbolAddress(&pkb, g_Kb);
    cudaGetSymbolAddress(&pvh, g_Vhi);
    cudaGetSymbolAddress(&pvl, g_Vlo);
    cudaGetSymbolAddress(&paoh, g_AOhi);
    cudaGetSymbolAddress(&paol, g_AOlo);

    __nv_bfloat16* Ahi = (__nv_bfloat16*)pah;
    __nv_bfloat16* Alo = (__nv_bfloat16*)pal;
    __nv_bfloat16* Bhi = (__nv_bfloat16*)pbh;
    __nv_bfloat16* Blo = (__nv_bfloat16*)pbl;
    __nv_bfloat16* Qb  = (__nv_bfloat16*)pqb;
    __nv_bfloat16* Kb  = (__nv_bfloat16*)pkb;
    __nv_bfloat16* Vhi = (__nv_bfloat16*)pvh;
    __nv_bfloat16* Vlo = (__nv_bfloat16*)pvl;
    __nv_bfloat16* AOhi = (__nv_bfloat16*)paoh;
    __nv_bfloat16* AOlo = (__nv_bfloat16*)paol;

    const long long OUT_ELEMS  = (long long)BB * SS * DMM;
    const long long ATTN_ELEMS = (long long)NBH * SS * SS;
    int writeE = ((long long)out_size >= OUT_ELEMS + ATTN_ELEMS) ? 1 : 0;
    float* attnbuf = writeE ? (out + OUT_ELEMS) : (float*)pattn;

    static int smem_set = 0;
    if (!smem_set) {
        cudaFuncSetAttribute(fused_attn, cudaFuncAttributeMaxDynamicSharedMemorySize, FA_SMEM);
        cudaFuncSetAttribute(gemm3x, cudaFuncAttributeMaxDynamicSharedMemorySize, G_SMEM);
        smem_set = 1;
    }

    const int n4 = MROWS * DMM / 4;
    dim3 thr(256);
    dim3 ggrid(DMM / 128, MROWS / 128);
    dim3 wgrid(32, 32), wthr(32, 8);

    // Q = query @ Wq + bq  -> bf16 Qb
    asplit<<<n4 / 256, thr>>>(query, Ahi, Alo, n4);
    wsplit<<<wgrid, wthr>>>(Wq, Bhi, Blo);
    gemm3x<<<ggrid, thr, G_SMEM>>>(Ahi, Alo, Bhi, Blo, bq, nullptr, Qb, nullptr, MROWS, DMM, DMM);

    // K -> bf16 Kb
    asplit<<<n4 / 256, thr>>>(keyy, Ahi, Alo, n4);
    wsplit<<<wgrid, wthr>>>(Wk, Bhi, Blo);
    gemm3x<<<ggrid, thr, G_SMEM>>>(Ahi, Alo, Bhi, Blo, bk, nullptr, Kb, nullptr, MROWS, DMM, DMM);

    // V -> bf16 hi/lo
    asplit<<<n4 / 256, thr>>>(value, Ahi, Alo, n4);
    wsplit<<<wgrid, wthr>>>(Wv, Bhi, Blo);
    gemm3x<<<ggrid, thr, G_SMEM>>>(Ahi, Alo, Bhi, Blo, bv, nullptr, Vhi, Vlo, MROWS, DMM, DMM);

    // fused attention -> AOhi/AOlo + normalized attn
    fused_attn<<<dim3(SS / 128, NBH), thr, FA_SMEM>>>(
        Qb, Kb, Vhi, Vlo, mask, AOhi, AOlo, attnbuf, writeE);

    // out = AO @ Wo + bo  (fp32)
    wsplit<<<wgrid, wthr>>>(Wo, Bhi, Blo);
    gemm3x<<<ggrid, thr, G_SMEM>>>(AOhi, AOlo, Bhi, Blo, bo, out, nullptr, nullptr, MROWS, DMM, DMM);
}

// round 9
// speedup vs baseline: 2.3303x; 1.0592x over previous
#include <cuda_runtime.h>
#include <cuda_bf16.h>
#include <cstdint>
#include <cstddef>

#define BB 8
#define SS 1024
#define DMM 1024
#define HH 16
#define DKK 64
#define DVV 64
#define MROWS (BB*SS)      /* 8192 */
#define NBH (BB*HH)        /* 128  */
#define APLANE ((size_t)MROWS*DMM)
#define WPLANE ((size_t)DMM*DMM)

// ---------------- scratch (static device globals; no runtime allocation) ----
__device__ float g_attn[(size_t)NBH*SS*SS];            // fallback attn buffer
__device__ __nv_bfloat16 g_Ahi[3*APLANE];
__device__ __nv_bfloat16 g_Alo[3*APLANE];
__device__ __nv_bfloat16 g_Bhi[4*WPLANE];
__device__ __nv_bfloat16 g_Blo[4*WPLANE];
__device__ __nv_bfloat16 g_Qb [APLANE];
__device__ __nv_bfloat16 g_Kb [APLANE];
__device__ __nv_bfloat16 g_Vhi[APLANE];
__device__ __nv_bfloat16 g_Vlo[APLANE];
__device__ __nv_bfloat16 g_AOhi[APLANE];
__device__ __nv_bfloat16 g_AOlo[APLANE];

// ============================================================================
// helpers (compute_80-level PTX only)
// ============================================================================
__device__ __forceinline__ uint32_t smem_u32(const void* p) {
    uint32_t a;
    asm("{ .reg .u64 t; cvta.to.shared.u64 t, %1; cvt.u32.u64 %0, t; }" : "=r"(a) : "l"(p));
    return a;
}
__device__ __forceinline__ void cp_async16(uint32_t dst, const void* src) {
    asm volatile("cp.async.cg.shared.global [%0], [%1], 16;" :: "r"(dst), "l"(src) : "memory");
}
__device__ __forceinline__ void ld4(uint32_t* r, uint32_t addr) {
    asm volatile("ldmatrix.sync.aligned.m8n8.x4.shared.b16 {%0,%1,%2,%3}, [%4];"
                 : "=r"(r[0]), "=r"(r[1]), "=r"(r[2]), "=r"(r[3]) : "r"(addr));
}
__device__ __forceinline__ void ld4t(uint32_t* r, uint32_t addr) {
    asm volatile("ldmatrix.sync.aligned.m8n8.x4.trans.shared.b16 {%0,%1,%2,%3}, [%4];"
                 : "=r"(r[0]), "=r"(r[1]), "=r"(r[2]), "=r"(r[3]) : "r"(addr));
}
__device__ __forceinline__ void mma16816(float* d, const uint32_t* a,
                                         uint32_t b0, uint32_t b1) {
    asm volatile(
        "mma.sync.aligned.m16n8k16.row.col.f32.bf16.bf16.f32 "
        "{%0,%1,%2,%3}, {%4,%5,%6,%7}, {%8,%9}, {%0,%1,%2,%3};"
        : "+f"(d[0]), "+f"(d[1]), "+f"(d[2]), "+f"(d[3])
        : "r"(a[0]), "r"(a[1]), "r"(a[2]), "r"(a[3]), "r"(b0), "r"(b1));
}
__device__ __forceinline__ uint32_t packbf2(__nv_bfloat16 x, __nv_bfloat16 y) {
    __nv_bfloat162 t; t.x = x; t.y = y;
    return *reinterpret_cast<uint32_t*>(&t);
}
__device__ __forceinline__ void packhl(float x, float y, uint32_t& h, uint32_t& l) {
    __nv_bfloat16 hx = __float2bfloat16(x), hy = __float2bfloat16(y);
    h = packbf2(hx, hy);
    l = packbf2(__float2bfloat16(x - __bfloat162float(hx)),
                __float2bfloat16(y - __bfloat162float(hy)));
}

// ============================================================================
// batched bf16x3 mma.sync GEMM: C[z] = A[z] @ W[z] + bias[z].  BK=64, 2-stage.
// ============================================================================
#define GS_STRIDE 144                 /* bytes per smem row (72 bf16) */
#define G_STAGE (128*GS_STRIDE)       /* 18432 */
#define G_SMEM  (4*G_STAGE)           /* 73728 */

struct G3B {
    const __nv_bfloat16* Ahi[3];
    const __nv_bfloat16* Alo[3];
    const __nv_bfloat16* Bhi[3];
    const __nv_bfloat16* Blo[3];
    const float* bias[3];
    float* C[3];
    __nv_bfloat16* Chi[3];
    __nv_bfloat16* Clo[3];
};

__global__ __launch_bounds__(256)
void gemm3x(G3B bat, int M, int N, int K)
{
    extern __shared__ char gsm[];
    const uint32_t sa0 = smem_u32(gsm);
    const uint32_t sb0 = sa0 + 2 * G_STAGE;
    const int z = blockIdx.z;

    const __nv_bfloat16* Ahi = bat.Ahi[z];
    const __nv_bfloat16* Alo = bat.Alo[z];
    const __nv_bfloat16* Bhi = bat.Bhi[z];
    const __nv_bfloat16* Blo = bat.Blo[z];
    const float* bias = bat.bias[z];
    float* C = bat.C[z];
    __nv_bfloat16* Chi = bat.Chi[z];
    __nv_bfloat16* Clo = bat.Clo[z];

    const int tid = threadIdx.x, wid = tid >> 5, lane = tid & 31;
    const int warp_m = wid & 3, warp_n = wid >> 2;
    const int mbase = blockIdx.y * 128, nbase = blockIdx.x * 128;
    const int g = lane >> 3, lr = lane & 7;

    const int KC = K / 64;            // 16
    const int NC = 3 * KC;            // 48
    const __nv_bfloat16* Aseg[3] = { Ahi, Alo, Ahi };
    const __nv_bfloat16* Bseg[3] = { Bhi, Bhi, Blo };

    float acc[2][8][4];
#pragma unroll
    for (int i = 0; i < 2; i++)
#pragma unroll
        for (int j = 0; j < 8; j++)
#pragma unroll
            for (int v = 0; v < 4; v++) acc[i][j][v] = 0.f;

    auto issue = [&](int ch) {
        const int seg = ch / KC, k0 = (ch % KC) * 64, s = ch & 1;
        const __nv_bfloat16* Ap = Aseg[seg] + (size_t)mbase * K + k0;
        const __nv_bfloat16* Bp = Bseg[seg] + (size_t)nbase * K + k0;
#pragma unroll
        for (int i = 0; i < 4; i++) {
            int idx = tid + i * 256;
            int r = idx >> 3, cb = (idx & 7) * 16;
            cp_async16(sa0 + s * G_STAGE + r * GS_STRIDE + cb,
                       (const char*)(Ap + (size_t)r * K) + cb);
            cp_async16(sb0 + s * G_STAGE + r * GS_STRIDE + cb,
                       (const char*)(Bp + (size_t)r * K) + cb);
        }
        asm volatile("cp.async.commit_group;" ::: "memory");
    };

    issue(0);
    for (int c = 0; c < NC; c++) {
        const int s = c & 1;
        if (c + 1 < NC) {
            issue(c + 1);
            asm volatile("cp.async.wait_group 1;" ::: "memory");
        } else {
            asm volatile("cp.async.wait_group 0;" ::: "memory");
        }
        __syncthreads();

        const uint32_t ab = sa0 + s * G_STAGE;
        const uint32_t bb = sb0 + s * G_STAGE;
#pragma unroll
        for (int kk = 0; kk < 4; kk++) {
            const uint32_t colb = kk * 32 + ((g >> 1) << 4);
            uint32_t afr[2][4];
#pragma unroll
            for (int i = 0; i < 2; i++) {
                int row = warp_m * 32 + i * 16 + ((g & 1) << 3) + lr;
                ld4(afr[i], ab + row * GS_STRIDE + colb);
            }
#pragma unroll
            for (int j = 0; j < 4; j++) {
                uint32_t bfr[4];
                int row = warp_n * 64 + j * 16 + ((g & 1) << 3) + lr;
                ld4(bfr, bb + row * GS_STRIDE + colb);
#pragma unroll
                for (int i = 0; i < 2; i++) {
                    mma16816(acc[i][2 * j + 0], afr[i], bfr[0], bfr[2]);
                    mma16816(acc[i][2 * j + 1], afr[i], bfr[1], bfr[3]);
                }
            }
        }
        __syncthreads();
    }

    // epilogue
#pragma unroll
    for (int i = 0; i < 2; i++) {
        int row0 = mbase + warp_m * 32 + i * 16 + (lane >> 2);
#pragma unroll
        for (int j = 0; j < 8; j++) {
            int col = nbase + warp_n * 64 + j * 8 + (lane & 3) * 2;
            float b0 = __ldg(bias + col), b1 = __ldg(bias + col + 1);
            float v0 = acc[i][j][0] + b0, v1 = acc[i][j][1] + b1;
            float v2 = acc[i][j][2] + b0, v3 = acc[i][j][3] + b1;
            if (C) {
                *(float2*)(C + (size_t)row0 * N + col) = make_float2(v0, v1);
                *(float2*)(C + (size_t)(row0 + 8) * N + col) = make_float2(v2, v3);
            }
            if (Chi) {
                __nv_bfloat16 h0 = __float2bfloat16(v0), h1 = __float2bfloat16(v1);
                __nv_bfloat16 h2 = __float2bfloat16(v2), h3 = __float2bfloat16(v3);
                *(uint32_t*)(Chi + (size_t)row0 * N + col) = packbf2(h0, h1);
                *(uint32_t*)(Chi + (size_t)(row0 + 8) * N + col) = packbf2(h2, h3);
                if (Clo) {
                    *(uint32_t*)(Clo + (size_t)row0 * N + col) =
                        packbf2(__float2bfloat16(v0 - __bfloat162float(h0)),
                                __float2bfloat16(v1 - __bfloat162float(h1)));
                    *(uint32_t*)(Clo + (size_t)(row0 + 8) * N + col) =
                        packbf2(__float2bfloat16(v2 - __bfloat162float(h2)),
                                __float2bfloat16(v3 - __bfloat162float(h3)));
                }
            }
        }
    }
}

// ---------------------------------------------------------------------------
// merged split of query/key/value: grid.y selects input -> plane y
// ---------------------------------------------------------------------------
__global__ __launch_bounds__(256)
void asplit3(const float* __restrict__ q, const float* __restrict__ k,
             const float* __restrict__ v,
             __nv_bfloat16* __restrict__ hi0, __nv_bfloat16* __restrict__ lo0)
{
    const int p = blockIdx.y;
    const float* A = (p == 0) ? q : (p == 1) ? k : v;
    __nv_bfloat16* hi = hi0 + (size_t)p * APLANE;
    __nv_bfloat16* lo = lo0 + (size_t)p * APLANE;
    int i = blockIdx.x * 256 + threadIdx.x;
    float4 val = ((const float4*)A)[i];
    __nv_bfloat16 h0 = __float2bfloat16(val.x), h1 = __float2bfloat16(val.y);
    __nv_bfloat16 h2 = __float2bfloat16(val.z), h3 = __float2bfloat16(val.w);
    __nv_bfloat162* hp = (__nv_bfloat162*)hi;
    __nv_bfloat162* lp = (__nv_bfloat162*)lo;
    hp[2 * i + 0] = __nv_bfloat162(h0, h1);
    hp[2 * i + 1] = __nv_bfloat162(h2, h3);
    lp[2 * i + 0] = __nv_bfloat162(__float2bfloat16(val.x - __bfloat162float(h0)),
                                   __float2bfloat16(val.y - __bfloat162float(h1)));
    lp[2 * i + 1] = __nv_bfloat162(__float2bfloat16(val.z - __bfloat162float(h2)),
                                   __float2bfloat16(val.w - __bfloat162float(h3)));
}

// ---------------------------------------------------------------------------
// merged transpose+split of all 4 weights: grid.z selects weight -> plane z
// ---------------------------------------------------------------------------
struct W4 { const float* W[4]; };

__global__ __launch_bounds__(256)
void wsplit(W4 ws, __nv_bfloat16* __restrict__ thi0, __nv_bfloat16* __restrict__ tlo0)
{
    __shared__ float t[32][33];
    const int z = blockIdx.z;
    const float* W = ws.W[z];
    __nv_bfloat16* thi = thi0 + (size_t)z * WPLANE;
    __nv_bfloat16* tlo = tlo0 + (size_t)z * WPLANE;
    const int n0 = blockIdx.x * 32, k0 = blockIdx.y * 32;
    const int x = threadIdx.x & 31, y = (threadIdx.x >> 5);
#pragma unroll
    for (int j = 0; j < 32; j += 8)
        t[y + j][x] = W[(size_t)(k0 + y + j) * DMM + n0 + x];
    __syncthreads();
#pragma unroll
    for (int j = 0; j < 32; j += 8) {
        float v = t[x][y + j];
        __nv_bfloat16 h = __float2bfloat16(v);
        size_t o = (size_t)(n0 + y + j) * DMM + k0 + x;
        thi[o] = h;
        tlo[o] = __float2bfloat16(v - __bfloat162float(h));
    }
}

// ============================================================================
// Fused attention, 2-pass normalized (identical to round-7 passing version).
// ============================================================================
#define FA_STRIDE 144
#define OFF_Q  0
#define OFF_K  18432
#define OFF_VH (OFF_K + 2*18432)
#define OFF_VL (OFF_VH + 2*18432)
#define OFF_O  (OFF_VL + 2*18432)
#define OFF_RS (OFF_O + 128*66*4)
#define OFF_INV (OFF_RS + 1024)
#define FA_SMEM (OFF_INV + 512)

__global__ __launch_bounds__(256, 1)
void fused_attn(const __nv_bfloat16* __restrict__ Qb, const __nv_bfloat16* __restrict__ Kb,
                const __nv_bfloat16* __restrict__ Vhi, const __nv_bfloat16* __restrict__ Vlo,
                const int* __restrict__ mask,
                __nv_bfloat16* __restrict__ AOhi, __nv_bfloat16* __restrict__ AOlo,
                float* __restrict__ ebuf, int writeE)
{
    extern __shared__ char smem[];
    const uint32_t sb = smem_u32(smem);
    const int tid = threadIdx.x, wid = tid >> 5, lane = tid & 31;
    const int warp_m = wid & 3, warp_n = wid >> 2;
    const int g = lane >> 3, lr = lane & 7;
    const int lr2 = lane >> 2, lc2 = (lane & 3) * 2;
    const int bh = blockIdx.y, b = bh >> 4;
    const int qbase = blockIdx.x * 128;

    const size_t chunk = (size_t)bh * (SS * 64);
    const int* mb = mask + (size_t)b * SS * SS;
    float* eb = ebuf + (size_t)bh * SS * SS;
    const float S64 = 1.0f / 64.0f;

    auto issueK = [&](int jt) {
        const int st = jt & 1;
        const size_t base = chunk + (size_t)jt * (128 * 64);
#pragma unroll
        for (int i = 0; i < 4; i++) {
            int idx = tid + i * 256;
            int r = idx >> 3, cb = (idx & 7) * 16;
            cp_async16(sb + OFF_K + st * 18432 + r * FA_STRIDE + cb,
                       (const char*)(Kb + base) + idx * 16);
        }
        asm volatile("cp.async.commit_group;" ::: "memory");
    };
    auto issueKV = [&](int jt) {
        const int st = jt & 1;
        const size_t base = chunk + (size_t)jt * (128 * 64);
#pragma unroll
        for (int i = 0; i < 4; i++) {
            int idx = tid + i * 256;
            int r = idx >> 3, cb = (idx & 7) * 16;
            cp_async16(sb + OFF_K  + st * 18432 + r * FA_STRIDE + cb, (const char*)(Kb  + base) + idx * 16);
            cp_async16(sb + OFF_VH + st * 18432 + r * FA_STRIDE + cb, (const char*)(Vhi + base) + idx * 16);
            cp_async16(sb + OFF_VL + st * 18432 + r * FA_STRIDE + cb, (const char*)(Vlo + base) + idx * 16);
        }
        asm volatile("cp.async.commit_group;" ::: "memory");
    };

    {
        const size_t qb0 = chunk + (size_t)qbase * 64;
#pragma unroll
        for (int i = 0; i < 4; i++) {
            int idx = tid + i * 256;
            int r = idx >> 3, cb = (idx & 7) * 16;
            cp_async16(sb + OFF_Q + r * FA_STRIDE + cb, (const char*)(Qb + qb0) + idx * 16);
        }
        issueK(0);
    }

    auto computeS = [&](int st, float (*acc_s)[8][4]) {
#pragma unroll
        for (int i = 0; i < 2; i++)
#pragma unroll
            for (int j = 0; j < 8; j++)
#pragma unroll
                for (int v = 0; v < 4; v++) acc_s[i][j][v] = 0.f;
        const uint32_t sKb = sb + OFF_K + st * 18432;
#pragma unroll
        for (int kk = 0; kk < 4; kk++) {
            const uint32_t colb = kk * 32 + ((g >> 1) << 4);
            uint32_t afr[2][4];
#pragma unroll
            for (int i = 0; i < 2; i++)
                ld4(afr[i], sb + OFF_Q + (warp_m * 32 + i * 16 + ((g & 1) << 3) + lr) * FA_STRIDE + colb);
#pragma unroll
            for (int jj = 0; jj < 4; jj++) {
                uint32_t bfr[4];
                ld4(bfr, sKb + (warp_n * 64 + jj * 16 + ((g & 1) << 3) + lr) * FA_STRIDE + colb);
#pragma unroll
                for (int i = 0; i < 2; i++) {
                    mma16816(acc_s[i][2 * jj + 0], afr[i], bfr[0], bfr[2]);
                    mma16816(acc_s[i][2 * jj + 1], afr[i], bfr[1], bfr[3]);
                }
            }
        }
    };

    // ================= PASS A: rowsums =================
    float rs[2][2] = {{0.f, 0.f}, {0.f, 0.f}};
    for (int jt = 0; jt < 8; jt++) {
        const int st = jt & 1;
        if (jt + 1 < 8) {
            issueK(jt + 1);
            asm volatile("cp.async.wait_group 1;" ::: "memory");
        } else {
            asm volatile("cp.async.wait_group 0;" ::: "memory");
        }
        __syncthreads();

        float acc_s[2][8][4];
        computeS(st, acc_s);

#pragma unroll
        for (int i = 0; i < 2; i++) {
            const int qr = qbase + warp_m * 32 + i * 16 + lr2;
#pragma unroll
            for (int jj = 0; jj < 8; jj++) {
                const int kc = jt * 128 + warp_n * 64 + jj * 8 + lc2;
                int2 m0 = __ldg((const int2*)(mb + (size_t)qr * SS + kc));
                int2 m1 = __ldg((const int2*)(mb + (size_t)(qr + 8) * SS + kc));
                float e0 = m0.x ? __expf(acc_s[i][jj][0] * S64) : 0.f;
                float e1 = m0.y ? __expf(acc_s[i][jj][1] * S64) : 0.f;
                float e2 = m1.x ? __expf(acc_s[i][jj][2] * S64) : 0.f;
                float e3 = m1.y ? __expf(acc_s[i][jj][3] * S64) : 0.f;
                rs[i][0] += e0 + e1;
                rs[i][1] += e2 + e3;
            }
        }
        __syncthreads();
    }

    float* s_rs = (float*)(smem + OFF_RS);
    float* sinv = (float*)(smem + OFF_INV);
#pragma unroll
    for (int i = 0; i < 2; i++)
#pragma unroll
        for (int h2 = 0; h2 < 2; h2++) {
            float v = rs[i][h2];
            v += __shfl_xor_sync(0xffffffffu, v, 1);
            v += __shfl_xor_sync(0xffffffffu, v, 2);
            if ((lane & 3) == 0)
                s_rs[warp_n * 128 + warp_m * 32 + i * 16 + lr2 + h2 * 8] = v;
        }
    __syncthreads();
    if (tid < 128) sinv[tid] = 1.0f / (s_rs[tid] + s_rs[128 + tid]);
    __syncthreads();

    float inva[2], invb[2];
#pragma unroll
    for (int i = 0; i < 2; i++) {
        int r = warp_m * 32 + i * 16 + lr2;
        inva[i] = sinv[r];
        invb[i] = sinv[r + 8];
    }

    // ================= PASS B: normalized attn + PV =================
    float acc_o[2][8][4];
#pragma unroll
    for (int i = 0; i < 2; i++)
#pragma unroll
        for (int j = 0; j < 8; j++)
#pragma unroll
            for (int v = 0; v < 4; v++) acc_o[i][j][v] = 0.f;

    issueKV(0);
    for (int jt = 0; jt < 8; jt++) {
        const int st = jt & 1;
        if (jt + 1 < 8) {
            issueKV(jt + 1);
            asm volatile("cp.async.wait_group 1;" ::: "memory");
        } else {
            asm volatile("cp.async.wait_group 0;" ::: "memory");
        }
        __syncthreads();

        float acc_s[2][8][4];
        computeS(st, acc_s);

#pragma unroll
        for (int i = 0; i < 2; i++) {
            const int qr = qbase + warp_m * 32 + i * 16 + lr2;
#pragma unroll
            for (int jj = 0; jj < 8; jj++) {
                const int kc = jt * 128 + warp_n * 64 + jj * 8 + lc2;
                int2 m0 = __ldg((const int2*)(mb + (size_t)qr * SS + kc));
                int2 m1 = __ldg((const int2*)(mb + (size_t)(qr + 8) * SS + kc));
                float e0 = m0.x ? __expf(acc_s[i][jj][0] * S64) * inva[i] : 0.f;
                float e1 = m0.y ? __expf(acc_s[i][jj][1] * S64) * inva[i] : 0.f;
                float e2 = m1.x ? __expf(acc_s[i][jj][2] * S64) * invb[i] : 0.f;
                float e3 = m1.y ? __expf(acc_s[i][jj][3] * S64) * invb[i] : 0.f;
                acc_s[i][jj][0] = e0; acc_s[i][jj][1] = e1;
                acc_s[i][jj][2] = e2; acc_s[i][jj][3] = e3;
                if (writeE) {
                    *(float2*)(eb + (size_t)qr * SS + kc) = make_float2(e0, e1);
                    *(float2*)(eb + (size_t)(qr + 8) * SS + kc) = make_float2(e2, e3);
                }
            }
        }

        const uint32_t sVh = sb + OFF_VH + st * 18432;
        const uint32_t sVl = sb + OFF_VL + st * 18432;
#pragma unroll
        for (int u = 0; u < 4; u++) {
            uint32_t vh[4][4], vl[4][4];
#pragma unroll
            for (int jj2 = 0; jj2 < 4; jj2++) {
                const uint32_t addr = (warp_n * 64 + u * 16 + ((g & 1) << 3) + lr) * FA_STRIDE
                                    + jj2 * 32 + ((g >> 1) << 4);
                ld4t(vh[jj2], sVh + addr);
                ld4t(vl[jj2], sVl + addr);
            }
#pragma unroll
            for (int i = 0; i < 2; i++) {
                uint32_t ah[4], al[4];
                packhl(acc_s[i][2 * u][0],     acc_s[i][2 * u][1],     ah[0], al[0]);
                packhl(acc_s[i][2 * u][2],     acc_s[i][2 * u][3],     ah[1], al[1]);
                packhl(acc_s[i][2 * u + 1][0], acc_s[i][2 * u + 1][1], ah[2], al[2]);
                packhl(acc_s[i][2 * u + 1][2], acc_s[i][2 * u + 1][3], ah[3], al[3]);
#pragma unroll
                for (int jj2 = 0; jj2 < 4; jj2++) {
                    mma16816(acc_o[i][2 * jj2 + 0], ah, vh[jj2][0], vh[jj2][1]);
                    mma16816(acc_o[i][2 * jj2 + 0], al, vh[jj2][0], vh[jj2][1]);
                    mma16816(acc_o[i][2 * jj2 + 0], ah, vl[jj2][0], vl[jj2][1]);
                    mma16816(acc_o[i][2 * jj2 + 1], ah, vh[jj2][2], vh[jj2][3]);
                    mma16816(acc_o[i][2 * jj2 + 1], al, vh[jj2][2], vh[jj2][3]);
                    mma16816(acc_o[i][2 * jj2 + 1], ah, vl[jj2][2], vl[jj2][3]);
                }
            }
        }
        __syncthreads();
    }

    // ---- O cross-warp reduce + store ----
    float* so = (float*)(smem + OFF_O);
    if (warp_n == 1) {
#pragma unroll
        for (int i = 0; i < 2; i++) {
            int r = warp_m * 32 + i * 16 + lr2;
#pragma unroll
            for (int jj = 0; jj < 8; jj++) {
                int c = jj * 8 + lc2;
                *(float2*)&so[r * 66 + c] = make_float2(acc_o[i][jj][0], acc_o[i][jj][1]);
                *(float2*)&so[(r + 8) * 66 + c] = make_float2(acc_o[i][jj][2], acc_o[i][jj][3]);
            }
        }
    }
    __syncthreads();
    if (warp_n == 0) {
#pragma unroll
        for (int i = 0; i < 2; i++) {
            int r = warp_m * 32 + i * 16 + lr2;
            size_t row0 = chunk + (size_t)(qbase + r) * 64;
            size_t row1 = chunk + (size_t)(qbase + r + 8) * 64;
#pragma unroll
            for (int jj = 0; jj < 8; jj++) {
                int c = jj * 8 + lc2;
                float o0 = acc_o[i][jj][0] + so[r * 66 + c];
                float o1 = acc_o[i][jj][1] + so[r * 66 + c + 1];
                float o2 = acc_o[i][jj][2] + so[(r + 8) * 66 + c];
                float o3 = acc_o[i][jj][3] + so[(r + 8) * 66 + c + 1];
                __nv_bfloat16 h0 = __float2bfloat16(o0), h1 = __float2bfloat16(o1);
                __nv_bfloat16 h2 = __float2bfloat16(o2), h3 = __float2bfloat16(o3);
                *(uint32_t*)(AOhi + row0 + c) = packbf2(h0, h1);
                *(uint32_t*)(AOhi + row1 + c) = packbf2(h2, h3);
                *(uint32_t*)(AOlo + row0 + c) =
                    packbf2(__float2bfloat16(o0 - __bfloat162float(h0)),
                            __float2bfloat16(o1 - __bfloat162float(h1)));
                *(uint32_t*)(AOlo + row1 + c) =
                    packbf2(__float2bfloat16(o2 - __bfloat162float(h2)),
                            __float2bfloat16(o3 - __bfloat162float(h3)));
            }
        }
    }
}

// ---------------------------------------------------------------------------
extern "C" void kernel_launch(void* const* d_in, const int* in_sizes, int n_in,
                              void* d_out, int out_size)
{
    const float* query = (const float*)d_in[0];
    const float* keyy  = (const float*)d_in[1];
    const float* value = (const float*)d_in[2];
    const int*   mask  = (const int*)  d_in[3];
    const float* Wq = (const float*)d_in[4];
    const float* bq = (const float*)d_in[5];
    const float* Wk = (const float*)d_in[6];
    const float* bk = (const float*)d_in[7];
    const float* Wv = (const float*)d_in[8];
    const float* bv = (const float*)d_in[9];
    const float* Wo = (const float*)d_in[10];
    const float* bo = (const float*)d_in[11];
    float* out = (float*)d_out;

    void *pattn, *pah, *pal, *pbh, *pbl, *pqb, *pkb, *pvh, *pvl, *paoh, *paol;
    cudaGetSymbolAddress(&pattn, g_attn);
    cudaGetSymbolAddress(&pah, g_Ahi);
    cudaGetSymbolAddress(&pal, g_Alo);
    cudaGetSymbolAddress(&pbh, g_Bhi);
    cudaGetSymbolAddress(&pbl, g_Blo);
    cudaGetSymbolAddress(&pqb, g_Qb);
    cudaGetSymbolAddress(&pkb, g_Kb);
    cudaGetSymbolAddress(&pvh, g_Vhi);
    cudaGetSymbolAddress(&pvl, g_Vlo);
    cudaGetSymbolAddress(&paoh, g_AOhi);
    cudaGetSymbolAddress(&paol, g_AOlo);

    __nv_bfloat16* Ahi = (__nv_bfloat16*)pah;
    __nv_bfloat16* Alo = (__nv_bfloat16*)pal;
    __nv_bfloat16* Bhi = (__nv_bfloat16*)pbh;
    __nv_bfloat16* Blo = (__nv_bfloat16*)pbl;
    __nv_bfloat16* Qb  = (__nv_bfloat16*)pqb;
    __nv_bfloat16* Kb  = (__nv_bfloat16*)pkb;
    __nv_bfloat16* Vhi = (__nv_bfloat16*)pvh;
    __nv_bfloat16* Vlo = (__nv_bfloat16*)pvl;
    __nv_bfloat16* AOhi = (__nv_bfloat16*)paoh;
    __nv_bfloat16* AOlo = (__nv_bfloat16*)paol;

    const long long OUT_ELEMS  = (long long)BB * SS * DMM;
    const long long ATTN_ELEMS = (long long)NBH * SS * SS;
    int writeE = ((long long)out_size >= OUT_ELEMS + ATTN_ELEMS) ? 1 : 0;
    float* attnbuf = writeE ? (out + OUT_ELEMS) : (float*)pattn;

    static int smem_set = 0;
    if (!smem_set) {
        cudaFuncSetAttribute(fused_attn, cudaFuncAttributeMaxDynamicSharedMemorySize, FA_SMEM);
        cudaFuncSetAttribute(gemm3x, cudaFuncAttributeMaxDynamicSharedMemorySize, G_SMEM);
        smem_set = 1;
    }

    const int n4 = MROWS * DMM / 4;
    dim3 thr(256);

    // split all A inputs (Q/K/V) in one launch
    asplit3<<<dim3(n4 / 256, 3), thr>>>(query, keyy, value, Ahi, Alo);

    // split all 4 weights in one launch
    W4 ws;
    ws.W[0] = Wq; ws.W[1] = Wk; ws.W[2] = Wv; ws.W[3] = Wo;
    wsplit<<<dim3(32, 32, 4), thr>>>(ws, Bhi, Blo);

    // Q/K/V projections in one batched gemm launch
    G3B bq3;
    for (int z = 0; z < 3; z++) {
        bq3.Ahi[z] = Ahi + (size_t)z * APLANE;
        bq3.Alo[z] = Alo + (size_t)z * APLANE;
        bq3.Bhi[z] = Bhi + (size_t)z * WPLANE;
        bq3.Blo[z] = Blo + (size_t)z * WPLANE;
        bq3.C[z] = nullptr;
    }
    bq3.bias[0] = bq; bq3.bias[1] = bk; bq3.bias[2] = bv;
    bq3.Chi[0] = Qb;  bq3.Chi[1] = Kb;  bq3.Chi[2] = Vhi;
    bq3.Clo[0] = nullptr; bq3.Clo[1] = nullptr; bq3.Clo[2] = Vlo;
    gemm3x<<<dim3(DMM / 128, MROWS / 128, 3), thr, G_SMEM>>>(bq3, MROWS, DMM, DMM);

    // fused attention -> AOhi/AOlo + normalized attn
    fused_attn<<<dim3(SS / 128, NBH), thr, FA_SMEM>>>(
        Qb, Kb, Vhi, Vlo, mask, AOhi, AOlo, attnbuf, writeE);

    // out = AO @ Wo + bo  (fp32)
    G3B bo3;
    bo3.Ahi[0] = AOhi; bo3.Alo[0] = AOlo;
    bo3.Bhi[0] = Bhi + 3 * WPLANE; bo3.Blo[0] = Blo + 3 * WPLANE;
    bo3.bias[0] = bo; bo3.C[0] = out; bo3.Chi[0] = nullptr; bo3.Clo[0] = nullptr;
    for (int z = 1; z < 3; z++) {
        bo3.Ahi[z] = nullptr; bo3.Alo[z] = nullptr; bo3.Bhi[z] = nullptr;
        bo3.Blo[z] = nullptr; bo3.bias[z] = nullptr; bo3.C[z] = nullptr;
        bo3.Chi[z] = nullptr; bo3.Clo[z] = nullptr;
    }
    gemm3x<<<dim3(DMM / 128, MROWS / 128, 1), thr, G_SMEM>>>(bo3, MROWS, DMM, DMM);
}

// round 11
// speedup vs baseline: 2.4255x; 1.0409x over previous
#include <cuda_runtime.h>
#include <cuda_bf16.h>
#include <cstdint>
#include <cstddef>

#define BB 8
#define SS 1024
#define DMM 1024
#define HH 16
#define DKK 64
#define DVV 64
#define MROWS (BB*SS)      /* 8192 */
#define NBH (BB*HH)        /* 128  */
#define APLANE ((size_t)MROWS*DMM)
#define WPLANE ((size_t)DMM*DMM)

// ---------------- scratch (static device globals; no runtime allocation) ----
__device__ float g_attn[(size_t)NBH*SS*SS];            // fallback attn buffer
__device__ __nv_bfloat16 g_Ahi[3*APLANE];
__device__ __nv_bfloat16 g_Alo[3*APLANE];
__device__ __nv_bfloat16 g_Bhi[4*WPLANE];
__device__ __nv_bfloat16 g_Blo[4*WPLANE];
__device__ __nv_bfloat16 g_Qb [APLANE];
__device__ __nv_bfloat16 g_Kb [APLANE];
__device__ __nv_bfloat16 g_Vhi[APLANE];
__device__ __nv_bfloat16 g_Vlo[APLANE];
__device__ __nv_bfloat16 g_AOhi[APLANE];
__device__ __nv_bfloat16 g_AOlo[APLANE];

// ============================================================================
// helpers (compute_80-level PTX only)
// ============================================================================
__device__ __forceinline__ uint32_t smem_u32(const void* p) {
    uint32_t a;
    asm("{ .reg .u64 t; cvta.to.shared.u64 t, %1; cvt.u32.u64 %0, t; }" : "=r"(a) : "l"(p));
    return a;
}
__device__ __forceinline__ void cp_async16(uint32_t dst, const void* src) {
    asm volatile("cp.async.cg.shared.global [%0], [%1], 16;" :: "r"(dst), "l"(src) : "memory");
}
__device__ __forceinline__ void ld4(uint32_t* r, uint32_t addr) {
    asm volatile("ldmatrix.sync.aligned.m8n8.x4.shared.b16 {%0,%1,%2,%3}, [%4];"
                 : "=r"(r[0]), "=r"(r[1]), "=r"(r[2]), "=r"(r[3]) : "r"(addr));
}
__device__ __forceinline__ void ld4t(uint32_t* r, uint32_t addr) {
    asm volatile("ldmatrix.sync.aligned.m8n8.x4.trans.shared.b16 {%0,%1,%2,%3}, [%4];"
                 : "=r"(r[0]), "=r"(r[1]), "=r"(r[2]), "=r"(r[3]) : "r"(addr));
}
__device__ __forceinline__ void mma16816(float* d, const uint32_t* a,
                                         uint32_t b0, uint32_t b1) {
    asm volatile(
        "mma.sync.aligned.m16n8k16.row.col.f32.bf16.bf16.f32 "
        "{%0,%1,%2,%3}, {%4,%5,%6,%7}, {%8,%9}, {%0,%1,%2,%3};"
        : "+f"(d[0]), "+f"(d[1]), "+f"(d[2]), "+f"(d[3])
        : "r"(a[0]), "r"(a[1]), "r"(a[2]), "r"(a[3]), "r"(b0), "r"(b1));
}
__device__ __forceinline__ uint32_t packbf2(__nv_bfloat16 x, __nv_bfloat16 y) {
    __nv_bfloat162 t; t.x = x; t.y = y;
    return *reinterpret_cast<uint32_t*>(&t);
}
__device__ __forceinline__ void packhl(float x, float y, uint32_t& h, uint32_t& l) {
    __nv_bfloat16 hx = __float2bfloat16(x), hy = __float2bfloat16(y);
    h = packbf2(hx, hy);
    l = packbf2(__float2bfloat16(x - __bfloat162float(hx)),
                __float2bfloat16(y - __bfloat162float(hy)));
}

// ============================================================================
// batched bf16x3 mma.sync GEMM: C[z] = A[z] @ W[z] + bias[z].  BK=64, 2-stage.
// launch_bounds(256,2): cap regs at 128 so 2 CTAs co-reside per SM.
// ============================================================================
#define GS_STRIDE 144                 /* bytes per smem row (72 bf16) */
#define G_STAGE (128*GS_STRIDE)       /* 18432 */
#define G_SMEM  (4*G_STAGE)           /* 73728 */

struct G3B {
    const __nv_bfloat16* Ahi[3];
    const __nv_bfloat16* Alo[3];
    const __nv_bfloat16* Bhi[3];
    const __nv_bfloat16* Blo[3];
    const float* bias[3];
    float* C[3];
    __nv_bfloat16* Chi[3];
    __nv_bfloat16* Clo[3];
};

__global__ __launch_bounds__(256, 2)
void gemm3x(G3B bat, int M, int N, int K)
{
    extern __shared__ char gsm[];
    const uint32_t sa0 = smem_u32(gsm);
    const uint32_t sb0 = sa0 + 2 * G_STAGE;
    const int z = blockIdx.z;

    const __nv_bfloat16* Ahi = bat.Ahi[z];
    const __nv_bfloat16* Alo = bat.Alo[z];
    const __nv_bfloat16* Bhi = bat.Bhi[z];
    const __nv_bfloat16* Blo = bat.Blo[z];
    const float* bias = bat.bias[z];
    float* C = bat.C[z];
    __nv_bfloat16* Chi = bat.Chi[z];
    __nv_bfloat16* Clo = bat.Clo[z];

    const int tid = threadIdx.x, wid = tid >> 5, lane = tid & 31;
    const int warp_m = wid & 3, warp_n = wid >> 2;
    const int mbase = blockIdx.y * 128, nbase = blockIdx.x * 128;
    const int g = lane >> 3, lr = lane & 7;

    const int KC = K / 64;            // 16
    const int NC = 3 * KC;            // 48
    const __nv_bfloat16* Aseg[3] = { Ahi, Alo, Ahi };
    const __nv_bfloat16* Bseg[3] = { Bhi, Bhi, Blo };

    float acc[2][8][4];
#pragma unroll
    for (int i = 0; i < 2; i++)
#pragma unroll
        for (int j = 0; j < 8; j++)
#pragma unroll
            for (int v = 0; v < 4; v++) acc[i][j][v] = 0.f;

    auto issue = [&](int ch) {
        const int seg = ch / KC, k0 = (ch % KC) * 64, s = ch & 1;
        const __nv_bfloat16* Ap = Aseg[seg] + (size_t)mbase * K + k0;
        const __nv_bfloat16* Bp = Bseg[seg] + (size_t)nbase * K + k0;
#pragma unroll
        for (int i = 0; i < 4; i++) {
            int idx = tid + i * 256;
            int r = idx >> 3, cb = (idx & 7) * 16;
            cp_async16(sa0 + s * G_STAGE + r * GS_STRIDE + cb,
                       (const char*)(Ap + (size_t)r * K) + cb);
            cp_async16(sb0 + s * G_STAGE + r * GS_STRIDE + cb,
                       (const char*)(Bp + (size_t)r * K) + cb);
        }
        asm volatile("cp.async.commit_group;" ::: "memory");
    };

    issue(0);
    for (int c = 0; c < NC; c++) {
        const int s = c & 1;
        if (c + 1 < NC) {
            issue(c + 1);
            asm volatile("cp.async.wait_group 1;" ::: "memory");
        } else {
            asm volatile("cp.async.wait_group 0;" ::: "memory");
        }
        __syncthreads();

        const uint32_t ab = sa0 + s * G_STAGE;
        const uint32_t bb = sb0 + s * G_STAGE;
#pragma unroll
        for (int kk = 0; kk < 4; kk++) {
            const uint32_t colb = kk * 32 + ((g >> 1) << 4);
            uint32_t afr[2][4];
#pragma unroll
            for (int i = 0; i < 2; i++) {
                int row = warp_m * 32 + i * 16 + ((g & 1) << 3) + lr;
                ld4(afr[i], ab + row * GS_STRIDE + colb);
            }
#pragma unroll
            for (int j = 0; j < 4; j++) {
                uint32_t bfr[4];
                int row = warp_n * 64 + j * 16 + ((g & 1) << 3) + lr;
                ld4(bfr, bb + row * GS_STRIDE + colb);
#pragma unroll
                for (int i = 0; i < 2; i++) {
                    mma16816(acc[i][2 * j + 0], afr[i], bfr[0], bfr[2]);
                    mma16816(acc[i][2 * j + 1], afr[i], bfr[1], bfr[3]);
                }
            }
        }
        __syncthreads();
    }

    // epilogue
#pragma unroll
    for (int i = 0; i < 2; i++) {
        int row0 = mbase + warp_m * 32 + i * 16 + (lane >> 2);
#pragma unroll
        for (int j = 0; j < 8; j++) {
            int col = nbase + warp_n * 64 + j * 8 + (lane & 3) * 2;
            float b0 = __ldg(bias + col), b1 = __ldg(bias + col + 1);
            float v0 = acc[i][j][0] + b0, v1 = acc[i][j][1] + b1;
            float v2 = acc[i][j][2] + b0, v3 = acc[i][j][3] + b1;
            if (C) {
                *(float2*)(C + (size_t)row0 * N + col) = make_float2(v0, v1);
                *(float2*)(C + (size_t)(row0 + 8) * N + col) = make_float2(v2, v3);
            }
            if (Chi) {
                __nv_bfloat16 h0 = __float2bfloat16(v0), h1 = __float2bfloat16(v1);
                __nv_bfloat16 h2 = __float2bfloat16(v2), h3 = __float2bfloat16(v3);
                *(uint32_t*)(Chi + (size_t)row0 * N + col) = packbf2(h0, h1);
                *(uint32_t*)(Chi + (size_t)(row0 + 8) * N + col) = packbf2(h2, h3);
                if (Clo) {
                    *(uint32_t*)(Clo + (size_t)row0 * N + col) =
                        packbf2(__float2bfloat16(v0 - __bfloat162float(h0)),
                                __float2bfloat16(v1 - __bfloat162float(h1)));
                    *(uint32_t*)(Clo + (size_t)(row0 + 8) * N + col) =
                        packbf2(__float2bfloat16(v2 - __bfloat162float(h2)),
                                __float2bfloat16(v3 - __bfloat162float(h3)));
                }
            }
        }
    }
}

// ---------------------------------------------------------------------------
// merged split of query/key/value: grid.y selects input -> plane y
// ---------------------------------------------------------------------------
__global__ __launch_bounds__(256)
void asplit3(const float* __restrict__ q, const float* __restrict__ k,
             const float* __restrict__ v,
             __nv_bfloat16* __restrict__ hi0, __nv_bfloat16* __restrict__ lo0)
{
    const int p = blockIdx.y;
    const float* A = (p == 0) ? q : (p == 1) ? k : v;
    __nv_bfloat16* hi = hi0 + (size_t)p * APLANE;
    __nv_bfloat16* lo = lo0 + (size_t)p * APLANE;
    int i = blockIdx.x * 256 + threadIdx.x;
    float4 val = ((const float4*)A)[i];
    __nv_bfloat16 h0 = __float2bfloat16(val.x), h1 = __float2bfloat16(val.y);
    __nv_bfloat16 h2 = __float2bfloat16(val.z), h3 = __float2bfloat16(val.w);
    __nv_bfloat162* hp = (__nv_bfloat162*)hi;
    __nv_bfloat162* lp = (__nv_bfloat162*)lo;
    hp[2 * i + 0] = __nv_bfloat162(h0, h1);
    hp[2 * i + 1] = __nv_bfloat162(h2, h3);
    lp[2 * i + 0] = __nv_bfloat162(__float2bfloat16(val.x - __bfloat162float(h0)),
                                   __float2bfloat16(val.y - __bfloat162float(h1)));
    lp[2 * i + 1] = __nv_bfloat162(__float2bfloat16(val.z - __bfloat162float(h2)),
                                   __float2bfloat16(val.w - __bfloat162float(h3)));
}

// ---------------------------------------------------------------------------
// merged transpose+split of all 4 weights: grid.z selects weight -> plane z
// ---------------------------------------------------------------------------
struct W4 { const float* W[4]; };

__global__ __launch_bounds__(256)
void wsplit(W4 ws, __nv_bfloat16* __restrict__ thi0, __nv_bfloat16* __restrict__ tlo0)
{
    __shared__ float t[32][33];
    const int z = blockIdx.z;
    const float* W = ws.W[z];
    __nv_bfloat16* thi = thi0 + (size_t)z * WPLANE;
    __nv_bfloat16* tlo = tlo0 + (size_t)z * WPLANE;
    const int n0 = blockIdx.x * 32, k0 = blockIdx.y * 32;
    const int x = threadIdx.x & 31, y = (threadIdx.x >> 5);
#pragma unroll
    for (int j = 0; j < 32; j += 8)
        t[y + j][x] = W[(size_t)(k0 + y + j) * DMM + n0 + x];
    __syncthreads();
#pragma unroll
    for (int j = 0; j < 32; j += 8) {
        float v = t[x][y + j];
        __nv_bfloat16 h = __float2bfloat16(v);
        size_t o = (size_t)(n0 + y + j) * DMM + k0 + x;
        thi[o] = h;
        tlo[o] = __float2bfloat16(v - __bfloat162float(h));
    }
}

// ============================================================================
// Fused attention, 2-pass normalized. Pass A caches mask predicates as warp
// ballots in smem; pass B reads them as broadcast LDS instead of gmem mask.
// ============================================================================
#define FA_STRIDE 144
#define OFF_Q  0
#define OFF_K  18432
#define OFF_VH (OFF_K + 2*18432)
#define OFF_VL (OFF_VH + 2*18432)
#define OFF_O  (OFF_VL + 2*18432)
#define OFF_RS (OFF_O + 128*66*4)
#define OFF_INV (OFF_RS + 1024)
#define OFF_MB (OFF_INV + 512)         /* 8 tiles x 8 warps x 2 x 8 x 16B = 16KB */
#define FA_SMEM (OFF_MB + 16384)       /* 180736 */

__global__ __launch_bounds__(256, 1)
void fused_attn(const __nv_bfloat16* __restrict__ Qb, const __nv_bfloat16* __restrict__ Kb,
                const __nv_bfloat16* __restrict__ Vhi, const __nv_bfloat16* __restrict__ Vlo,
                const int* __restrict__ mask,
                __nv_bfloat16* __restrict__ AOhi, __nv_bfloat16* __restrict__ AOlo,
                float* __restrict__ ebuf, int writeE)
{
    extern __shared__ char smem[];
    const uint32_t sb = smem_u32(smem);
    const int tid = threadIdx.x, wid = tid >> 5, lane = tid & 31;
    const int warp_m = wid & 3, warp_n = wid >> 2;
    const int g = lane >> 3, lr = lane & 7;
    const int lr2 = lane >> 2, lc2 = (lane & 3) * 2;
    const int bh = blockIdx.y, b = bh >> 4;
    const int qbase = blockIdx.x * 128;

    const size_t chunk = (size_t)bh * (SS * 64);
    const int* mb = mask + (size_t)b * SS * SS;
    float* eb = ebuf + (size_t)bh * SS * SS;
    const float S64 = 1.0f / 64.0f;

    auto issueK = [&](int jt) {
        const int st = jt & 1;
        const size_t base = chunk + (size_t)jt * (128 * 64);
#pragma unroll
        for (int i = 0; i < 4; i++) {
            int idx = tid + i * 256;
            int r = idx >> 3, cb = (idx & 7) * 16;
            cp_async16(sb + OFF_K + st * 18432 + r * FA_STRIDE + cb,
                       (const char*)(Kb + base) + idx * 16);
        }
        asm volatile("cp.async.commit_group;" ::: "memory");
    };
    auto issueKV = [&](int jt) {
        const int st = jt & 1;
        const size_t base = chunk + (size_t)jt * (128 * 64);
#pragma unroll
        for (int i = 0; i < 4; i++) {
            int idx = tid + i * 256;
            int r = idx >> 3, cb = (idx & 7) * 16;
            cp_async16(sb + OFF_K  + st * 18432 + r * FA_STRIDE + cb, (const char*)(Kb  + base) + idx * 16);
            cp_async16(sb + OFF_VH + st * 18432 + r * FA_STRIDE + cb, (const char*)(Vhi + base) + idx * 16);
            cp_async16(sb + OFF_VL + st * 18432 + r * FA_STRIDE + cb, (const char*)(Vlo + base) + idx * 16);
        }
        asm volatile("cp.async.commit_group;" ::: "memory");
    };

    {
        const size_t qb0 = chunk + (size_t)qbase * 64;
#pragma unroll
        for (int i = 0; i < 4; i++) {
            int idx = tid + i * 256;
            int r = idx >> 3, cb = (idx & 7) * 16;
            cp_async16(sb + OFF_Q + r * FA_STRIDE + cb, (const char*)(Qb + qb0) + idx * 16);
        }
        issueK(0);
    }

    auto computeS = [&](int st, float (*acc_s)[8][4]) {
#pragma unroll
        for (int i = 0; i < 2; i++)
#pragma unroll
            for (int j = 0; j < 8; j++)
#pragma unroll
                for (int v = 0; v < 4; v++) acc_s[i][j][v] = 0.f;
        const uint32_t sKb = sb + OFF_K + st * 18432;
#pragma unroll
        for (int kk = 0; kk < 4; kk++) {
            const uint32_t colb = kk * 32 + ((g >> 1) << 4);
            uint32_t afr[2][4];
#pragma unroll
            for (int i = 0; i < 2; i++)
                ld4(afr[i], sb + OFF_Q + (warp_m * 32 + i * 16 + ((g & 1) << 3) + lr) * FA_STRIDE + colb);
#pragma unroll
            for (int jj = 0; jj < 4; jj++) {
                uint32_t bfr[4];
                ld4(bfr, sKb + (warp_n * 64 + jj * 16 + ((g & 1) << 3) + lr) * FA_STRIDE + colb);
#pragma unroll
                for (int i = 0; i < 2; i++) {
                    mma16816(acc_s[i][2 * jj + 0], afr[i], bfr[0], bfr[2]);
                    mma16816(acc_s[i][2 * jj + 1], afr[i], bfr[1], bfr[3]);
                }
            }
        }
    };

    // mask-ballot slot address for (tile, i, jj) of this warp
    auto mbslot = [&](int jt, int i, int jj) -> uint32_t {
        return sb + OFF_MB + (((jt * 8 + wid) * 2 + i) * 8 + jj) * 16;
    };

    // ================= PASS A: rowsums + ballot cache =================
    float rs[2][2] = {{0.f, 0.f}, {0.f, 0.f}};
    for (int jt = 0; jt < 8; jt++) {
        const int st = jt & 1;
        if (jt + 1 < 8) {
            issueK(jt + 1);
            asm volatile("cp.async.wait_group 1;" ::: "memory");
        } else {
            asm volatile("cp.async.wait_group 0;" ::: "memory");
        }
        __syncthreads();

        float acc_s[2][8][4];
        computeS(st, acc_s);

#pragma unroll
        for (int i = 0; i < 2; i++) {
            const int qr = qbase + warp_m * 32 + i * 16 + lr2;
#pragma unroll
            for (int jj = 0; jj < 8; jj++) {
                const int kc = jt * 128 + warp_n * 64 + jj * 8 + lc2;
                int2 m0 = __ldg((const int2*)(mb + (size_t)qr * SS + kc));
                int2 m1 = __ldg((const int2*)(mb + (size_t)(qr + 8) * SS + kc));
                unsigned bl0 = __ballot_sync(0xffffffffu, m0.x != 0);
                unsigned bl1 = __ballot_sync(0xffffffffu, m0.y != 0);
                unsigned bl2 = __ballot_sync(0xffffffffu, m1.x != 0);
                unsigned bl3 = __ballot_sync(0xffffffffu, m1.y != 0);
                if (lane == 0) {
                    asm volatile("st.shared.v4.b32 [%0], {%1,%2,%3,%4};"
                                 :: "r"(mbslot(jt, i, jj)),
                                    "r"(bl0), "r"(bl1), "r"(bl2), "r"(bl3) : "memory");
                }
                float e0 = m0.x ? __expf(acc_s[i][jj][0] * S64) : 0.f;
                float e1 = m0.y ? __expf(acc_s[i][jj][1] * S64) : 0.f;
                float e2 = m1.x ? __expf(acc_s[i][jj][2] * S64) : 0.f;
                float e3 = m1.y ? __expf(acc_s[i][jj][3] * S64) : 0.f;
                rs[i][0] += e0 + e1;
                rs[i][1] += e2 + e3;
            }
        }
        __syncthreads();
    }

    float* s_rs = (float*)(smem + OFF_RS);
    float* sinv = (float*)(smem + OFF_INV);
#pragma unroll
    for (int i = 0; i < 2; i++)
#pragma unroll
        for (int h2 = 0; h2 < 2; h2++) {
            float v = rs[i][h2];
            v += __shfl_xor_sync(0xffffffffu, v, 1);
            v += __shfl_xor_sync(0xffffffffu, v, 2);
            if ((lane & 3) == 0)
                s_rs[warp_n * 128 + warp_m * 32 + i * 16 + lr2 + h2 * 8] = v;
        }
    __syncthreads();
    if (tid < 128) sinv[tid] = 1.0f / (s_rs[tid] + s_rs[128 + tid]);
    __syncthreads();

    float inva[2], invb[2];
#pragma unroll
    for (int i = 0; i < 2; i++) {
        int r = warp_m * 32 + i * 16 + lr2;
        inva[i] = sinv[r];
        invb[i] = sinv[r + 8];
    }

    // ================= PASS B: normalized attn + PV =================
    float acc_o[2][8][4];
#pragma unroll
    for (int i = 0; i < 2; i++)
#pragma unroll
        for (int j = 0; j < 8; j++)
#pragma unroll
            for (int v = 0; v < 4; v++) acc_o[i][j][v] = 0.f;

    issueKV(0);
    for (int jt = 0; jt < 8; jt++) {
        const int st = jt & 1;
        if (jt + 1 < 8) {
            issueKV(jt + 1);
            asm volatile("cp.async.wait_group 1;" ::: "memory");
        } else {
            asm volatile("cp.async.wait_group 0;" ::: "memory");
        }
        __syncthreads();

        float acc_s[2][8][4];
        computeS(st, acc_s);

#pragma unroll
        for (int i = 0; i < 2; i++) {
            const int qr = qbase + warp_m * 32 + i * 16 + lr2;
#pragma unroll
            for (int jj = 0; jj < 8; jj++) {
                const int kc = jt * 128 + warp_n * 64 + jj * 8 + lc2;
                uint32_t w0, w1, w2, w3;
                asm volatile("ld.shared.v4.b32 {%0,%1,%2,%3}, [%4];"
                             : "=r"(w0), "=r"(w1), "=r"(w2), "=r"(w3)
                             : "r"(mbslot(jt, i, jj)));
                bool b0 = (w0 >> lane) & 1u;
                bool b1 = (w1 >> lane) & 1u;
                bool b2 = (w2 >> lane) & 1u;
                bool b3 = (w3 >> lane) & 1u;
                float e0 = b0 ? __expf(acc_s[i][jj][0] * S64) * inva[i] : 0.f;
                float e1 = b1 ? __expf(acc_s[i][jj][1] * S64) * inva[i] : 0.f;
                float e2 = b2 ? __expf(acc_s[i][jj][2] * S64) * invb[i] : 0.f;
                float e3 = b3 ? __expf(acc_s[i][jj][3] * S64) * invb[i] : 0.f;
                acc_s[i][jj][0] = e0; acc_s[i][jj][1] = e1;
                acc_s[i][jj][2] = e2; acc_s[i][jj][3] = e3;
                if (writeE) {
                    *(float2*)(eb + (size_t)qr * SS + kc) = make_float2(e0, e1);
                    *(float2*)(eb + (size_t)(qr + 8) * SS + kc) = make_float2(e2, e3);
                }
            }
        }

        const uint32_t sVh = sb + OFF_VH + st * 18432;
        const uint32_t sVl = sb + OFF_VL + st * 18432;
#pragma unroll
        for (int u = 0; u < 4; u++) {
            uint32_t vh[4][4], vl[4][4];
#pragma unroll
            for (int jj2 = 0; jj2 < 4; jj2++) {
                const uint32_t addr = (warp_n * 64 + u * 16 + ((g & 1) << 3) + lr) * FA_STRIDE
                                    + jj2 * 32 + ((g >> 1) << 4);
                ld4t(vh[jj2], sVh + addr);
                ld4t(vl[jj2], sVl + addr);
            }
#pragma unroll
            for (int i = 0; i < 2; i++) {
                uint32_t ah[4], al[4];
                packhl(acc_s[i][2 * u][0],     acc_s[i][2 * u][1],     ah[0], al[0]);
                packhl(acc_s[i][2 * u][2],     acc_s[i][2 * u][3],     ah[1], al[1]);
                packhl(acc_s[i][2 * u + 1][0], acc_s[i][2 * u + 1][1], ah[2], al[2]);
                packhl(acc_s[i][2 * u + 1][2], acc_s[i][2 * u + 1][3], ah[3], al[3]);
#pragma unroll
                for (int jj2 = 0; jj2 < 4; jj2++) {
                    mma16816(acc_o[i][2 * jj2 + 0], ah, vh[jj2][0], vh[jj2][1]);
                    mma16816(acc_o[i][2 * jj2 + 0], al, vh[jj2][0], vh[jj2][1]);
                    mma16816(acc_o[i][2 * jj2 + 0], ah, vl[jj2][0], vl[jj2][1]);
                    mma16816(acc_o[i][2 * jj2 + 1], ah, vh[jj2][2], vh[jj2][3]);
                    mma16816(acc_o[i][2 * jj2 + 1], al, vh[jj2][2], vh[jj2][3]);
                    mma16816(acc_o[i][2 * jj2 + 1], ah, vl[jj2][2], vl[jj2][3]);
                }
            }
        }
        __syncthreads();
    }

    // ---- O cross-warp reduce + store ----
    float* so = (float*)(smem + OFF_O);
    if (warp_n == 1) {
#pragma unroll
        for (int i = 0; i < 2; i++) {
            int r = warp_m * 32 + i * 16 + lr2;
#pragma unroll
            for (int jj = 0; jj < 8; jj++) {
                int c = jj * 8 + lc2;
                *(float2*)&so[r * 66 + c] = make_float2(acc_o[i][jj][0], acc_o[i][jj][1]);
                *(float2*)&so[(r + 8) * 66 + c] = make_float2(acc_o[i][jj][2], acc_o[i][jj][3]);
            }
        }
    }
    __syncthreads();
    if (warp_n == 0) {
#pragma unroll
        for (int i = 0; i < 2; i++) {
            int r = warp_m * 32 + i * 16 + lr2;
            size_t row0 = chunk + (size_t)(qbase + r) * 64;
            size_t row1 = chunk + (size_t)(qbase + r + 8) * 64;
#pragma unroll
            for (int jj = 0; jj < 8; jj++) {
                int c = jj * 8 + lc2;
                float o0 = acc_o[i][jj][0] + so[r * 66 + c];
                float o1 = acc_o[i][jj][1] + so[r * 66 + c + 1];
                float o2 = acc_o[i][jj][2] + so[(r + 8) * 66 + c];
                float o3 = acc_o[i][jj][3] + so[(r + 8) * 66 + c + 1];
                __nv_bfloat16 h0 = __float2bfloat16(o0), h1 = __float2bfloat16(o1);
                __nv_bfloat16 h2 = __float2bfloat16(o2), h3 = __float2bfloat16(o3);
                *(uint32_t*)(AOhi + row0 + c) = packbf2(h0, h1);
                *(uint32_t*)(AOhi + row1 + c) = packbf2(h2, h3);
                *(uint32_t*)(AOlo + row0 + c) =
                    packbf2(__float2bfloat16(o0 - __bfloat162float(h0)),
                            __float2bfloat16(o1 - __bfloat162float(h1)));
                *(uint32_t*)(AOlo + row1 + c) =
                    packbf2(__float2bfloat16(o2 - __bfloat162float(h2)),
                            __float2bfloat16(o3 - __bfloat162float(h3)));
            }
        }
    }
}

// ---------------------------------------------------------------------------
extern "C" void kernel_launch(void* const* d_in, const int* in_sizes, int n_in,
                              void* d_out, int out_size)
{
    const float* query = (const float*)d_in[0];
    const float* keyy  = (const float*)d_in[1];
    const float* value = (const float*)d_in[2];
    const int*   mask  = (const int*)  d_in[3];
    const float* Wq = (const float*)d_in[4];
    const float* bq = (const float*)d_in[5];
    const float* Wk = (const float*)d_in[6];
    const float* bk = (const float*)d_in[7];
    const float* Wv = (const float*)d_in[8];
    const float* bv = (const float*)d_in[9];
    const float* Wo = (const float*)d_in[10];
    const float* bo = (const float*)d_in[11];
    float* out = (float*)d_out;

    void *pattn, *pah, *pal, *pbh, *pbl, *pqb, *pkb, *pvh, *pvl, *paoh, *paol;
    cudaGetSymbolAddress(&pattn, g_attn);
    cudaGetSymbolAddress(&pah, g_Ahi);
    cudaGetSymbolAddress(&pal, g_Alo);
    cudaGetSymbolAddress(&pbh, g_Bhi);
    cudaGetSymbolAddress(&pbl, g_Blo);
    cudaGetSymbolAddress(&pqb, g_Qb);
    cudaGetSymbolAddress(&pkb, g_Kb);
    cudaGetSymbolAddress(&pvh, g_Vhi);
    cudaGetSymbolAddress(&pvl, g_Vlo);
    cudaGetSymbolAddress(&paoh, g_AOhi);
    cudaGetSymbolAddress(&paol, g_AOlo);

    __nv_bfloat16* Ahi = (__nv_bfloat16*)pah;
    __nv_bfloat16* Alo = (__nv_bfloat16*)pal;
    __nv_bfloat16* Bhi = (__nv_bfloat16*)pbh;
    __nv_bfloat16* Blo = (__nv_bfloat16*)pbl;
    __nv_bfloat16* Qb  = (__nv_bfloat16*)pqb;
    __nv_bfloat16* Kb  = (__nv_bfloat16*)pkb;
    __nv_bfloat16* Vhi = (__nv_bfloat16*)pvh;
    __nv_bfloat16* Vlo = (__nv_bfloat16*)pvl;
    __nv_bfloat16* AOhi = (__nv_bfloat16*)paoh;
    __nv_bfloat16* AOlo = (__nv_bfloat16*)paol;

    const long long OUT_ELEMS  = (long long)BB * SS * DMM;
    const long long ATTN_ELEMS = (long long)NBH * SS * SS;
    int writeE = ((long long)out_size >= OUT_ELEMS + ATTN_ELEMS) ? 1 : 0;
    float* attnbuf = writeE ? (out + OUT_ELEMS) : (float*)pattn;

    static int smem_set = 0;
    if (!smem_set) {
        cudaFuncSetAttribute(fused_attn, cudaFuncAttributeMaxDynamicSharedMemorySize, FA_SMEM);
        cudaFuncSetAttribute(gemm3x, cudaFuncAttributeMaxDynamicSharedMemorySize, G_SMEM);
        smem_set = 1;
    }

    const int n4 = MROWS * DMM / 4;
    dim3 thr(256);

    // split all A inputs (Q/K/V) in one launch
    asplit3<<<dim3(n4 / 256, 3), thr>>>(query, keyy, value, Ahi, Alo);

    // split all 4 weights in one launch
    W4 ws;
    ws.W[0] = Wq; ws.W[1] = Wk; ws.W[2] = Wv; ws.W[3] = Wo;
    wsplit<<<dim3(32, 32, 4), thr>>>(ws, Bhi, Blo);

    // Q/K/V projections in one batched gemm launch
    G3B bq3;
    for (int z = 0; z < 3; z++) {
        bq3.Ahi[z] = Ahi + (size_t)z * APLANE;
        bq3.Alo[z] = Alo + (size_t)z * APLANE;
        bq3.Bhi[z] = Bhi + (size_t)z * WPLANE;
        bq3.Blo[z] = Blo + (size_t)z * WPLANE;
        bq3.C[z] = nullptr;
    }
    bq3.bias[0] = bq; bq3.bias[1] = bk; bq3.bias[2] = bv;
    bq3.Chi[0] = Qb;  bq3.Chi[1] = Kb;  bq3.Chi[2] = Vhi;
    bq3.Clo[0] = nullptr; bq3.Clo[1] = nullptr; bq3.Clo[2] = Vlo;
    gemm3x<<<dim3(DMM / 128, MROWS / 128, 3), thr, G_SMEM>>>(bq3, MROWS, DMM, DMM);

    // fused attention -> AOhi/AOlo + normalized attn
    fused_attn<<<dim3(SS / 128, NBH), thr, FA_SMEM>>>(
        Qb, Kb, Vhi, Vlo, mask, AOhi, AOlo, attnbuf, writeE);

    // out = AO @ Wo + bo  (fp32)
    G3B bo3;
    bo3.Ahi[0] = AOhi; bo3.Alo[0] = AOlo;
    bo3.Bhi[0] = Bhi + 3 * WPLANE; bo3.Blo[0] = Blo + 3 * WPLANE;
    bo3.bias[0] = bo; bo3.C[0] = out; bo3.Chi[0] = nullptr; bo3.Clo[0] = nullptr;
    for (int z = 1; z < 3; z++) {
        bo3.Ahi[z] = nullptr; bo3.Alo[z] = nullptr; bo3.Bhi[z] = nullptr;
        bo3.Blo[z] = nullptr; bo3.bias[z] = nullptr; bo3.C[z] = nullptr;
        bo3.Chi[z] = nullptr; bo3.Clo[z] = nullptr;
    }
    gemm3x<<<dim3(DMM / 128, MROWS / 128, 1), thr, G_SMEM>>>(bo3, MROWS, DMM, DMM);
}

// round 12
// speedup vs baseline: 2.5753x; 1.0617x over previous
#include <cuda_runtime.h>
#include <cuda_bf16.h>
#include <cstdint>
#include <cstddef>

#define BB 8
#define SS 1024
#define DMM 1024
#define HH 16
#define DKK 64
#define DVV 64
#define MROWS (BB*SS)      /* 8192 */
#define NBH (BB*HH)        /* 128  */
#define APLANE ((size_t)MROWS*DMM)
#define WPLANE ((size_t)DMM*DMM)

// ---------------- scratch (static device globals; no runtime allocation) ----
__device__ float g_attn[(size_t)NBH*SS*SS];            // fallback attn buffer
__device__ __nv_bfloat16 g_Ahi[3*APLANE];
__device__ __nv_bfloat16 g_Alo[3*APLANE];
__device__ __nv_bfloat16 g_Bhi[4*WPLANE];
__device__ __nv_bfloat16 g_Blo[4*WPLANE];
__device__ __nv_bfloat16 g_Qb [APLANE];
__device__ __nv_bfloat16 g_Kb [APLANE];
__device__ __nv_bfloat16 g_Vhi[APLANE];
__device__ __nv_bfloat16 g_Vlo[APLANE];
__device__ __nv_bfloat16 g_AOhi[APLANE];
__device__ __nv_bfloat16 g_AOlo[APLANE];

// ============================================================================
// helpers (compute_80-level PTX only)
// ============================================================================
__device__ __forceinline__ uint32_t smem_u32(const void* p) {
    uint32_t a;
    asm("{ .reg .u64 t; cvta.to.shared.u64 t, %1; cvt.u32.u64 %0, t; }" : "=r"(a) : "l"(p));
    return a;
}
__device__ __forceinline__ void cp_async16(uint32_t dst, const void* src) {
    asm volatile("cp.async.cg.shared.global [%0], [%1], 16;" :: "r"(dst), "l"(src) : "memory");
}
__device__ __forceinline__ void ld4(uint32_t* r, uint32_t addr) {
    asm volatile("ldmatrix.sync.aligned.m8n8.x4.shared.b16 {%0,%1,%2,%3}, [%4];"
                 : "=r"(r[0]), "=r"(r[1]), "=r"(r[2]), "=r"(r[3]) : "r"(addr));
}
__device__ __forceinline__ void ld4t(uint32_t* r, uint32_t addr) {
    asm volatile("ldmatrix.sync.aligned.m8n8.x4.trans.shared.b16 {%0,%1,%2,%3}, [%4];"
                 : "=r"(r[0]), "=r"(r[1]), "=r"(r[2]), "=r"(r[3]) : "r"(addr));
}
__device__ __forceinline__ void mma16816(float* d, const uint32_t* a,
                                         uint32_t b0, uint32_t b1) {
    asm volatile(
        "mma.sync.aligned.m16n8k16.row.col.f32.bf16.bf16.f32 "
        "{%0,%1,%2,%3}, {%4,%5,%6,%7}, {%8,%9}, {%0,%1,%2,%3};"
        : "+f"(d[0]), "+f"(d[1]), "+f"(d[2]), "+f"(d[3])
        : "r"(a[0]), "r"(a[1]), "r"(a[2]), "r"(a[3]), "r"(b0), "r"(b1));
}
__device__ __forceinline__ uint32_t packbf2(__nv_bfloat16 x, __nv_bfloat16 y) {
    __nv_bfloat162 t; t.x = x; t.y = y;
    return *reinterpret_cast<uint32_t*>(&t);
}
__device__ __forceinline__ void packhl(float x, float y, uint32_t& h, uint32_t& l) {
    __nv_bfloat16 hx = __float2bfloat16(x), hy = __float2bfloat16(y);
    h = packbf2(hx, hy);
    l = packbf2(__float2bfloat16(x - __bfloat162float(hx)),
                __float2bfloat16(y - __bfloat162float(hy)));
}

// ============================================================================
// batched bf16x[nseg] mma.sync GEMM: C[z] = A[z] @ W[z] + bias[z].
// nseg=3: hi*hi + lo*hi + hi*lo.  nseg=2: hi*hi + lo*hi (for bf16-bound outputs)
// BK=64, 2-stage. launch_bounds(256,2) for 2 CTAs/SM.
// ============================================================================
#define GS_STRIDE 144                 /* bytes per smem row (72 bf16) */
#define G_STAGE (128*GS_STRIDE)       /* 18432 */
#define G_SMEM  (4*G_STAGE)           /* 73728 */

struct G3B {
    const __nv_bfloat16* Ahi[3];
    const __nv_bfloat16* Alo[3];
    const __nv_bfloat16* Bhi[3];
    const __nv_bfloat16* Blo[3];
    const float* bias[3];
    float* C[3];
    __nv_bfloat16* Chi[3];
    __nv_bfloat16* Clo[3];
    int nseg[3];
};

__global__ __launch_bounds__(256, 2)
void gemm3x(G3B bat, int M, int N, int K)
{
    extern __shared__ char gsm[];
    const uint32_t sa0 = smem_u32(gsm);
    const uint32_t sb0 = sa0 + 2 * G_STAGE;
    const int z = blockIdx.z;

    const __nv_bfloat16* Ahi = bat.Ahi[z];
    const __nv_bfloat16* Alo = bat.Alo[z];
    const __nv_bfloat16* Bhi = bat.Bhi[z];
    const __nv_bfloat16* Blo = bat.Blo[z];
    const float* bias = bat.bias[z];
    float* C = bat.C[z];
    __nv_bfloat16* Chi = bat.Chi[z];
    __nv_bfloat16* Clo = bat.Clo[z];

    const int tid = threadIdx.x, wid = tid >> 5, lane = tid & 31;
    const int warp_m = wid & 3, warp_n = wid >> 2;
    const int mbase = blockIdx.y * 128, nbase = blockIdx.x * 128;
    const int g = lane >> 3, lr = lane & 7;

    const int KC = K / 64;               // 16
    const int NC = bat.nseg[z] * KC;     // 32 or 48
    const __nv_bfloat16* Aseg[3] = { Ahi, Alo, Ahi };
    const __nv_bfloat16* Bseg[3] = { Bhi, Bhi, Blo };

    float acc[2][8][4];
#pragma unroll
    for (int i = 0; i < 2; i++)
#pragma unroll
        for (int j = 0; j < 8; j++)
#pragma unroll
            for (int v = 0; v < 4; v++) acc[i][j][v] = 0.f;

    auto issue = [&](int ch) {
        const int seg = ch / KC, k0 = (ch % KC) * 64, s = ch & 1;
        const __nv_bfloat16* Ap = Aseg[seg] + (size_t)mbase * K + k0;
        const __nv_bfloat16* Bp = Bseg[seg] + (size_t)nbase * K + k0;
#pragma unroll
        for (int i = 0; i < 4; i++) {
            int idx = tid + i * 256;
            int r = idx >> 3, cb = (idx & 7) * 16;
            cp_async16(sa0 + s * G_STAGE + r * GS_STRIDE + cb,
                       (const char*)(Ap + (size_t)r * K) + cb);
            cp_async16(sb0 + s * G_STAGE + r * GS_STRIDE + cb,
                       (const char*)(Bp + (size_t)r * K) + cb);
        }
        asm volatile("cp.async.commit_group;" ::: "memory");
    };

    issue(0);
    for (int c = 0; c < NC; c++) {
        const int s = c & 1;
        if (c + 1 < NC) {
            issue(c + 1);
            asm volatile("cp.async.wait_group 1;" ::: "memory");
        } else {
            asm volatile("cp.async.wait_group 0;" ::: "memory");
        }
        __syncthreads();

        const uint32_t ab = sa0 + s * G_STAGE;
        const uint32_t bb = sb0 + s * G_STAGE;
#pragma unroll
        for (int kk = 0; kk < 4; kk++) {
            const uint32_t colb = kk * 32 + ((g >> 1) << 4);
            uint32_t afr[2][4];
#pragma unroll
            for (int i = 0; i < 2; i++) {
                int row = warp_m * 32 + i * 16 + ((g & 1) << 3) + lr;
                ld4(afr[i], ab + row * GS_STRIDE + colb);
            }
#pragma unroll
            for (int j = 0; j < 4; j++) {
                uint32_t bfr[4];
                int row = warp_n * 64 + j * 16 + ((g & 1) << 3) + lr;
                ld4(bfr, bb + row * GS_STRIDE + colb);
#pragma unroll
                for (int i = 0; i < 2; i++) {
                    mma16816(acc[i][2 * j + 0], afr[i], bfr[0], bfr[2]);
                    mma16816(acc[i][2 * j + 1], afr[i], bfr[1], bfr[3]);
                }
            }
        }
        __syncthreads();
    }

    // epilogue
#pragma unroll
    for (int i = 0; i < 2; i++) {
        int row0 = mbase + warp_m * 32 + i * 16 + (lane >> 2);
#pragma unroll
        for (int j = 0; j < 8; j++) {
            int col = nbase + warp_n * 64 + j * 8 + (lane & 3) * 2;
            float b0 = __ldg(bias + col), b1 = __ldg(bias + col + 1);
            float v0 = acc[i][j][0] + b0, v1 = acc[i][j][1] + b1;
            float v2 = acc[i][j][2] + b0, v3 = acc[i][j][3] + b1;
            if (C) {
                *(float2*)(C + (size_t)row0 * N + col) = make_float2(v0, v1);
                *(float2*)(C + (size_t)(row0 + 8) * N + col) = make_float2(v2, v3);
            }
            if (Chi) {
                __nv_bfloat16 h0 = __float2bfloat16(v0), h1 = __float2bfloat16(v1);
                __nv_bfloat16 h2 = __float2bfloat16(v2), h3 = __float2bfloat16(v3);
                *(uint32_t*)(Chi + (size_t)row0 * N + col) = packbf2(h0, h1);
                *(uint32_t*)(Chi + (size_t)(row0 + 8) * N + col) = packbf2(h2, h3);
                if (Clo) {
                    *(uint32_t*)(Clo + (size_t)row0 * N + col) =
                        packbf2(__float2bfloat16(v0 - __bfloat162float(h0)),
                                __float2bfloat16(v1 - __bfloat162float(h1)));
                    *(uint32_t*)(Clo + (size_t)(row0 + 8) * N + col) =
                        packbf2(__float2bfloat16(v2 - __bfloat162float(h2)),
                                __float2bfloat16(v3 - __bfloat162float(h3)));
                }
            }
        }
    }
}

// ---------------------------------------------------------------------------
// merged split of query/key/value: grid.y selects input -> plane y
// ---------------------------------------------------------------------------
__global__ __launch_bounds__(256)
void asplit3(const float* __restrict__ q, const float* __restrict__ k,
             const float* __restrict__ v,
             __nv_bfloat16* __restrict__ hi0, __nv_bfloat16* __restrict__ lo0)
{
    const int p = blockIdx.y;
    const float* A = (p == 0) ? q : (p == 1) ? k : v;
    __nv_bfloat16* hi = hi0 + (size_t)p * APLANE;
    __nv_bfloat16* lo = lo0 + (size_t)p * APLANE;
    int i = blockIdx.x * 256 + threadIdx.x;
    float4 val = ((const float4*)A)[i];
    __nv_bfloat16 h0 = __float2bfloat16(val.x), h1 = __float2bfloat16(val.y);
    __nv_bfloat16 h2 = __float2bfloat16(val.z), h3 = __float2bfloat16(val.w);
    __nv_bfloat162* hp = (__nv_bfloat162*)hi;
    __nv_bfloat162* lp = (__nv_bfloat162*)lo;
    hp[2 * i + 0] = __nv_bfloat162(h0, h1);
    hp[2 * i + 1] = __nv_bfloat162(h2, h3);
    lp[2 * i + 0] = __nv_bfloat162(__float2bfloat16(val.x - __bfloat162float(h0)),
                                   __float2bfloat16(val.y - __bfloat162float(h1)));
    lp[2 * i + 1] = __nv_bfloat162(__float2bfloat16(val.z - __bfloat162float(h2)),
                                   __float2bfloat16(val.w - __bfloat162float(h3)));
}

// ---------------------------------------------------------------------------
// merged transpose+split of all 4 weights: grid.z selects weight -> plane z
// ---------------------------------------------------------------------------
struct W4 { const float* W[4]; };

__global__ __launch_bounds__(256)
void wsplit(W4 ws, __nv_bfloat16* __restrict__ thi0, __nv_bfloat16* __restrict__ tlo0)
{
    __shared__ float t[32][33];
    const int z = blockIdx.z;
    const float* W = ws.W[z];
    __nv_bfloat16* thi = thi0 + (size_t)z * WPLANE;
    __nv_bfloat16* tlo = tlo0 + (size_t)z * WPLANE;
    const int n0 = blockIdx.x * 32, k0 = blockIdx.y * 32;
    const int x = threadIdx.x & 31, y = (threadIdx.x >> 5);
#pragma unroll
    for (int j = 0; j < 32; j += 8)
        t[y + j][x] = W[(size_t)(k0 + y + j) * DMM + n0 + x];
    __syncthreads();
#pragma unroll
    for (int j = 0; j < 32; j += 8) {
        float v = t[x][y + j];
        __nv_bfloat16 h = __float2bfloat16(v);
        size_t o = (size_t)(n0 + y + j) * DMM + k0 + x;
        thi[o] = h;
        tlo[o] = __float2bfloat16(v - __bfloat162float(h));
    }
}

// ============================================================================
// Fused attention, 2-pass normalized. Pass A caches mask predicates as warp
// ballots in smem; pass B reads them as broadcast LDS instead of gmem mask.
// ============================================================================
#define FA_STRIDE 144
#define OFF_Q  0
#define OFF_K  18432
#define OFF_VH (OFF_K + 2*18432)
#define OFF_VL (OFF_VH + 2*18432)
#define OFF_O  (OFF_VL + 2*18432)
#define OFF_RS (OFF_O + 128*66*4)
#define OFF_INV (OFF_RS + 1024)
#define OFF_MB (OFF_INV + 512)         /* 8 tiles x 8 warps x 2 x 8 x 16B = 16KB */
#define FA_SMEM (OFF_MB + 16384)       /* 180736 */

__global__ __launch_bounds__(256, 1)
void fused_attn(const __nv_bfloat16* __restrict__ Qb, const __nv_bfloat16* __restrict__ Kb,
                const __nv_bfloat16* __restrict__ Vhi, const __nv_bfloat16* __restrict__ Vlo,
                const int* __restrict__ mask,
                __nv_bfloat16* __restrict__ AOhi, __nv_bfloat16* __restrict__ AOlo,
                float* __restrict__ ebuf, int writeE)
{
    extern __shared__ char smem[];
    const uint32_t sb = smem_u32(smem);
    const int tid = threadIdx.x, wid = tid >> 5, lane = tid & 31;
    const int warp_m = wid & 3, warp_n = wid >> 2;
    const int g = lane >> 3, lr = lane & 7;
    const int lr2 = lane >> 2, lc2 = (lane & 3) * 2;
    const int bh = blockIdx.y, b = bh >> 4;
    const int qbase = blockIdx.x * 128;

    const size_t chunk = (size_t)bh * (SS * 64);
    const int* mb = mask + (size_t)b * SS * SS;
    float* eb = ebuf + (size_t)bh * SS * SS;
    const float S64 = 1.0f / 64.0f;

    auto issueK = [&](int jt) {
        const int st = jt & 1;
        const size_t base = chunk + (size_t)jt * (128 * 64);
#pragma unroll
        for (int i = 0; i < 4; i++) {
            int idx = tid + i * 256;
            int r = idx >> 3, cb = (idx & 7) * 16;
            cp_async16(sb + OFF_K + st * 18432 + r * FA_STRIDE + cb,
                       (const char*)(Kb + base) + idx * 16);
        }
        asm volatile("cp.async.commit_group;" ::: "memory");
    };
    auto issueKV = [&](int jt) {
        const int st = jt & 1;
        const size_t base = chunk + (size_t)jt * (128 * 64);
#pragma unroll
        for (int i = 0; i < 4; i++) {
            int idx = tid + i * 256;
            int r = idx >> 3, cb = (idx & 7) * 16;
            cp_async16(sb + OFF_K  + st * 18432 + r * FA_STRIDE + cb, (const char*)(Kb  + base) + idx * 16);
            cp_async16(sb + OFF_VH + st * 18432 + r * FA_STRIDE + cb, (const char*)(Vhi + base) + idx * 16);
            cp_async16(sb + OFF_VL + st * 18432 + r * FA_STRIDE + cb, (const char*)(Vlo + base) + idx * 16);
        }
        asm volatile("cp.async.commit_group;" ::: "memory");
    };

    {
        const size_t qb0 = chunk + (size_t)qbase * 64;
#pragma unroll
        for (int i = 0; i < 4; i++) {
            int idx = tid + i * 256;
            int r = idx >> 3, cb = (idx & 7) * 16;
            cp_async16(sb + OFF_Q + r * FA_STRIDE + cb, (const char*)(Qb + qb0) + idx * 16);
        }
        issueK(0);
    }

    auto computeS = [&](int st, float (*acc_s)[8][4]) {
#pragma unroll
        for (int i = 0; i < 2; i++)
#pragma unroll
            for (int j = 0; j < 8; j++)
#pragma unroll
                for (int v = 0; v < 4; v++) acc_s[i][j][v] = 0.f;
        const uint32_t sKb = sb + OFF_K + st * 18432;
#pragma unroll
        for (int kk = 0; kk < 4; kk++) {
            const uint32_t colb = kk * 32 + ((g >> 1) << 4);
            uint32_t afr[2][4];
#pragma unroll
            for (int i = 0; i < 2; i++)
                ld4(afr[i], sb + OFF_Q + (warp_m * 32 + i * 16 + ((g & 1) << 3) + lr) * FA_STRIDE + colb);
#pragma unroll
            for (int jj = 0; jj < 4; jj++) {
                uint32_t bfr[4];
                ld4(bfr, sKb + (warp_n * 64 + jj * 16 + ((g & 1) << 3) + lr) * FA_STRIDE + colb);
#pragma unroll
                for (int i = 0; i < 2; i++) {
                    mma16816(acc_s[i][2 * jj + 0], afr[i], bfr[0], bfr[2]);
                    mma16816(acc_s[i][2 * jj + 1], afr[i], bfr[1], bfr[3]);
                }
            }
        }
    };

    // mask-ballot slot address for (tile, i, jj) of this warp
    auto mbslot = [&](int jt, int i, int jj) -> uint32_t {
        return sb + OFF_MB + (((jt * 8 + wid) * 2 + i) * 8 + jj) * 16;
    };

    // ================= PASS A: rowsums + ballot cache =================
    float rs[2][2] = {{0.f, 0.f}, {0.f, 0.f}};
    for (int jt = 0; jt < 8; jt++) {
        const int st = jt & 1;
        if (jt + 1 < 8) {
            issueK(jt + 1);
            asm volatile("cp.async.wait_group 1;" ::: "memory");
        } else {
            asm volatile("cp.async.wait_group 0;" ::: "memory");
        }
        __syncthreads();

        float acc_s[2][8][4];
        computeS(st, acc_s);

#pragma unroll
        for (int i = 0; i < 2; i++) {
            const int qr = qbase + warp_m * 32 + i * 16 + lr2;
#pragma unroll
            for (int jj = 0; jj < 8; jj++) {
                const int kc = jt * 128 + warp_n * 64 + jj * 8 + lc2;
                int2 m0 = __ldg((const int2*)(mb + (size_t)qr * SS + kc));
                int2 m1 = __ldg((const int2*)(mb + (size_t)(qr + 8) * SS + kc));
                unsigned bl0 = __ballot_sync(0xffffffffu, m0.x != 0);
                unsigned bl1 = __ballot_sync(0xffffffffu, m0.y != 0);
                unsigned bl2 = __ballot_sync(0xffffffffu, m1.x != 0);
                unsigned bl3 = __ballot_sync(0xffffffffu, m1.y != 0);
                if (lane == 0) {
                    asm volatile("st.shared.v4.b32 [%0], {%1,%2,%3,%4};"
                                 :: "r"(mbslot(jt, i, jj)),
                                    "r"(bl0), "r"(bl1), "r"(bl2), "r"(bl3) : "memory");
                }
                float e0 = m0.x ? __expf(acc_s[i][jj][0] * S64) : 0.f;
                float e1 = m0.y ? __expf(acc_s[i][jj][1] * S64) : 0.f;
                float e2 = m1.x ? __expf(acc_s[i][jj][2] * S64) : 0.f;
                float e3 = m1.y ? __expf(acc_s[i][jj][3] * S64) : 0.f;
                rs[i][0] += e0 + e1;
                rs[i][1] += e2 + e3;
            }
        }
        __syncthreads();
    }

    float* s_rs = (float*)(smem + OFF_RS);
    float* sinv = (float*)(smem + OFF_INV);
#pragma unroll
    for (int i = 0; i < 2; i++)
#pragma unroll
        for (int h2 = 0; h2 < 2; h2++) {
            float v = rs[i][h2];
            v += __shfl_xor_sync(0xffffffffu, v, 1);
            v += __shfl_xor_sync(0xffffffffu, v, 2);
            if ((lane & 3) == 0)
                s_rs[warp_n * 128 + warp_m * 32 + i * 16 + lr2 + h2 * 8] = v;
        }
    __syncthreads();
    if (tid < 128) sinv[tid] = 1.0f / (s_rs[tid] + s_rs[128 + tid]);
    __syncthreads();

    float inva[2], invb[2];
#pragma unroll
    for (int i = 0; i < 2; i++) {
        int r = warp_m * 32 + i * 16 + lr2;
        inva[i] = sinv[r];
        invb[i] = sinv[r + 8];
    }

    // ================= PASS B: normalized attn + PV =================
    float acc_o[2][8][4];
#pragma unroll
    for (int i = 0; i < 2; i++)
#pragma unroll
        for (int j = 0; j < 8; j++)
#pragma unroll
            for (int v = 0; v < 4; v++) acc_o[i][j][v] = 0.f;

    issueKV(0);
    for (int jt = 0; jt < 8; jt++) {
        const int st = jt & 1;
        if (jt + 1 < 8) {
            issueKV(jt + 1);
            asm volatile("cp.async.wait_group 1;" ::: "memory");
        } else {
            asm volatile("cp.async.wait_group 0;" ::: "memory");
        }
        __syncthreads();

        float acc_s[2][8][4];
        computeS(st, acc_s);

#pragma unroll
        for (int i = 0; i < 2; i++) {
            const int qr = qbase + warp_m * 32 + i * 16 + lr2;
#pragma unroll
            for (int jj = 0; jj < 8; jj++) {
                const int kc = jt * 128 + warp_n * 64 + jj * 8 + lc2;
                uint32_t w0, w1, w2, w3;
                asm volatile("ld.shared.v4.b32 {%0,%1,%2,%3}, [%4];"
                             : "=r"(w0), "=r"(w1), "=r"(w2), "=r"(w3)
                             : "r"(mbslot(jt, i, jj)));
                bool b0 = (w0 >> lane) & 1u;
                bool b1 = (w1 >> lane) & 1u;
                bool b2 = (w2 >> lane) & 1u;
                bool b3 = (w3 >> lane) & 1u;
                float e0 = b0 ? __expf(acc_s[i][jj][0] * S64) * inva[i] : 0.f;
                float e1 = b1 ? __expf(acc_s[i][jj][1] * S64) * inva[i] : 0.f;
                float e2 = b2 ? __expf(acc_s[i][jj][2] * S64) * invb[i] : 0.f;
                float e3 = b3 ? __expf(acc_s[i][jj][3] * S64) * invb[i] : 0.f;
                acc_s[i][jj][0] = e0; acc_s[i][jj][1] = e1;
                acc_s[i][jj][2] = e2; acc_s[i][jj][3] = e3;
                if (writeE) {
                    *(float2*)(eb + (size_t)qr * SS + kc) = make_float2(e0, e1);
                    *(float2*)(eb + (size_t)(qr + 8) * SS + kc) = make_float2(e2, e3);
                }
            }
        }

        const uint32_t sVh = sb + OFF_VH + st * 18432;
        const uint32_t sVl = sb + OFF_VL + st * 18432;
#pragma unroll
        for (int u = 0; u < 4; u++) {
            uint32_t vh[4][4], vl[4][4];
#pragma unroll
            for (int jj2 = 0; jj2 < 4; jj2++) {
                const uint32_t addr = (warp_n * 64 + u * 16 + ((g & 1) << 3) + lr) * FA_STRIDE
                                    + jj2 * 32 + ((g >> 1) << 4);
                ld4t(vh[jj2], sVh + addr);
                ld4t(vl[jj2], sVl + addr);
            }
#pragma unroll
            for (int i = 0; i < 2; i++) {
                uint32_t ah[4], al[4];
                packhl(acc_s[i][2 * u][0],     acc_s[i][2 * u][1],     ah[0], al[0]);
                packhl(acc_s[i][2 * u][2],     acc_s[i][2 * u][3],     ah[1], al[1]);
                packhl(acc_s[i][2 * u + 1][0], acc_s[i][2 * u + 1][1], ah[2], al[2]);
                packhl(acc_s[i][2 * u + 1][2], acc_s[i][2 * u + 1][3], ah[3], al[3]);
#pragma unroll
                for (int jj2 = 0; jj2 < 4; jj2++) {
                    mma16816(acc_o[i][2 * jj2 + 0], ah, vh[jj2][0], vh[jj2][1]);
                    mma16816(acc_o[i][2 * jj2 + 0], al, vh[jj2][0], vh[jj2][1]);
                    mma16816(acc_o[i][2 * jj2 + 0], ah, vl[jj2][0], vl[jj2][1]);
                    mma16816(acc_o[i][2 * jj2 + 1], ah, vh[jj2][2], vh[jj2][3]);
                    mma16816(acc_o[i][2 * jj2 + 1], al, vh[jj2][2], vh[jj2][3]);
                    mma16816(acc_o[i][2 * jj2 + 1], ah, vl[jj2][2], vl[jj2][3]);
                }
            }
        }
        __syncthreads();
    }

    // ---- O cross-warp reduce + store ----
    float* so = (float*)(smem + OFF_O);
    if (warp_n == 1) {
#pragma unroll
        for (int i = 0; i < 2; i++) {
            int r = warp_m * 32 + i * 16 + lr2;
#pragma unroll
            for (int jj = 0; jj < 8; jj++) {
                int c = jj * 8 + lc2;
                *(float2*)&so[r * 66 + c] = make_float2(acc_o[i][jj][0], acc_o[i][jj][1]);
                *(float2*)&so[(r + 8) * 66 + c] = make_float2(acc_o[i][jj][2], acc_o[i][jj][3]);
            }
        }
    }
    __syncthreads();
    if (warp_n == 0) {
#pragma unroll
        for (int i = 0; i < 2; i++) {
            int r = warp_m * 32 + i * 16 + lr2;
            size_t row0 = chunk + (size_t)(qbase + r) * 64;
            size_t row1 = chunk + (size_t)(qbase + r + 8) * 64;
#pragma unroll
            for (int jj = 0; jj < 8; jj++) {
                int c = jj * 8 + lc2;
                float o0 = acc_o[i][jj][0] + so[r * 66 + c];
                float o1 = acc_o[i][jj][1] + so[r * 66 + c + 1];
                float o2 = acc_o[i][jj][2] + so[(r + 8) * 66 + c];
                float o3 = acc_o[i][jj][3] + so[(r + 8) * 66 + c + 1];
                __nv_bfloat16 h0 = __float2bfloat16(o0), h1 = __float2bfloat16(o1);
                __nv_bfloat16 h2 = __float2bfloat16(o2), h3 = __float2bfloat16(o3);
                *(uint32_t*)(AOhi + row0 + c) = packbf2(h0, h1);
                *(uint32_t*)(AOhi + row1 + c) = packbf2(h2, h3);
                *(uint32_t*)(AOlo + row0 + c) =
                    packbf2(__float2bfloat16(o0 - __bfloat162float(h0)),
                            __float2bfloat16(o1 - __bfloat162float(h1)));
                *(uint32_t*)(AOlo + row1 + c) =
                    packbf2(__float2bfloat16(o2 - __bfloat162float(h2)),
                            __float2bfloat16(o3 - __bfloat162float(h3)));
            }
        }
    }
}

// ---------------------------------------------------------------------------
extern "C" void kernel_launch(void* const* d_in, const int* in_sizes, int n_in,
                              void* d_out, int out_size)
{
    const float* query = (const float*)d_in[0];
    const float* keyy  = (const float*)d_in[1];
    const float* value = (const float*)d_in[2];
    const int*   mask  = (const int*)  d_in[3];
    const float* Wq = (const float*)d_in[4];
    const float* bq = (const float*)d_in[5];
    const float* Wk = (const float*)d_in[6];
    const float* bk = (const float*)d_in[7];
    const float* Wv = (const float*)d_in[8];
    const float* bv = (const float*)d_in[9];
    const float* Wo = (const float*)d_in[10];
    const float* bo = (const float*)d_in[11];
    float* out = (float*)d_out;

    void *pattn, *pah, *pal, *pbh, *pbl, *pqb, *pkb, *pvh, *pvl, *paoh, *paol;
    cudaGetSymbolAddress(&pattn, g_attn);
    cudaGetSymbolAddress(&pah, g_Ahi);
    cudaGetSymbolAddress(&pal, g_Alo);
    cudaGetSymbolAddress(&pbh, g_Bhi);
    cudaGetSymbolAddress(&pbl, g_Blo);
    cudaGetSymbolAddress(&pqb, g_Qb);
    cudaGetSymbolAddress(&pkb, g_Kb);
    cudaGetSymbolAddress(&pvh, g_Vhi);
    cudaGetSymbolAddress(&pvl, g_Vlo);
    cudaGetSymbolAddress(&paoh, g_AOhi);
    cudaGetSymbolAddress(&paol, g_AOlo);

    __nv_bfloat16* Ahi = (__nv_bfloat16*)pah;
    __nv_bfloat16* Alo = (__nv_bfloat16*)pal;
    __nv_bfloat16* Bhi = (__nv_bfloat16*)pbh;
    __nv_bfloat16* Blo = (__nv_bfloat16*)pbl;
    __nv_bfloat16* Qb  = (__nv_bfloat16*)pqb;
    __nv_bfloat16* Kb  = (__nv_bfloat16*)pkb;
    __nv_bfloat16* Vhi = (__nv_bfloat16*)pvh;
    __nv_bfloat16* Vlo = (__nv_bfloat16*)pvl;
    __nv_bfloat16* AOhi = (__nv_bfloat16*)paoh;
    __nv_bfloat16* AOlo = (__nv_bfloat16*)paol;

    const long long OUT_ELEMS  = (long long)BB * SS * DMM;
    const long long ATTN_ELEMS = (long long)NBH * SS * SS;
    int writeE = ((long long)out_size >= OUT_ELEMS + ATTN_ELEMS) ? 1 : 0;
    float* attnbuf = writeE ? (out + OUT_ELEMS) : (float*)pattn;

    static int smem_set = 0;
    if (!smem_set) {
        cudaFuncSetAttribute(fused_attn, cudaFuncAttributeMaxDynamicSharedMemorySize, FA_SMEM);
        cudaFuncSetAttribute(gemm3x, cudaFuncAttributeMaxDynamicSharedMemorySize, G_SMEM);
        smem_set = 1;
    }

    const int n4 = MROWS * DMM / 4;
    dim3 thr(256);

    // split all A inputs (Q/K/V) in one launch
    asplit3<<<dim3(n4 / 256, 3), thr>>>(query, keyy, value, Ahi, Alo);

    // split all 4 weights in one launch
    W4 ws;
    ws.W[0] = Wq; ws.W[1] = Wk; ws.W[2] = Wv; ws.W[3] = Wo;
    wsplit<<<dim3(32, 32, 4), thr>>>(ws, Bhi, Blo);

    // Q/K/V projections in one batched gemm launch.
    // Q,K outputs are rounded to bf16 -> 2 segments suffice; V keeps 3.
    G3B bq3;
    for (int z = 0; z < 3; z++) {
        bq3.Ahi[z] = Ahi + (size_t)z * APLANE;
        bq3.Alo[z] = Alo + (size_t)z * APLANE;
        bq3.Bhi[z] = Bhi + (size_t)z * WPLANE;
        bq3.Blo[z] = Blo + (size_t)z * WPLANE;
        bq3.C[z] = nullptr;
    }
    bq3.bias[0] = bq; bq3.bias[1] = bk; bq3.bias[2] = bv;
    bq3.Chi[0] = Qb;  bq3.Chi[1] = Kb;  bq3.Chi[2] = Vhi;
    bq3.Clo[0] = nullptr; bq3.Clo[1] = nullptr; bq3.Clo[2] = Vlo;
    bq3.nseg[0] = 2; bq3.nseg[1] = 2; bq3.nseg[2] = 3;
    gemm3x<<<dim3(DMM / 128, MROWS / 128, 3), thr, G_SMEM>>>(bq3, MROWS, DMM, DMM);

    // fused attention -> AOhi/AOlo + normalized attn
    fused_attn<<<dim3(SS / 128, NBH), thr, FA_SMEM>>>(
        Qb, Kb, Vhi, Vlo, mask, AOhi, AOlo, attnbuf, writeE);

    // out = AO @ Wo + bo  (fp32, full 3 segments)
    G3B bo3;
    bo3.Ahi[0] = AOhi; bo3.Alo[0] = AOlo;
    bo3.Bhi[0] = Bhi + 3 * WPLANE; bo3.Blo[0] = Blo + 3 * WPLANE;
    bo3.bias[0] = bo; bo3.C[0] = out; bo3.Chi[0] = nullptr; bo3.Clo[0] = nullptr;
    bo3.nseg[0] = 3;
    for (int z = 1; z < 3; z++) {
        bo3.Ahi[z] = nullptr; bo3.Alo[z] = nullptr; bo3.Bhi[z] = nullptr;
        bo3.Blo[z] = nullptr; bo3.bias[z] = nullptr; bo3.C[z] = nullptr;
        bo3.Chi[z] = nullptr; bo3.Clo[z] = nullptr; bo3.nseg[z] = 3;
    }
    gemm3x<<<dim3(DMM / 128, MROWS / 128, 1), thr, G_SMEM>>>(bo3, MROWS, DMM, DMM);
}

// round 13
// speedup vs baseline: 2.6419x; 1.0258x over previous
#include <cuda_runtime.h>
#include <cuda_bf16.h>
#include <cstdint>
#include <cstddef>

#define BB 8
#define SS 1024
#define DMM 1024
#define HH 16
#define DKK 64
#define DVV 64
#define MROWS (BB*SS)      /* 8192 */
#define NBH (BB*HH)        /* 128  */
#define APLANE ((size_t)MROWS*DMM)
#define WPLANE ((size_t)DMM*DMM)

// ---------------- scratch (static device globals; no runtime allocation) ----
__device__ float g_attn[(size_t)NBH*SS*SS];            // fallback attn buffer
__device__ __nv_bfloat16 g_Ahi[3*APLANE];
__device__ __nv_bfloat16 g_Alo[3*APLANE];
__device__ __nv_bfloat16 g_Bhi[4*WPLANE];
__device__ __nv_bfloat16 g_Blo[4*WPLANE];
__device__ __nv_bfloat16 g_Qb [APLANE];
__device__ __nv_bfloat16 g_Kb [APLANE];
__device__ __nv_bfloat16 g_Vhi[APLANE];
__device__ __nv_bfloat16 g_Vlo[APLANE];
__device__ __nv_bfloat16 g_AOhi[APLANE];
__device__ __nv_bfloat16 g_AOlo[APLANE];

// ============================================================================
// helpers (compute_80-level PTX only)
// ============================================================================
__device__ __forceinline__ uint32_t smem_u32(const void* p) {
    uint32_t a;
    asm("{ .reg .u64 t; cvta.to.shared.u64 t, %1; cvt.u32.u64 %0, t; }" : "=r"(a) : "l"(p));
    return a;
}
__device__ __forceinline__ void cp_async16(uint32_t dst, const void* src) {
    asm volatile("cp.async.cg.shared.global [%0], [%1], 16;" :: "r"(dst), "l"(src) : "memory");
}
__device__ __forceinline__ void ld4(uint32_t* r, uint32_t addr) {
    asm volatile("ldmatrix.sync.aligned.m8n8.x4.shared.b16 {%0,%1,%2,%3}, [%4];"
                 : "=r"(r[0]), "=r"(r[1]), "=r"(r[2]), "=r"(r[3]) : "r"(addr));
}
__device__ __forceinline__ void ld4t(uint32_t* r, uint32_t addr) {
    asm volatile("ldmatrix.sync.aligned.m8n8.x4.trans.shared.b16 {%0,%1,%2,%3}, [%4];"
                 : "=r"(r[0]), "=r"(r[1]), "=r"(r[2]), "=r"(r[3]) : "r"(addr));
}
__device__ __forceinline__ void mma16816(float* d, const uint32_t* a,
                                         uint32_t b0, uint32_t b1) {
    asm volatile(
        "mma.sync.aligned.m16n8k16.row.col.f32.bf16.bf16.f32 "
        "{%0,%1,%2,%3}, {%4,%5,%6,%7}, {%8,%9}, {%0,%1,%2,%3};"
        : "+f"(d[0]), "+f"(d[1]), "+f"(d[2]), "+f"(d[3])
        : "r"(a[0]), "r"(a[1]), "r"(a[2]), "r"(a[3]), "r"(b0), "r"(b1));
}
__device__ __forceinline__ uint32_t packbf2(__nv_bfloat16 x, __nv_bfloat16 y) {
    __nv_bfloat162 t; t.x = x; t.y = y;
    return *reinterpret_cast<uint32_t*>(&t);
}
__device__ __forceinline__ void packhl(float x, float y, uint32_t& h, uint32_t& l) {
    __nv_bfloat16 hx = __float2bfloat16(x), hy = __float2bfloat16(y);
    h = packbf2(hx, hy);
    l = packbf2(__float2bfloat16(x - __bfloat162float(hx)),
                __float2bfloat16(y - __bfloat162float(hy)));
}

// ============================================================================
// batched bf16x[nseg] mma.sync GEMM: C[z] = A[z] @ W[z] + bias[z].
// nseg=3: hi*hi + lo*hi + hi*lo.  nseg=2: hi*hi + lo*hi (bf16-bound outputs)
// BK=64, 2-stage. launch_bounds(256,2) for 2 CTAs/SM.
// ============================================================================
#define GS_STRIDE 144                 /* bytes per smem row (72 bf16) */
#define G_STAGE (128*GS_STRIDE)       /* 18432 */
#define G_SMEM  (4*G_STAGE)           /* 73728 */

struct G3B {
    const __nv_bfloat16* Ahi[3];
    const __nv_bfloat16* Alo[3];
    const __nv_bfloat16* Bhi[3];
    const __nv_bfloat16* Blo[3];
    const float* bias[3];
    float* C[3];
    __nv_bfloat16* Chi[3];
    __nv_bfloat16* Clo[3];
    int nseg[3];
};

__global__ __launch_bounds__(256, 2)
void gemm3x(G3B bat, int M, int N, int K)
{
    extern __shared__ char gsm[];
    const uint32_t sa0 = smem_u32(gsm);
    const uint32_t sb0 = sa0 + 2 * G_STAGE;
    const int z = blockIdx.z;

    const __nv_bfloat16* Ahi = bat.Ahi[z];
    const __nv_bfloat16* Alo = bat.Alo[z];
    const __nv_bfloat16* Bhi = bat.Bhi[z];
    const __nv_bfloat16* Blo = bat.Blo[z];
    const float* bias = bat.bias[z];
    float* C = bat.C[z];
    __nv_bfloat16* Chi = bat.Chi[z];
    __nv_bfloat16* Clo = bat.Clo[z];

    const int tid = threadIdx.x, wid = tid >> 5, lane = tid & 31;
    const int warp_m = wid & 3, warp_n = wid >> 2;
    const int mbase = blockIdx.y * 128, nbase = blockIdx.x * 128;
    const int g = lane >> 3, lr = lane & 7;

    const int KC = K / 64;
    const int NC = bat.nseg[z] * KC;
    const __nv_bfloat16* Aseg[3] = { Ahi, Alo, Ahi };
    const __nv_bfloat16* Bseg[3] = { Bhi, Bhi, Blo };

    float acc[2][8][4];
#pragma unroll
    for (int i = 0; i < 2; i++)
#pragma unroll
        for (int j = 0; j < 8; j++)
#pragma unroll
            for (int v = 0; v < 4; v++) acc[i][j][v] = 0.f;

    auto issue = [&](int ch) {
        const int seg = ch / KC, k0 = (ch % KC) * 64, s = ch & 1;
        const __nv_bfloat16* Ap = Aseg[seg] + (size_t)mbase * K + k0;
        const __nv_bfloat16* Bp = Bseg[seg] + (size_t)nbase * K + k0;
#pragma unroll
        for (int i = 0; i < 4; i++) {
            int idx = tid + i * 256;
            int r = idx >> 3, cb = (idx & 7) * 16;
            cp_async16(sa0 + s * G_STAGE + r * GS_STRIDE + cb,
                       (const char*)(Ap + (size_t)r * K) + cb);
            cp_async16(sb0 + s * G_STAGE + r * GS_STRIDE + cb,
                       (const char*)(Bp + (size_t)r * K) + cb);
        }
        asm volatile("cp.async.commit_group;" ::: "memory");
    };

    issue(0);
    for (int c = 0; c < NC; c++) {
        const int s = c & 1;
        if (c + 1 < NC) {
            issue(c + 1);
            asm volatile("cp.async.wait_group 1;" ::: "memory");
        } else {
            asm volatile("cp.async.wait_group 0;" ::: "memory");
        }
        __syncthreads();

        const uint32_t ab = sa0 + s * G_STAGE;
        const uint32_t bb = sb0 + s * G_STAGE;
#pragma unroll
        for (int kk = 0; kk < 4; kk++) {
            const uint32_t colb = kk * 32 + ((g >> 1) << 4);
            uint32_t afr[2][4];
#pragma unroll
            for (int i = 0; i < 2; i++) {
                int row = warp_m * 32 + i * 16 + ((g & 1) << 3) + lr;
                ld4(afr[i], ab + row * GS_STRIDE + colb);
            }
#pragma unroll
            for (int j = 0; j < 4; j++) {
                uint32_t bfr[4];
                int row = warp_n * 64 + j * 16 + ((g & 1) << 3) + lr;
                ld4(bfr, bb + row * GS_STRIDE + colb);
#pragma unroll
                for (int i = 0; i < 2; i++) {
                    mma16816(acc[i][2 * j + 0], afr[i], bfr[0], bfr[2]);
                    mma16816(acc[i][2 * j + 1], afr[i], bfr[1], bfr[3]);
                }
            }
        }
        __syncthreads();
    }

    // epilogue
#pragma unroll
    for (int i = 0; i < 2; i++) {
        int row0 = mbase + warp_m * 32 + i * 16 + (lane >> 2);
#pragma unroll
        for (int j = 0; j < 8; j++) {
            int col = nbase + warp_n * 64 + j * 8 + (lane & 3) * 2;
            float b0 = __ldg(bias + col), b1 = __ldg(bias + col + 1);
            float v0 = acc[i][j][0] + b0, v1 = acc[i][j][1] + b1;
            float v2 = acc[i][j][2] + b0, v3 = acc[i][j][3] + b1;
            if (C) {
                *(float2*)(C + (size_t)row0 * N + col) = make_float2(v0, v1);
                *(float2*)(C + (size_t)(row0 + 8) * N + col) = make_float2(v2, v3);
            }
            if (Chi) {
                __nv_bfloat16 h0 = __float2bfloat16(v0), h1 = __float2bfloat16(v1);
                __nv_bfloat16 h2 = __float2bfloat16(v2), h3 = __float2bfloat16(v3);
                *(uint32_t*)(Chi + (size_t)row0 * N + col) = packbf2(h0, h1);
                *(uint32_t*)(Chi + (size_t)(row0 + 8) * N + col) = packbf2(h2, h3);
                if (Clo) {
                    *(uint32_t*)(Clo + (size_t)row0 * N + col) =
                        packbf2(__float2bfloat16(v0 - __bfloat162float(h0)),
                                __float2bfloat16(v1 - __bfloat162float(h1)));
                    *(uint32_t*)(Clo + (size_t)(row0 + 8) * N + col) =
                        packbf2(__float2bfloat16(v2 - __bfloat162float(h2)),
                                __float2bfloat16(v3 - __bfloat162float(h3)));
                }
            }
        }
    }
}

// ---------------------------------------------------------------------------
__global__ __launch_bounds__(256)
void asplit3(const float* __restrict__ q, const float* __restrict__ k,
             const float* __restrict__ v,
             __nv_bfloat16* __restrict__ hi0, __nv_bfloat16* __restrict__ lo0)
{
    const int p = blockIdx.y;
    const float* A = (p == 0) ? q : (p == 1) ? k : v;
    __nv_bfloat16* hi = hi0 + (size_t)p * APLANE;
    __nv_bfloat16* lo = lo0 + (size_t)p * APLANE;
    int i = blockIdx.x * 256 + threadIdx.x;
    float4 val = ((const float4*)A)[i];
    __nv_bfloat16 h0 = __float2bfloat16(val.x), h1 = __float2bfloat16(val.y);
    __nv_bfloat16 h2 = __float2bfloat16(val.z), h3 = __float2bfloat16(val.w);
    __nv_bfloat162* hp = (__nv_bfloat162*)hi;
    __nv_bfloat162* lp = (__nv_bfloat162*)lo;
    hp[2 * i + 0] = __nv_bfloat162(h0, h1);
    hp[2 * i + 1] = __nv_bfloat162(h2, h3);
    lp[2 * i + 0] = __nv_bfloat162(__float2bfloat16(val.x - __bfloat162float(h0)),
                                   __float2bfloat16(val.y - __bfloat162float(h1)));
    lp[2 * i + 1] = __nv_bfloat162(__float2bfloat16(val.z - __bfloat162float(h2)),
                                   __float2bfloat16(val.w - __bfloat162float(h3)));
}

// ---------------------------------------------------------------------------
struct W4 { const float* W[4]; };

__global__ __launch_bounds__(256)
void wsplit(W4 ws, __nv_bfloat16* __restrict__ thi0, __nv_bfloat16* __restrict__ tlo0)
{
    __shared__ float t[32][33];
    const int z = blockIdx.z;
    const float* W = ws.W[z];
    __nv_bfloat16* thi = thi0 + (size_t)z * WPLANE;
    __nv_bfloat16* tlo = tlo0 + (size_t)z * WPLANE;
    const int n0 = blockIdx.x * 32, k0 = blockIdx.y * 32;
    const int x = threadIdx.x & 31, y = (threadIdx.x >> 5);
#pragma unroll
    for (int j = 0; j < 32; j += 8)
        t[y + j][x] = W[(size_t)(k0 + y + j) * DMM + n0 + x];
    __syncthreads();
#pragma unroll
    for (int j = 0; j < 32; j += 8) {
        float v = t[x][y + j];
        __nv_bfloat16 h = __float2bfloat16(v);
        size_t o = (size_t)(n0 + y + j) * DMM + k0 + x;
        thi[o] = h;
        tlo[o] = __float2bfloat16(v - __bfloat162float(h));
    }
}

// ============================================================================
// Fused attention, 2-pass normalized, 512 threads (16 warps: 8 m x 2 n).
// Each warp owns one m16 fragment (16 q-rows) x 64 k-cols.
// Pass A caches mask ballots in smem; pass B reads them via LDS.
// ============================================================================
#define FA_STRIDE 144
#define OFF_Q  0
#define OFF_K  18432
#define OFF_VH (OFF_K + 2*18432)
#define OFF_VL (OFF_VH + 2*18432)
#define OFF_O  (OFF_VL + 2*18432)
#define OFF_RS (OFF_O + 128*66*4)
#define OFF_INV (OFF_RS + 1024)
#define OFF_MB (OFF_INV + 512)         /* 8 tiles x 16 warps x 8 x 16B = 16KB */
#define FA_SMEM (OFF_MB + 16384)       /* 180736 */

__global__ __launch_bounds__(512, 1)
void fused_attn(const __nv_bfloat16* __restrict__ Qb, const __nv_bfloat16* __restrict__ Kb,
                const __nv_bfloat16* __restrict__ Vhi, const __nv_bfloat16* __restrict__ Vlo,
                const int* __restrict__ mask,
                __nv_bfloat16* __restrict__ AOhi, __nv_bfloat16* __restrict__ AOlo,
                float* __restrict__ ebuf, int writeE)
{
    extern __shared__ char smem[];
    const uint32_t sb = smem_u32(smem);
    const int tid = threadIdx.x, wid = tid >> 5, lane = tid & 31;
    const int warp_m = wid & 7, warp_n = wid >> 3;
    const int g = lane >> 3, lr = lane & 7;
    const int lr2 = lane >> 2, lc2 = (lane & 3) * 2;
    const int bh = blockIdx.y, b = bh >> 4;
    const int qbase = blockIdx.x * 128;

    const size_t chunk = (size_t)bh * (SS * 64);
    const int* mb = mask + (size_t)b * SS * SS;
    float* eb = ebuf + (size_t)bh * SS * SS;
    const float S64 = 1.0f / 64.0f;

    auto issueK = [&](int jt) {
        const int st = jt & 1;
        const size_t base = chunk + (size_t)jt * (128 * 64);
#pragma unroll
        for (int i = 0; i < 2; i++) {
            int idx = tid + i * 512;                 // 0..1023
            int r = idx >> 3, cb = (idx & 7) * 16;
            cp_async16(sb + OFF_K + st * 18432 + r * FA_STRIDE + cb,
                       (const char*)(Kb + base) + idx * 16);
        }
        asm volatile("cp.async.commit_group;" ::: "memory");
    };
    auto issueKV = [&](int jt) {
        const int st = jt & 1;
        const size_t base = chunk + (size_t)jt * (128 * 64);
#pragma unroll
        for (int i = 0; i < 2; i++) {
            int idx = tid + i * 512;
            int r = idx >> 3, cb = (idx & 7) * 16;
            cp_async16(sb + OFF_K  + st * 18432 + r * FA_STRIDE + cb, (const char*)(Kb  + base) + idx * 16);
            cp_async16(sb + OFF_VH + st * 18432 + r * FA_STRIDE + cb, (const char*)(Vhi + base) + idx * 16);
            cp_async16(sb + OFF_VL + st * 18432 + r * FA_STRIDE + cb, (const char*)(Vlo + base) + idx * 16);
        }
        asm volatile("cp.async.commit_group;" ::: "memory");
    };

    {
        const size_t qb0 = chunk + (size_t)qbase * 64;
#pragma unroll
        for (int i = 0; i < 2; i++) {
            int idx = tid + i * 512;
            int r = idx >> 3, cb = (idx & 7) * 16;
            cp_async16(sb + OFF_Q + r * FA_STRIDE + cb, (const char*)(Qb + qb0) + idx * 16);
        }
        issueK(0);
    }

    // S fragments for this warp's 16 q-rows x 64 k-cols
    auto computeS = [&](int st, float (*acc_s)[4]) {
#pragma unroll
        for (int j = 0; j < 8; j++)
#pragma unroll
            for (int v = 0; v < 4; v++) acc_s[j][v] = 0.f;
        const uint32_t sKb = sb + OFF_K + st * 18432;
#pragma unroll
        for (int kk = 0; kk < 4; kk++) {
            const uint32_t colb = kk * 32 + ((g >> 1) << 4);
            uint32_t afr[4];
            ld4(afr, sb + OFF_Q + (warp_m * 16 + ((g & 1) << 3) + lr) * FA_STRIDE + colb);
#pragma unroll
            for (int jj = 0; jj < 4; jj++) {
                uint32_t bfr[4];
                ld4(bfr, sKb + (warp_n * 64 + jj * 16 + ((g & 1) << 3) + lr) * FA_STRIDE + colb);
                mma16816(acc_s[2 * jj + 0], afr, bfr[0], bfr[2]);
                mma16816(acc_s[2 * jj + 1], afr, bfr[1], bfr[3]);
            }
        }
    };

    // mask-ballot slot address for (tile, jj) of this warp
    auto mbslot = [&](int jt, int jj) -> uint32_t {
        return sb + OFF_MB + (((jt * 16 + wid)) * 8 + jj) * 16;
    };

    // ================= PASS A: rowsums + ballot cache =================
    float rs[2] = {0.f, 0.f};
    for (int jt = 0; jt < 8; jt++) {
        const int st = jt & 1;
        if (jt + 1 < 8) {
            issueK(jt + 1);
            asm volatile("cp.async.wait_group 1;" ::: "memory");
        } else {
            asm volatile("cp.async.wait_group 0;" ::: "memory");
        }
        __syncthreads();

        float acc_s[8][4];
        computeS(st, acc_s);

        const int qr = qbase + warp_m * 16 + lr2;
#pragma unroll
        for (int jj = 0; jj < 8; jj++) {
            const int kc = jt * 128 + warp_n * 64 + jj * 8 + lc2;
            int2 m0 = __ldg((const int2*)(mb + (size_t)qr * SS + kc));
            int2 m1 = __ldg((const int2*)(mb + (size_t)(qr + 8) * SS + kc));
            unsigned bl0 = __ballot_sync(0xffffffffu, m0.x != 0);
            unsigned bl1 = __ballot_sync(0xffffffffu, m0.y != 0);
            unsigned bl2 = __ballot_sync(0xffffffffu, m1.x != 0);
            unsigned bl3 = __ballot_sync(0xffffffffu, m1.y != 0);
            if (lane == 0) {
                asm volatile("st.shared.v4.b32 [%0], {%1,%2,%3,%4};"
                             :: "r"(mbslot(jt, jj)),
                                "r"(bl0), "r"(bl1), "r"(bl2), "r"(bl3) : "memory");
            }
            float e0 = m0.x ? __expf(acc_s[jj][0] * S64) : 0.f;
            float e1 = m0.y ? __expf(acc_s[jj][1] * S64) : 0.f;
            float e2 = m1.x ? __expf(acc_s[jj][2] * S64) : 0.f;
            float e3 = m1.y ? __expf(acc_s[jj][3] * S64) : 0.f;
            rs[0] += e0 + e1;
            rs[1] += e2 + e3;
        }
        __syncthreads();
    }

    float* s_rs = (float*)(smem + OFF_RS);    // [2][128]
    float* sinv = (float*)(smem + OFF_INV);   // [128]
#pragma unroll
    for (int h2 = 0; h2 < 2; h2++) {
        float v = rs[h2];
        v += __shfl_xor_sync(0xffffffffu, v, 1);
        v += __shfl_xor_sync(0xffffffffu, v, 2);
        if ((lane & 3) == 0)
            s_rs[warp_n * 128 + warp_m * 16 + lr2 + h2 * 8] = v;
    }
    __syncthreads();
    if (tid < 128) sinv[tid] = 1.0f / (s_rs[tid] + s_rs[128 + tid]);
    __syncthreads();

    const float inva = sinv[warp_m * 16 + lr2];
    const float invb = sinv[warp_m * 16 + lr2 + 8];

    // ================= PASS B: normalized attn + PV =================
    float acc_o[8][4];
#pragma unroll
    for (int j = 0; j < 8; j++)
#pragma unroll
        for (int v = 0; v < 4; v++) acc_o[j][v] = 0.f;

    issueKV(0);
    for (int jt = 0; jt < 8; jt++) {
        const int st = jt & 1;
        if (jt + 1 < 8) {
            issueKV(jt + 1);
            asm volatile("cp.async.wait_group 1;" ::: "memory");
        } else {
            asm volatile("cp.async.wait_group 0;" ::: "memory");
        }
        __syncthreads();

        float acc_s[8][4];
        computeS(st, acc_s);

        const int qr = qbase + warp_m * 16 + lr2;
#pragma unroll
        for (int jj = 0; jj < 8; jj++) {
            const int kc = jt * 128 + warp_n * 64 + jj * 8 + lc2;
            uint32_t w0, w1, w2, w3;
            asm volatile("ld.shared.v4.b32 {%0,%1,%2,%3}, [%4];"
                         : "=r"(w0), "=r"(w1), "=r"(w2), "=r"(w3)
                         : "r"(mbslot(jt, jj)));
            bool b0 = (w0 >> lane) & 1u;
            bool b1 = (w1 >> lane) & 1u;
            bool b2 = (w2 >> lane) & 1u;
            bool b3 = (w3 >> lane) & 1u;
            float e0 = b0 ? __expf(acc_s[jj][0] * S64) * inva : 0.f;
            float e1 = b1 ? __expf(acc_s[jj][1] * S64) * inva : 0.f;
            float e2 = b2 ? __expf(acc_s[jj][2] * S64) * invb : 0.f;
            float e3 = b3 ? __expf(acc_s[jj][3] * S64) * invb : 0.f;
            acc_s[jj][0] = e0; acc_s[jj][1] = e1;
            acc_s[jj][2] = e2; acc_s[jj][3] = e3;
            if (writeE) {
                *(float2*)(eb + (size_t)qr * SS + kc) = make_float2(e0, e1);
                *(float2*)(eb + (size_t)(qr + 8) * SS + kc) = make_float2(e2, e3);
            }
        }

        const uint32_t sVh = sb + OFF_VH + st * 18432;
        const uint32_t sVl = sb + OFF_VL + st * 18432;
#pragma unroll
        for (int u = 0; u < 4; u++) {
            uint32_t vh[4][4], vl[4][4];
#pragma unroll
            for (int jj2 = 0; jj2 < 4; jj2++) {
                const uint32_t addr = (warp_n * 64 + u * 16 + ((g & 1) << 3) + lr) * FA_STRIDE
                                    + jj2 * 32 + ((g >> 1) << 4);
                ld4t(vh[jj2], sVh + addr);
                ld4t(vl[jj2], sVl + addr);
            }
            uint32_t ah[4], al[4];
            packhl(acc_s[2 * u][0],     acc_s[2 * u][1],     ah[0], al[0]);
            packhl(acc_s[2 * u][2],     acc_s[2 * u][3],     ah[1], al[1]);
            packhl(acc_s[2 * u + 1][0], acc_s[2 * u + 1][1], ah[2], al[2]);
            packhl(acc_s[2 * u + 1][2], acc_s[2 * u + 1][3], ah[3], al[3]);
#pragma unroll
            for (int jj2 = 0; jj2 < 4; jj2++) {
                mma16816(acc_o[2 * jj2 + 0], ah, vh[jj2][0], vh[jj2][1]);
                mma16816(acc_o[2 * jj2 + 0], al, vh[jj2][0], vh[jj2][1]);
                mma16816(acc_o[2 * jj2 + 0], ah, vl[jj2][0], vl[jj2][1]);
                mma16816(acc_o[2 * jj2 + 1], ah, vh[jj2][2], vh[jj2][3]);
                mma16816(acc_o[2 * jj2 + 1], al, vh[jj2][2], vh[jj2][3]);
                mma16816(acc_o[2 * jj2 + 1], ah, vl[jj2][2], vl[jj2][3]);
            }
        }
        __syncthreads();
    }

    // ---- O cross-warp reduce + store ----
    float* so = (float*)(smem + OFF_O);      // [128][66]
    if (warp_n == 1) {
        int r = warp_m * 16 + lr2;
#pragma unroll
        for (int jj = 0; jj < 8; jj++) {
            int c = jj * 8 + lc2;
            *(float2*)&so[r * 66 + c] = make_float2(acc_o[jj][0], acc_o[jj][1]);
            *(float2*)&so[(r + 8) * 66 + c] = make_float2(acc_o[jj][2], acc_o[jj][3]);
        }
    }
    __syncthreads();
    if (warp_n == 0) {
        int r = warp_m * 16 + lr2;
        size_t row0 = chunk + (size_t)(qbase + r) * 64;
        size_t row1 = chunk + (size_t)(qbase + r + 8) * 64;
#pragma unroll
        for (int jj = 0; jj < 8; jj++) {
            int c = jj * 8 + lc2;
            float o0 = acc_o[jj][0] + so[r * 66 + c];
            float o1 = acc_o[jj][1] + so[r * 66 + c + 1];
            float o2 = acc_o[jj][2] + so[(r + 8) * 66 + c];
            float o3 = acc_o[jj][3] + so[(r + 8) * 66 + c + 1];
            __nv_bfloat16 h0 = __float2bfloat16(o0), h1 = __float2bfloat16(o1);
            __nv_bfloat16 h2 = __float2bfloat16(o2), h3 = __float2bfloat16(o3);
            *(uint32_t*)(AOhi + row0 + c) = packbf2(h0, h1);
            *(uint32_t*)(AOhi + row1 + c) = packbf2(h2, h3);
            *(uint32_t*)(AOlo + row0 + c) =
                packbf2(__float2bfloat16(o0 - __bfloat162float(h0)),
                        __float2bfloat16(o1 - __bfloat162float(h1)));
            *(uint32_t*)(AOlo + row1 + c) =
                packbf2(__float2bfloat16(o2 - __bfloat162float(h2)),
                        __float2bfloat16(o3 - __bfloat162float(h3)));
        }
    }
}

// ---------------------------------------------------------------------------
extern "C" void kernel_launch(void* const* d_in, const int* in_sizes, int n_in,
                              void* d_out, int out_size)
{
    const float* query = (const float*)d_in[0];
    const float* keyy  = (const float*)d_in[1];
    const float* value = (const float*)d_in[2];
    const int*   mask  = (const int*)  d_in[3];
    const float* Wq = (const float*)d_in[4];
    const float* bq = (const float*)d_in[5];
    const float* Wk = (const float*)d_in[6];
    const float* bk = (const float*)d_in[7];
    const float* Wv = (const float*)d_in[8];
    const float* bv = (const float*)d_in[9];
    const float* Wo = (const float*)d_in[10];
    const float* bo = (const float*)d_in[11];
    float* out = (float*)d_out;

    void *pattn, *pah, *pal, *pbh, *pbl, *pqb, *pkb, *pvh, *pvl, *paoh, *paol;
    cudaGetSymbolAddress(&pattn, g_attn);
    cudaGetSymbolAddress(&pah, g_Ahi);
    cudaGetSymbolAddress(&pal, g_Alo);
    cudaGetSymbolAddress(&pbh, g_Bhi);
    cudaGetSymbolAddress(&pbl, g_Blo);
    cudaGetSymbolAddress(&pqb, g_Qb);
    cudaGetSymbolAddress(&pkb, g_Kb);
    cudaGetSymbolAddress(&pvh, g_Vhi);
    cudaGetSymbolAddress(&pvl, g_Vlo);
    cudaGetSymbolAddress(&paoh, g_AOhi);
    cudaGetSymbolAddress(&paol, g_AOlo);

    __nv_bfloat16* Ahi = (__nv_bfloat16*)pah;
    __nv_bfloat16* Alo = (__nv_bfloat16*)pal;
    __nv_bfloat16* Bhi = (__nv_bfloat16*)pbh;
    __nv_bfloat16* Blo = (__nv_bfloat16*)pbl;
    __nv_bfloat16* Qb  = (__nv_bfloat16*)pqb;
    __nv_bfloat16* Kb  = (__nv_bfloat16*)pkb;
    __nv_bfloat16* Vhi = (__nv_bfloat16*)pvh;
    __nv_bfloat16* Vlo = (__nv_bfloat16*)pvl;
    __nv_bfloat16* AOhi = (__nv_bfloat16*)paoh;
    __nv_bfloat16* AOlo = (__nv_bfloat16*)paol;

    const long long OUT_ELEMS  = (long long)BB * SS * DMM;
    const long long ATTN_ELEMS = (long long)NBH * SS * SS;
    int writeE = ((long long)out_size >= OUT_ELEMS + ATTN_ELEMS) ? 1 : 0;
    float* attnbuf = writeE ? (out + OUT_ELEMS) : (float*)pattn;

    static int smem_set = 0;
    if (!smem_set) {
        cudaFuncSetAttribute(fused_attn, cudaFuncAttributeMaxDynamicSharedMemorySize, FA_SMEM);
        cudaFuncSetAttribute(gemm3x, cudaFuncAttributeMaxDynamicSharedMemorySize, G_SMEM);
        smem_set = 1;
    }

    const int n4 = MROWS * DMM / 4;
    dim3 thr(256);

    // split all A inputs (Q/K/V) in one launch
    asplit3<<<dim3(n4 / 256, 3), thr>>>(query, keyy, value, Ahi, Alo);

    // split all 4 weights in one launch
    W4 ws;
    ws.W[0] = Wq; ws.W[1] = Wk; ws.W[2] = Wv; ws.W[3] = Wo;
    wsplit<<<dim3(32, 32, 4), thr>>>(ws, Bhi, Blo);

    // Q/K/V projections in one batched gemm launch (Q,K: 2 segments; V: 3)
    G3B bq3;
    for (int z = 0; z < 3; z++) {
        bq3.Ahi[z] = Ahi + (size_t)z * APLANE;
        bq3.Alo[z] = Alo + (size_t)z * APLANE;
        bq3.Bhi[z] = Bhi + (size_t)z * WPLANE;
        bq3.Blo[z] = Blo + (size_t)z * WPLANE;
        bq3.C[z] = nullptr;
    }
    bq3.bias[0] = bq; bq3.bias[1] = bk; bq3.bias[2] = bv;
    bq3.Chi[0] = Qb;  bq3.Chi[1] = Kb;  bq3.Chi[2] = Vhi;
    bq3.Clo[0] = nullptr; bq3.Clo[1] = nullptr; bq3.Clo[2] = Vlo;
    bq3.nseg[0] = 2; bq3.nseg[1] = 2; bq3.nseg[2] = 3;
    gemm3x<<<dim3(DMM / 128, MROWS / 128, 3), thr, G_SMEM>>>(bq3, MROWS, DMM, DMM);

    // fused attention (512 threads) -> AOhi/AOlo + normalized attn
    fused_attn<<<dim3(SS / 128, NBH), dim3(512), FA_SMEM>>>(
        Qb, Kb, Vhi, Vlo, mask, AOhi, AOlo, attnbuf, writeE);

    // out = AO @ Wo + bo  (fp32, 3 segments)
    G3B bo3;
    bo3.Ahi[0] = AOhi; bo3.Alo[0] = AOlo;
    bo3.Bhi[0] = Bhi + 3 * WPLANE; bo3.Blo[0] = Blo + 3 * WPLANE;
    bo3.bias[0] = bo; bo3.C[0] = out; bo3.Chi[0] = nullptr; bo3.Clo[0] = nullptr;
    bo3.nseg[0] = 3;
    for (int z = 1; z < 3; z++) {
        bo3.Ahi[z] = nullptr; bo3.Alo[z] = nullptr; bo3.Bhi[z] = nullptr;
        bo3.Blo[z] = nullptr; bo3.bias[z] = nullptr; bo3.C[z] = nullptr;
        bo3.Chi[z] = nullptr; bo3.Clo[z] = nullptr; bo3.nseg[z] = 3;
    }
    gemm3x<<<dim3(DMM / 128, MROWS / 128, 1), thr, G_SMEM>>>(bo3, MROWS, DMM, DMM);
}